// round 12
// baseline (speedup 1.0000x reference)
#include <cuda_runtime.h>
#include <cuda_bf16.h>
#include <cstdint>
#include <math.h>

// ---------------------------------------------------------------------------
// Problem dims
// ---------------------------------------------------------------------------
constexpr int B_   = 256;
constexpr int R_   = 6;
constexpr int K_   = 49;
constexpr int C_   = 512;
constexpr int H_   = 1024;
constexpr int E_   = 300;
constexpr int BR_  = B_ * R_;          // 1536
constexpr int NL_  = 2001;
constexpr int TWO_E = 2 * E_;          // 600
constexpr int CATW  = H_ + TWO_E;      // 1624

// ---------------------------------------------------------------------------
// fp32 scratch
// ---------------------------------------------------------------------------
constexpr long SZ_IMG0 = (long)B_ * K_ * C_;   // 6422528
constexpr long SZ_V    = (long)B_ * K_ * H_;
constexpr long SZ_H    = (long)BR_ * H_;
constexpr long SZ_2H   = (long)BR_ * 2048;
constexpr long SZ_3H   = (long)BR_ * 3072;

constexpr long OFF_IMG0  = 0;
constexpr long OFF_V1    = OFF_IMG0  + SZ_IMG0;
constexpr long OFF_V2    = OFF_V1    + SZ_V;
constexpr long OFF_QAQR  = OFF_V2    + SZ_V;      // [BR,2048] = [qa|qrepr]
constexpr long OFF_VREPR1= OFF_QAQR  + SZ_2H;     // [2BR,1024] (VREPR1;VREPRV)
constexpr long OFF_OUT   = OFF_VREPR1+ 2*SZ_H;    // [2BR,1024] (OUT;OUTV)
constexpr long OFF_QKV3  = OFF_OUT   + 2*SZ_H;    // [BR,3072]
constexpr long OFF_QAQR2 = OFF_QKV3  + SZ_3H;     // [BR,2048]
constexpr long OFF_VREPR2= OFF_QAQR2 + SZ_2H;
constexpr long OFF_BIASAQN = OFF_VREPR2 + SZ_H;   // 2048 floats
constexpr long SCRATCH_TOTAL = OFF_BIASAQN + 2048;

__device__ float g_scratch[SCRATCH_TOTAL];

// ---------------------------------------------------------------------------
// bf16 ACTIVATION planes (hi at off, lo at off+ATOTAL). Zero-initialized.
// ---------------------------------------------------------------------------
constexpr long ABF_IMG0  = 0;                          // [12544][512]
constexpr long ABF_IMGF  = ABF_IMG0  + 12544L * 512;   // [12544][512]
constexpr long ABF_RV    = ABF_IMGF  + 12544L * 512;   // [1536][640]
constexpr long ABF_QEMB  = ABF_RV    + 1536L * 640;    // [1536][1024]
constexpr long ABF_VEMB12= ABF_QEMB  + 1536L * 1024;   // [3072][512]
constexpr long ABF_VEMB3 = ABF_VEMB12+ 3072L * 512;    // [1536][512]
constexpr long ABF_OUT   = ABF_VEMB3 + 1536L * 512;    // [3072][1024]
constexpr long ABF_CTX   = ABF_OUT   + 3072L * 1024;   // [1536][1024]
constexpr long ABF_CAT   = ABF_CTX   + 1536L * 1024;   // [1536][1664]
constexpr long ABF_UQ    = ABF_CAT   + 1536L * 1664;   // [1536][1024]
constexpr long ABF_OUTF  = ABF_UQ    + 1536L * 1024;   // [1536][1024]
constexpr long ATOTAL    = ABF_OUTF  + 1536L * 1024;

__device__ __align__(256) __nv_bfloat16 g_abf[2 * ATOTAL];

// ---------------------------------------------------------------------------
// bf16 WEIGHT planes (transposed [Npad][Kpad], hi at off, lo at off+WTOTAL)
// ---------------------------------------------------------------------------
constexpr long WOFF_QC  = 0;                           // [1024][640]
constexpr long WOFF_AV  = WOFF_QC  + 1024L * 640;      // [1024][512]
constexpr long WOFF_AQN = WOFF_AV  + 1024L * 512;      // [2048][1024]
constexpr long WOFF_VN  = WOFF_AQN + 2048L * 1024;     // [1024][512]
constexpr long WOFF_QKV = WOFF_VN  + 1024L * 512;      // [3072][1024]
constexpr long WOFF_WO  = WOFF_QKV + 3072L * 1024;     // [1024][1024]
constexpr long WOFF_UQC = WOFF_WO  + 1024L * 1024;     // [1024][1664]
constexpr long WOFF_CLS = WOFF_UQC + 1024L * 1664;     // [2048][1024]
constexpr long WTOTAL   = WOFF_CLS + 2048L * 1024;

__device__ __align__(256) __nv_bfloat16 g_wbf[2 * WTOTAL];

// ---------------------------------------------------------------------------
// helpers
// ---------------------------------------------------------------------------
__device__ __forceinline__ uint32_t smem_u32(const void* p) {
    uint32_t a;
    asm("{ .reg .u64 t; cvta.to.shared.u64 t, %1; cvt.u32.u64 %0, t; }" : "=r"(a) : "l"(p));
    return a;
}
__device__ __forceinline__ void stsplit(long base, float v) {
    __nv_bfloat16 h = __float2bfloat16(v);
    g_abf[base] = h;
    g_abf[base + ATOTAL] = __float2bfloat16(v - __bfloat162float(h));
}
__device__ __forceinline__ void ldm_x4(uint32_t* r, uint32_t addr) {
    asm volatile("ldmatrix.sync.aligned.m8n8.x4.shared.b16 {%0,%1,%2,%3}, [%4];"
                 : "=r"(r[0]), "=r"(r[1]), "=r"(r[2]), "=r"(r[3]) : "r"(addr));
}
__device__ __forceinline__ void mma16816(float* c, const uint32_t* a, const uint32_t* b) {
    asm volatile(
        "mma.sync.aligned.m16n8k16.row.col.f32.bf16.bf16.f32 "
        "{%0,%1,%2,%3}, {%4,%5,%6,%7}, {%8,%9}, {%0,%1,%2,%3};"
        : "+f"(c[0]), "+f"(c[1]), "+f"(c[2]), "+f"(c[3])
        : "r"(a[0]), "r"(a[1]), "r"(a[2]), "r"(a[3]), "r"(b[0]), "r"(b[1]));
}
__device__ __forceinline__ void cpa16(uint32_t s, const void* g) {
    asm volatile("cp.async.cg.shared.global [%0], [%1], 16;" :: "r"(s), "l"(g));
}
#define CP_COMMIT() asm volatile("cp.async.commit_group;" ::: "memory")
template<int N> __device__ __forceinline__ void cp_wait() {
    asm volatile("cp.async.wait_group %0;" :: "n"(N) : "memory");
}

// ---------------------------------------------------------------------------
// megaconv: ALL weight transposes + bf16 splits in ONE launch
// ---------------------------------------------------------------------------
struct WAll {
    const float* W[11];
    int K[11], N[11], tilesK[11];
    int pre[12];
    long off[11];
};

__global__ void megaconv_kernel(WAll P)
{
    __shared__ float tile[32][33];
    int bx = blockIdx.x;
    int w = 0;
    while (bx >= P.pre[w + 1]) w++;
    int tix = bx - P.pre[w];
    int tK  = P.tilesK[w];
    int k0  = (tix % tK) * 32;
    int n0  = (tix / tK) * 32;
    int K = P.K[w], N = P.N[w], Kp = tK * 32;
    const float* W = P.W[w];
    long off = P.off[w];

    int tx = threadIdx.x, ty = threadIdx.y;
#pragma unroll
    for (int i = 0; i < 32; i += 8) {
        int k = k0 + ty + i, n = n0 + tx;
        tile[ty + i][tx] = (k < K && n < N) ? W[(size_t)k * N + n] : 0.f;
    }
    __syncthreads();
#pragma unroll
    for (int i = 0; i < 32; i += 8) {
        int n = n0 + ty + i, k = k0 + tx;
        float v = tile[tx][ty + i];
        __nv_bfloat16 h = __float2bfloat16(v);
        __nv_bfloat16 l = __float2bfloat16(v - __bfloat162float(h));
        long o = off + (long)n * Kp + k;
        g_wbf[o] = h;
        g_wbf[o + WTOTAL] = l;
    }
}

// ---------------------------------------------------------------------------
// prep: v_org transpose (fp32 + split), img_feat split, bias pack — ONE launch
// ---------------------------------------------------------------------------
__global__ void prep_kernel(const float* __restrict__ v_org,
                            const float* __restrict__ imgf,
                            const float* __restrict__ b0,
                            const float* __restrict__ b1)
{
    long idx = (long)blockIdx.x * 256 + threadIdx.x;
    if (idx < SZ_IMG0) {
        int  c = (int)(idx % C_);
        long t = idx / C_;
        int  k = (int)(t % K_);
        int  b = (int)(t / K_);
        float v = v_org[((long)b * C_ + c) * K_ + k];
        g_scratch[OFF_IMG0 + idx] = v;
        stsplit(ABF_IMG0 + idx, v);
    } else if (idx < 2 * SZ_IMG0) {
        long i = idx - SZ_IMG0;
        stsplit(ABF_IMGF + i, imgf[i]);
    } else {
        long i = idx - 2 * SZ_IMG0;
        if (i < 1024)      g_scratch[OFF_BIASAQN + i] = b0[i];
        else if (i < 2048) g_scratch[OFF_BIASAQN + i] = b1[i - 1024];
    }
}

// ---------------------------------------------------------------------------
// rv gather: bf16 split into ABF_RV (stride 640) AND ABF_CAT cols 1024..
// ---------------------------------------------------------------------------
__global__ void gather_rv_kernel(const int* __restrict__ gt_verb,
                                 const int* __restrict__ role_idx,
                                 const float* __restrict__ vt,
                                 const float* __restrict__ rt)
{
    long idx = (long)blockIdx.x * 256 + threadIdx.x;
    if (idx >= (long)BR_ * TWO_E) return;
    int e = (int)(idx % TWO_E);
    int n = (int)(idx / TWO_E);
    int b = n / R_;
    float val = (e < E_) ? vt[(long)gt_verb[b] * E_ + e]
                         : rt[(long)role_idx[n] * E_ + (e - E_)];
    stsplit(ABF_RV  + (long)n * 640  + e, val);
    stsplit(ABF_CAT + (long)n * 1664 + 1024 + e, val);
}

// ---------------------------------------------------------------------------
// GEMM problem descriptor
// ---------------------------------------------------------------------------
struct GemmDesc {
    long aOff, wOff;
    const float* biasPtr;
    long biasOff;
    float* CExt;
    long offC, offCbf;
    int cbfStride;
    int M, N, Kp, act;
};

// ---------------------------------------------------------------------------
// HMMA bf16-split GEMM. BM=64, 4 warps (2x2), warp tile 32 x (BN/2).
// NSTAGE-deep cp.async pipeline (wait -> sync -> issue -> compute).
// Dual-problem: blocks with blockIdx.y < ySplit run d0, rest run d1.
// ---------------------------------------------------------------------------
template<int BN, int NT, int NSTAGE, int MAXCTA>
__global__ __launch_bounds__(128, MAXCTA)
void mma_gemm_kernel(GemmDesc d0, GemmDesc d1, int ySplit)
{
    constexpr int BM = 64, BKP = 40;
    constexpr int MI  = 2;
    constexpr int ASZ = BM * BKP;
    constexpr int BSZ = BN * BKP;
    constexpr int STG = 2 * ASZ + 2 * BSZ;
    constexpr uint32_t ASZ2 = ASZ * 2, BSZ2 = BSZ * 2;

    extern __shared__ __align__(16) __nv_bfloat16 sm[];
    const bool first = ((int)blockIdx.y < ySplit);
    const GemmDesc d = first ? d0 : d1;
    const int byy = first ? blockIdx.y : (blockIdx.y - ySplit);

    const __nv_bfloat16* Ahp = g_abf + d.aOff;
    const __nv_bfloat16* Alp = g_abf + d.aOff + ATOTAL;
    const __nv_bfloat16* Bwh = g_wbf + d.wOff;
    const __nv_bfloat16* Bwl = g_wbf + d.wOff + WTOTAL;
    const float* bias = d.biasPtr ? d.biasPtr
                      : (d.biasOff >= 0 ? (const float*)(g_scratch + d.biasOff) : nullptr);

    const int tid  = threadIdx.x;
    const int wid  = tid >> 5, lane = tid & 31;
    const int brow = byy * BM, bcol = blockIdx.x * BN;
    const int wm   = (wid >> 1) * 32;
    const int wn   = (wid & 1) * (BN / 2);
    const uint32_t sb = smem_u32(sm);
    const int Kp = d.Kp;

    auto cpAll = [&](int t, int s) {
        const uint32_t st = sb + (uint32_t)(s * STG) * 2;
#pragma unroll
        for (int l = 0; l < 2; l++) {
            int idx = tid + l * 128;
            int row = idx >> 2, seg = idx & 3;
            size_t go = (size_t)(brow + row) * Kp + t * 32 + seg * 8;
            uint32_t so = (uint32_t)(row * BKP + seg * 8) * 2;
            cpa16(st + so,        Ahp + go);
            cpa16(st + ASZ2 + so, Alp + go);
        }
#pragma unroll
        for (int l = 0; l < BN / 32; l++) {
            int idx = tid + l * 128;
            int row = idx >> 2, seg = idx & 3;
            size_t go = (size_t)(bcol + row) * Kp + t * 32 + seg * 8;
            uint32_t so = (uint32_t)(row * BKP + seg * 8) * 2;
            cpa16(st + 2 * ASZ2 + so,        Bwh + go);
            cpa16(st + 2 * ASZ2 + BSZ2 + so, Bwl + go);
        }
    };

    float acc[MI][NT][4];
#pragma unroll
    for (int i = 0; i < MI; i++)
#pragma unroll
        for (int j = 0; j < NT; j++)
#pragma unroll
            for (int q = 0; q < 4; q++) acc[i][j][q] = 0.f;

    const int nCh = Kp / 32;

    // prologue: fill NSTAGE-1 stages
#pragma unroll
    for (int s = 0; s < NSTAGE - 1; s++) {
        if (s < nCh) cpAll(s, s);
        CP_COMMIT();
    }

    const int aRow = (lane & 7) + ((lane >> 3) & 1) * 8;
    const int aCol = (lane >> 4) * 8;
    const int bRow = (lane & 7) + ((lane >> 4) & 1) * 8;
    const int bCol = ((lane >> 3) & 1) * 8;

    for (int t = 0; t < nCh; t++) {
        cp_wait<NSTAGE - 2>();          // group t (stage t data) complete
        __syncthreads();                // all warps done with stage being refilled
        {
            int tn = t + NSTAGE - 1;
            if (tn < nCh) cpAll(tn, tn % NSTAGE);
            CP_COMMIT();                // always commit (group counting)
        }

        const int s = t % NSTAGE;
        const uint32_t ahB = sb + (uint32_t)(s * STG) * 2;
        const uint32_t alB = ahB + ASZ2;
        const uint32_t bhB = alB + ASZ2;
        const uint32_t blB = bhB + BSZ2;

#pragma unroll
        for (int ks = 0; ks < 2; ks++) {
            uint32_t ah[MI][4], al[MI][4];
#pragma unroll
            for (int mi = 0; mi < MI; mi++) {
                uint32_t off = (uint32_t)((wm + mi * 16 + aRow) * BKP + ks * 16 + aCol) * 2;
                ldm_x4(ah[mi], ahB + off);
                ldm_x4(al[mi], alB + off);
            }
            uint32_t bh[NT][2], bl[NT][2];
#pragma unroll
            for (int bt = 0; bt < NT / 2; bt++) {
                uint32_t off = (uint32_t)((wn + bt * 16 + bRow) * BKP + ks * 16 + bCol) * 2;
                uint32_t r[4];
                ldm_x4(r, bhB + off);
                bh[2 * bt][0] = r[0]; bh[2 * bt][1] = r[1];
                bh[2 * bt + 1][0] = r[2]; bh[2 * bt + 1][1] = r[3];
                ldm_x4(r, blB + off);
                bl[2 * bt][0] = r[0]; bl[2 * bt][1] = r[1];
                bl[2 * bt + 1][0] = r[2]; bl[2 * bt + 1][1] = r[3];
            }
#pragma unroll
            for (int mi = 0; mi < MI; mi++)
#pragma unroll
                for (int ni = 0; ni < NT; ni++) {
                    mma16816(acc[mi][ni], ah[mi], bh[ni]);
                    mma16816(acc[mi][ni], ah[mi], bl[ni]);
                    mma16816(acc[mi][ni], al[mi], bh[ni]);
                }
        }
    }

    // epilogue
    float* C = d.CExt ? d.CExt : (g_scratch + d.offC);
#pragma unroll
    for (int mi = 0; mi < MI; mi++) {
#pragma unroll
        for (int ni = 0; ni < NT; ni++) {
            int r0 = brow + wm + mi * 16 + (lane >> 2);
            int c0 = bcol + wn + ni * 8 + 2 * (lane & 3);
#pragma unroll
            for (int half = 0; half < 2; half++) {
                int gr = r0 + half * 8;
                float v0 = acc[mi][ni][2 * half + 0];
                float v1 = acc[mi][ni][2 * half + 1];
                if (d.offCbf >= 0) {
                    if (bias) { v0 += bias[c0]; v1 += bias[c0 + 1]; }
                    if (d.act) { v0 = fmaxf(v0, 0.f); v1 = fmaxf(v1, 0.f); }
                    __nv_bfloat16 h0 = __float2bfloat16(v0);
                    __nv_bfloat16 h1 = __float2bfloat16(v1);
                    __nv_bfloat16 l0 = __float2bfloat16(v0 - __bfloat162float(h0));
                    __nv_bfloat16 l1 = __float2bfloat16(v1 - __bfloat162float(h1));
                    long o = d.offCbf + (long)gr * d.cbfStride + c0;
                    uint32_t hp = (uint32_t)__bfloat16_as_ushort(h0)
                                | ((uint32_t)__bfloat16_as_ushort(h1) << 16);
                    uint32_t lp = (uint32_t)__bfloat16_as_ushort(l0)
                                | ((uint32_t)__bfloat16_as_ushort(l1) << 16);
                    *(uint32_t*)&g_abf[o] = hp;
                    *(uint32_t*)&g_abf[o + ATOTAL] = lp;
                } else {
                    if (c0 < d.N) {
                        float o = v0 + (bias ? bias[c0] : 0.f);
                        if (d.act) o = fmaxf(o, 0.f);
                        C[(size_t)gr * d.N + c0] = o;
                    }
                    if (c0 + 1 < d.N) {
                        float o = v1 + (bias ? bias[c0 + 1] : 0.f);
                        if (d.act) o = fmaxf(o, 0.f);
                        C[(size_t)gr * d.N + c0 + 1] = o;
                    }
                }
            }
        }
    }
}

constexpr int SMEM_BIG   = 2 * (2 * 64 * 40 + 2 * 128 * 40) * 2;  // 61440 B (2 stages)
constexpr int SMEM_SMALL = 3 * (2 * 64 * 40 + 2 * 64 * 40) * 2;   // 61440 B (3 stages)

static inline GemmDesc mkdesc(long aOff, long wOff, const float* bias, long biasOff,
                              float* CExt, long offC, long offCbf, int cbfStride,
                              int M, int N, int Kp, int act)
{
    GemmDesc d;
    d.aOff = aOff; d.wOff = wOff; d.biasPtr = bias; d.biasOff = biasOff;
    d.CExt = CExt; d.offC = offC; d.offCbf = offCbf; d.cbfStride = cbfStride;
    d.M = M; d.N = N; d.Kp = Kp; d.act = act;
    return d;
}

static inline void tgemm(long aOff, long wOff, const float* bias, long biasOff,
                         float* CExt, long offC, long offCbf, int cbfStride,
                         int M, int N, int Np, int Kp, int act)
{
    GemmDesc d = mkdesc(aOff, wOff, bias, biasOff, CExt, offC, offCbf, cbfStride,
                        M, N, Kp, act);
    if (M >= 4096 || Np >= 2048) {
        dim3 grid(Np / 128, M / 64);
        mma_gemm_kernel<128, 8, 2, 3><<<grid, 128, SMEM_BIG>>>(d, d, grid.y);
    } else {
        dim3 grid(Np / 64, M / 64);
        mma_gemm_kernel<64, 4, 3, 3><<<grid, 128, SMEM_SMALL>>>(d, d, grid.y);
    }
}

// dual launch: both problems must share Np (grid.x) and use the BIG config
static inline void tgemm_dual(const GemmDesc& d0, const GemmDesc& d1, int Np)
{
    dim3 grid(Np / 128, d0.M / 64 + d1.M / 64);
    mma_gemm_kernel<128, 8, 2, 3><<<grid, 128, SMEM_BIG>>>(d0, d1, d0.M / 64);
}

// ---------------------------------------------------------------------------
// Visual attention (block per (b, src)); src=blockIdx.y: 0 -> (V1, img0),
// 1 -> (V2, img_feat). Single-source calls use gridDim.y == 1.
// ---------------------------------------------------------------------------
__global__ __launch_bounds__(256) void att6_kernel(
    long offQA, int qStride,
    const float* __restrict__ aoW, const float* __restrict__ aoB,
    const float* __restrict__ imgf,
    long abfOut0, long abfOut1)
{
    int b  = blockIdx.x;
    int which = blockIdx.y;
    int n0 = b * R_;
    const float* V   = g_scratch + (which ? OFF_V2 : OFF_V1) + (long)b * K_ * H_;
    const float* img = which ? (imgf + (long)b * K_ * C_)
                             : (g_scratch + OFF_IMG0 + (long)b * K_ * C_);
    long abfOut = which ? abfOut1 : abfOut0;

    __shared__ float qa[R_][H_];
    __shared__ float attw[R_][K_ + 1];

    int tid = threadIdx.x, wid = tid >> 5, lane = tid & 31;

    for (int idx = tid; idx < R_ * H_; idx += 256) {
        int r = idx / H_, h = idx % H_;
        qa[r][h] = g_scratch[offQA + (long)(n0 + r) * qStride + h] * aoW[h];
    }
    __syncthreads();

    for (int k = wid; k < K_; k += 8) {
        const float* vk = V + (long)k * H_;
        float s0=0,s1=0,s2=0,s3=0,s4=0,s5=0;
        for (int h = lane; h < H_; h += 32) {
            float v = vk[h];
            s0 = fmaf(v, qa[0][h], s0); s1 = fmaf(v, qa[1][h], s1);
            s2 = fmaf(v, qa[2][h], s2); s3 = fmaf(v, qa[3][h], s3);
            s4 = fmaf(v, qa[4][h], s4); s5 = fmaf(v, qa[5][h], s5);
        }
#pragma unroll
        for (int o = 16; o; o >>= 1) {
            s0 += __shfl_xor_sync(0xffffffffu, s0, o);
            s1 += __shfl_xor_sync(0xffffffffu, s1, o);
            s2 += __shfl_xor_sync(0xffffffffu, s2, o);
            s3 += __shfl_xor_sync(0xffffffffu, s3, o);
            s4 += __shfl_xor_sync(0xffffffffu, s4, o);
            s5 += __shfl_xor_sync(0xffffffffu, s5, o);
        }
        if (lane == 0) {
            float ab = aoB[0];
            attw[0][k] = s0 + ab; attw[1][k] = s1 + ab; attw[2][k] = s2 + ab;
            attw[3][k] = s3 + ab; attw[4][k] = s4 + ab; attw[5][k] = s5 + ab;
        }
    }
    __syncthreads();

    if (tid < R_) {
        float mx = -1e30f;
        for (int k = 0; k < K_; k++) mx = fmaxf(mx, attw[tid][k]);
        float sum = 0.f;
        for (int k = 0; k < K_; k++) sum += expf(attw[tid][k] - mx);
        float inv = 1.f / sum;
        for (int k = 0; k < K_; k++) attw[tid][k] = expf(attw[tid][k] - mx) * inv;
    }
    __syncthreads();

    for (int c = tid; c < C_; c += 256) {
        float a0=0,a1=0,a2=0,a3=0,a4=0,a5=0;
#pragma unroll 7
        for (int k = 0; k < K_; k++) {
            float f = img[(long)k * C_ + c];
            a0 = fmaf(attw[0][k], f, a0); a1 = fmaf(attw[1][k], f, a1);
            a2 = fmaf(attw[2][k], f, a2); a3 = fmaf(attw[3][k], f, a3);
            a4 = fmaf(attw[4][k], f, a4); a5 = fmaf(attw[5][k], f, a5);
        }
        long base = abfOut + (long)n0 * C_ + c;
        stsplit(base,          a0); stsplit(base + C_,     a1);
        stsplit(base + 2 * C_, a2); stsplit(base + 3 * C_, a3);
        stsplit(base + 4 * C_, a4); stsplit(base + 5 * C_, a5);
    }
}

// ---------------------------------------------------------------------------
// MFB pool. mode 0: write fp32 rows (OUT/OUTV) + bf16 split (ABF_OUT).
// mode 1: fuse gated combine — r=out2; read outv/ans0 fp32; write ABF_OUTF.
// ---------------------------------------------------------------------------
__global__ void mfb_kernel(long offQ, int qStride, int qWrap,
                           long offV, int mode)
{
    int n = blockIdx.x;
    const float* q = g_scratch + offQ + (long)(n % qWrap) * qStride;
    const float* v = g_scratch + offV + (long)n * H_;
    int tid = threadIdx.x;

    float s = 0.f;
    for (int h = tid; h < H_; h += 256) {
        float z = q[h] * v[h];
        s += fabsf(z);
    }
    __shared__ float red[8];
#pragma unroll
    for (int off = 16; off; off >>= 1) s += __shfl_xor_sync(0xffffffffu, s, off);
    if ((tid & 31) == 0) red[tid >> 5] = s;
    __syncthreads();
    float tot = 0.f;
#pragma unroll
    for (int i = 0; i < 8; i++) tot += red[i];
    float inv = 1.f / fmaxf(sqrtf(tot), 1e-12f);

    for (int h = tid; h < H_; h += 256) {
        float z = q[h] * v[h];
        float sg = (z > 0.f) ? sqrtf(z) : -sqrtf(-z);
        float r = sg * inv;
        if (mode == 0) {
            g_scratch[OFF_OUT + (long)n * H_ + h] = r;
            stsplit(ABF_OUT + (long)n * H_ + h, r);
        } else {
            float ov = g_scratch[OFF_OUT + SZ_H + (long)n * H_ + h];
            float a0 = g_scratch[OFF_OUT + (long)n * H_ + h];
            float g  = 1.f / (1.f + expf(-(r + ov)));
            stsplit(ABF_OUTF + (long)n * H_ + h, (1.f - g) * ov + g * tanhf(r + a0));
        }
    }
}

// ---------------------------------------------------------------------------
// Masked role attention -> ctx as bf16 split
// ---------------------------------------------------------------------------
__global__ void role_att_kernel(const int* __restrict__ mask)
{
    int b = blockIdx.x;
    const float* base = g_scratch + OFF_QKV3 + (long)b * R_ * 3072;

    __shared__ float sc[R_][R_];
    __shared__ float attn[R_][R_];
    int tid = threadIdx.x, wid = tid >> 5, lane = tid & 31;

    for (int p = wid; p < R_ * R_; p += 8) {
        int i = p / R_, j = p % R_;
        const float* qh = base + (long)i * 3072;
        const float* kh = base + (long)j * 3072 + 1024;
        float s = 0.f;
        for (int h = lane; h < H_; h += 32)
            s = fmaf(qh[h], kh[h], s);
#pragma unroll
        for (int o = 16; o; o >>= 1) s += __shfl_xor_sync(0xffffffffu, s, o);
        if (lane == 0) {
            bool valid = (i != j) && (mask[((long)b * R_ + i) * R_ + j] > 0);
            sc[i][j] = valid ? s * (1.f / 32.f) : -1e9f;
        }
    }
    __syncthreads();

    if (tid < R_ * R_) {
        int i = tid / R_, j = tid % R_;
        float mx = -1e30f;
        for (int jj = 0; jj < R_; jj++) mx = fmaxf(mx, sc[i][jj]);
        float sum = 0.f;
        for (int jj = 0; jj < R_; jj++) sum += expf(sc[i][jj] - mx);
        attn[i][j] = expf(sc[i][j] - mx) / sum;
    }
    __syncthreads();

    for (int idx = tid; idx < R_ * H_; idx += 256) {
        int i = idx / H_, h = idx % H_;
        float acc = 0.f;
#pragma unroll
        for (int j = 0; j < R_; j++)
            acc = fmaf(attn[i][j], base[(long)j * 3072 + 2048 + h], acc);
        stsplit(ABF_CTX + (long)(b * R_ + i) * H_ + h, acc);
    }
}

// ---------------------------------------------------------------------------
// Launch sequence
// ---------------------------------------------------------------------------
extern "C" void kernel_launch(void* const* d_in, const int* in_sizes, int n_in,
                              void* d_out, int out_size)
{
    const float* v_org    = (const float*)d_in[0];
    const float* img_feat = (const float*)d_in[1];
    const int*   gt_verb  = (const int*)d_in[2];
    const int*   role_idx = (const int*)d_in[3];
    const int*   mask     = (const int*)d_in[4];
    const float* verb_t   = (const float*)d_in[5];
    const float* role_t   = (const float*)d_in[6];
    const float* qc_W = (const float*)d_in[7];   const float* qc_b = (const float*)d_in[8];
    const float* av_W = (const float*)d_in[9];   const float* av_b = (const float*)d_in[10];
    const float* aq_W = (const float*)d_in[11];  const float* aq_b = (const float*)d_in[12];
    const float* ao_W = (const float*)d_in[13];  const float* ao_b = (const float*)d_in[14];
    const float* vn_W = (const float*)d_in[15];  const float* vn_b = (const float*)d_in[16];
    const float* qn_W = (const float*)d_in[17];  const float* qn_b = (const float*)d_in[18];
    const float* Wq   = (const float*)d_in[19];
    const float* Wk   = (const float*)d_in[20];
    const float* Wv   = (const float*)d_in[21];
    const float* Wo   = (const float*)d_in[22];
    const float* uqc_W = (const float*)d_in[23]; const float* uqc_b = (const float*)d_in[24];
    const float* cls_W = (const float*)d_in[25]; const float* cls_b = (const float*)d_in[26];

    cudaFuncSetAttribute((const void*)mma_gemm_kernel<128, 8, 2, 3>,
                         cudaFuncAttributeMaxDynamicSharedMemorySize, SMEM_BIG);
    cudaFuncSetAttribute((const void*)mma_gemm_kernel<64, 4, 3, 3>,
                         cudaFuncAttributeMaxDynamicSharedMemorySize, SMEM_SMALL);

    // megaconv descriptor table
    WAll P;
    const float* Ws[11] = {qc_W, av_W, aq_W, qn_W, vn_W, Wq, Wk, Wv, Wo, uqc_W, cls_W};
    int  Ks[11]  = {600, 512, 1024, 1024, 512, 1024, 1024, 1024, 1024, CATW, 1024};
    int  Ns[11]  = {1024,1024,1024, 1024, 1024,1024, 1024, 1024, 1024, 1024, NL_};
    int  tK[11]  = {20,  16,  32,   32,   16,  32,   32,   32,   32,   52,   32};
    int  Nps[11] = {1024,1024,1024, 1024, 1024,1024, 1024, 1024, 1024, 1024, 2048};
    long offs[11]= {WOFF_QC, WOFF_AV, WOFF_AQN, WOFF_AQN + 1024L * 1024, WOFF_VN,
                    WOFF_QKV, WOFF_QKV + 1024L * 1024, WOFF_QKV + 2048L * 1024,
                    WOFF_WO, WOFF_UQC, WOFF_CLS};
    int pre = 0;
    for (int i = 0; i < 11; i++) {
        P.W[i] = Ws[i]; P.K[i] = Ks[i]; P.N[i] = Ns[i];
        P.tilesK[i] = tK[i]; P.off[i] = offs[i];
        P.pre[i] = pre;
        pre += tK[i] * (Nps[i] / 32);
    }
    P.pre[11] = pre;

    // 0: prep, 1: megaconv, 2: gather, 3: DUAL V1V2+QEMB GEMM (profiled slot)
    prep_kernel<<<(int)((2 * SZ_IMG0 + 2048 + 255) / 256), 256>>>(v_org, img_feat,
                                                                  aq_b, qn_b);
    megaconv_kernel<<<pre, dim3(32, 8)>>>(P);
    gather_rv_kernel<<<(int)(((long)BR_ * TWO_E + 255) / 256), 256>>>(gt_verb, role_idx,
                                                                      verb_t, role_t);
    // DUAL: V1V2 (M=25088, K=512) + QEMB (M=1536, K=640) — both Np=1024
    {
        GemmDesc dv = mkdesc(ABF_IMG0, WOFF_AV, av_b, -1, nullptr, OFF_V1, -1, 0,
                             2 * B_ * K_, 1024, 512, 1);
        GemmDesc dq = mkdesc(ABF_RV, WOFF_QC, qc_b, -1, nullptr, 0, ABF_QEMB, 1024,
                             BR_, 1024, 640, 1);
        tgemm_dual(dv, dq, 1024);
    }

    tgemm(ABF_QEMB, WOFF_AQN, nullptr, OFF_BIASAQN, nullptr, OFF_QAQR, -1, 0,
          BR_, 2048, 2048, 1024, 1);

    // attention 1 + attention-verb in ONE launch (grid B x 2)
    att6_kernel<<<dim3(B_, 2), 256>>>(OFF_QAQR, 2048, ao_W, ao_b, img_feat,
                                      ABF_VEMB12, ABF_VEMB12 + (long)BR_ * 512);

    // fused VN over [VEMB1;VEMB2]
    tgemm(ABF_VEMB12, WOFF_VN, vn_b, -1, nullptr, OFF_VREPR1, -1, 0,
          2 * BR_, 1024, 1024, 512, 1);

    // fused MFB for OUT & OUTV (mode 0)
    mfb_kernel<<<2 * BR_, 256>>>(OFF_QAQR + 1024, 2048, BR_, OFF_VREPR1, 0);

    // role-node neighbour attention
    tgemm(ABF_OUT, WOFF_QKV, nullptr, -1, nullptr, OFF_QKV3, -1, 0,
          BR_, 3072, 3072, 1024, 0);
    role_att_kernel<<<B_, 256>>>(mask);
    // WO writes bf16 split DIRECTLY into CAT rows (stride 1664)
    tgemm(ABF_CTX, WOFF_WO, nullptr, -1, nullptr, 0, ABF_CAT, 1664,
          BR_, 1024, 1024, 1024, 0);

    // updated query
    tgemm(ABF_CAT, WOFF_UQC, uqc_b, -1, nullptr, 0, ABF_UQ, 1024,
          BR_, 1024, 1024, 1664, 1);
    tgemm(ABF_UQ, WOFF_AQN, nullptr, OFF_BIASAQN, nullptr, OFF_QAQR2, -1, 0,
          BR_, 2048, 2048, 1024, 1);

    // attention 2 (single source)
    att6_kernel<<<dim3(B_, 1), 256>>>(OFF_QAQR2, 2048, ao_W, ao_b, img_feat,
                                      ABF_VEMB3, ABF_VEMB3);
    tgemm(ABF_VEMB3, WOFF_VN, vn_b, -1, nullptr, OFF_VREPR2, -1, 0,
          BR_, 1024, 1024, 512, 1);

    // MFB(out2) fused with gated combine (mode 1) -> ABF_OUTF
    mfb_kernel<<<BR_, 256>>>(OFF_QAQR2 + 1024, 2048, BR_, OFF_VREPR2, 1);

    // classifier -> d_out
    tgemm(ABF_OUTF, WOFF_CLS, cls_b, -1, (float*)d_out, 0, -1, 0,
          BR_, NL_, 2048, 1024, 0);
}

// round 13
// speedup vs baseline: 1.0283x; 1.0283x over previous
#include <cuda_runtime.h>
#include <cuda_bf16.h>
#include <cstdint>
#include <math.h>

// ---------------------------------------------------------------------------
// Problem dims
// ---------------------------------------------------------------------------
constexpr int B_   = 256;
constexpr int R_   = 6;
constexpr int K_   = 49;
constexpr int C_   = 512;
constexpr int H_   = 1024;
constexpr int E_   = 300;
constexpr int BR_  = B_ * R_;          // 1536
constexpr int NL_  = 2001;
constexpr int TWO_E = 2 * E_;          // 600
constexpr int CATW  = H_ + TWO_E;      // 1624

// ---------------------------------------------------------------------------
// fp32 scratch
// ---------------------------------------------------------------------------
constexpr long SZ_IMG0 = (long)B_ * K_ * C_;   // 6422528
constexpr long SZ_V    = (long)B_ * K_ * H_;
constexpr long SZ_H    = (long)BR_ * H_;
constexpr long SZ_2H   = (long)BR_ * 2048;
constexpr long SZ_3H   = (long)BR_ * 3072;

constexpr long OFF_IMG0  = 0;
constexpr long OFF_V1    = OFF_IMG0  + SZ_IMG0;
constexpr long OFF_V2    = OFF_V1    + SZ_V;
constexpr long OFF_QAQR  = OFF_V2    + SZ_V;      // [BR,2048] = [qa|qrepr]
constexpr long OFF_VREPR1= OFF_QAQR  + SZ_2H;     // [2BR,1024] (VREPR1;VREPRV)
constexpr long OFF_OUT   = OFF_VREPR1+ 2*SZ_H;    // [2BR,1024] (OUT;OUTV)
constexpr long OFF_QKV3  = OFF_OUT   + 2*SZ_H;    // [BR,3072]
constexpr long OFF_QAQR2 = OFF_QKV3  + SZ_3H;     // [BR,2048]
constexpr long OFF_VREPR2= OFF_QAQR2 + SZ_2H;
constexpr long OFF_BIASAQN = OFF_VREPR2 + SZ_H;   // 2048 floats
constexpr long SCRATCH_TOTAL = OFF_BIASAQN + 2048;

__device__ float g_scratch[SCRATCH_TOTAL];

// ---------------------------------------------------------------------------
// bf16 ACTIVATION planes (hi at off, lo at off+ATOTAL). Zero-initialized.
// ---------------------------------------------------------------------------
constexpr long ABF_IMG0  = 0;                          // [12544][512]
constexpr long ABF_IMGF  = ABF_IMG0  + 12544L * 512;   // [12544][512]
constexpr long ABF_RV    = ABF_IMGF  + 12544L * 512;   // [1536][640]
constexpr long ABF_QEMB  = ABF_RV    + 1536L * 640;    // [1536][1024]
constexpr long ABF_VEMB12= ABF_QEMB  + 1536L * 1024;   // [3072][512]
constexpr long ABF_VEMB3 = ABF_VEMB12+ 3072L * 512;    // [1536][512]
constexpr long ABF_OUT   = ABF_VEMB3 + 1536L * 512;    // [3072][1024]
constexpr long ABF_CTX   = ABF_OUT   + 3072L * 1024;   // [1536][1024]
constexpr long ABF_CAT   = ABF_CTX   + 1536L * 1024;   // [1536][1664]
constexpr long ABF_UQ    = ABF_CAT   + 1536L * 1664;   // [1536][1024]
constexpr long ABF_OUTF  = ABF_UQ    + 1536L * 1024;   // [1536][1024]
constexpr long ATOTAL    = ABF_OUTF  + 1536L * 1024;

__device__ __align__(256) __nv_bfloat16 g_abf[2 * ATOTAL];

// ---------------------------------------------------------------------------
// bf16 WEIGHT planes (transposed [Npad][Kpad], hi at off, lo at off+WTOTAL)
// ---------------------------------------------------------------------------
constexpr long WOFF_QC  = 0;                           // [1024][640]
constexpr long WOFF_AV  = WOFF_QC  + 1024L * 640;      // [1024][512]
constexpr long WOFF_AQN = WOFF_AV  + 1024L * 512;      // [2048][1024]
constexpr long WOFF_VN  = WOFF_AQN + 2048L * 1024;     // [1024][512]
constexpr long WOFF_QKV = WOFF_VN  + 1024L * 512;      // [3072][1024]
constexpr long WOFF_WO  = WOFF_QKV + 3072L * 1024;     // [1024][1024]
constexpr long WOFF_UQC = WOFF_WO  + 1024L * 1024;     // [1024][1664]
constexpr long WOFF_CLS = WOFF_UQC + 1024L * 1664;     // [2048][1024]
constexpr long WTOTAL   = WOFF_CLS + 2048L * 1024;

__device__ __align__(256) __nv_bfloat16 g_wbf[2 * WTOTAL];

// ---------------------------------------------------------------------------
// helpers
// ---------------------------------------------------------------------------
__device__ __forceinline__ uint32_t smem_u32(const void* p) {
    uint32_t a;
    asm("{ .reg .u64 t; cvta.to.shared.u64 t, %1; cvt.u32.u64 %0, t; }" : "=r"(a) : "l"(p));
    return a;
}
__device__ __forceinline__ void stsplit(long base, float v) {
    __nv_bfloat16 h = __float2bfloat16(v);
    g_abf[base] = h;
    g_abf[base + ATOTAL] = __float2bfloat16(v - __bfloat162float(h));
}
__device__ __forceinline__ void ldm_x4(uint32_t* r, uint32_t addr) {
    asm volatile("ldmatrix.sync.aligned.m8n8.x4.shared.b16 {%0,%1,%2,%3}, [%4];"
                 : "=r"(r[0]), "=r"(r[1]), "=r"(r[2]), "=r"(r[3]) : "r"(addr));
}
__device__ __forceinline__ void mma16816(float* c, const uint32_t* a, const uint32_t* b) {
    asm volatile(
        "mma.sync.aligned.m16n8k16.row.col.f32.bf16.bf16.f32 "
        "{%0,%1,%2,%3}, {%4,%5,%6,%7}, {%8,%9}, {%0,%1,%2,%3};"
        : "+f"(c[0]), "+f"(c[1]), "+f"(c[2]), "+f"(c[3])
        : "r"(a[0]), "r"(a[1]), "r"(a[2]), "r"(a[3]), "r"(b[0]), "r"(b[1]));
}
__device__ __forceinline__ void cpa16(uint32_t s, const void* g) {
    asm volatile("cp.async.cg.shared.global [%0], [%1], 16;" :: "r"(s), "l"(g));
}
#define CP_COMMIT() asm volatile("cp.async.commit_group;" ::: "memory")
#define CP_WAIT0()  asm volatile("cp.async.wait_group 0;" ::: "memory")

// ---------------------------------------------------------------------------
// megaconv: ALL weight transposes + bf16 splits in ONE launch
// ---------------------------------------------------------------------------
struct WAll {
    const float* W[11];
    int K[11], N[11], tilesK[11];
    int pre[12];
    long off[11];
};

__global__ void megaconv_kernel(WAll P)
{
    __shared__ float tile[32][33];
    int bx = blockIdx.x;
    int w = 0;
    while (bx >= P.pre[w + 1]) w++;
    int tix = bx - P.pre[w];
    int tK  = P.tilesK[w];
    int k0  = (tix % tK) * 32;
    int n0  = (tix / tK) * 32;
    int K = P.K[w], N = P.N[w], Kp = tK * 32;
    const float* W = P.W[w];
    long off = P.off[w];

    int tx = threadIdx.x, ty = threadIdx.y;
#pragma unroll
    for (int i = 0; i < 32; i += 8) {
        int k = k0 + ty + i, n = n0 + tx;
        tile[ty + i][tx] = (k < K && n < N) ? W[(size_t)k * N + n] : 0.f;
    }
    __syncthreads();
#pragma unroll
    for (int i = 0; i < 32; i += 8) {
        int n = n0 + ty + i, k = k0 + tx;
        float v = tile[tx][ty + i];
        __nv_bfloat16 h = __float2bfloat16(v);
        __nv_bfloat16 l = __float2bfloat16(v - __bfloat162float(h));
        long o = off + (long)n * Kp + k;
        g_wbf[o] = h;
        g_wbf[o + WTOTAL] = l;
    }
}

// ---------------------------------------------------------------------------
// prep: coalesced tiled v_org transpose + img_feat split + bias pack.
// Grid: [0, TRB): transpose tiles; [TRB, TRB+IFB): imgf; last: bias.
// ---------------------------------------------------------------------------
constexpr int TR_TILES_B = 2 * (C_ / 32);             // 2 k-tiles x 16 c-tiles
constexpr int TRB = B_ * TR_TILES_B;                   // 8192
constexpr int IFB = (int)(SZ_IMG0 / 2048);             // 3136

__global__ void prep_kernel(const float* __restrict__ v_org,
                            const float* __restrict__ imgf,
                            const float* __restrict__ b0,
                            const float* __restrict__ b1)
{
    int bx = blockIdx.x;
    int tx = threadIdx.x, ty = threadIdx.y;
    int tid = ty * 32 + tx;

    if (bx < TRB) {
        // tiled transpose: v_org[b][c][k] -> img0[b][k][c] (fp32 + bf16 split)
        __shared__ float tile[32][33];
        int b   = bx / TR_TILES_B;
        int t   = bx % TR_TILES_B;
        int k0  = (t & 1) * 32;              // 0 or 32
        int c0  = (t >> 1) * 32;             // 0..480
        const float* src = v_org + (long)b * C_ * K_;
#pragma unroll
        for (int i = 0; i < 32; i += 8) {
            int c = c0 + ty + i, k = k0 + tx;
            tile[ty + i][tx] = (k < K_) ? src[(long)c * K_ + k] : 0.f;
        }
        __syncthreads();
#pragma unroll
        for (int i = 0; i < 32; i += 8) {
            int k = k0 + ty + i, c = c0 + tx;
            if (k < K_) {
                float v = tile[tx][ty + i];
                long idx = ((long)b * K_ + k) * C_ + c;
                g_scratch[OFF_IMG0 + idx] = v;
                stsplit(ABF_IMG0 + idx, v);
            }
        }
    } else if (bx < TRB + IFB) {
        long base = (long)(bx - TRB) * 2048;
#pragma unroll
        for (int j = 0; j < 8; j++) {
            long i = base + tid + j * 256;
            stsplit(ABF_IMGF + i, imgf[i]);
        }
    } else {
#pragma unroll
        for (int j = 0; j < 8; j++) {
            int i = tid + j * 256;
            if (i < 1024)      g_scratch[OFF_BIASAQN + i] = b0[i];
            else if (i < 2048) g_scratch[OFF_BIASAQN + i] = b1[i - 1024];
        }
    }
}

// ---------------------------------------------------------------------------
// rv gather: bf16 split into ABF_RV (stride 640) AND ABF_CAT cols 1024..
// ---------------------------------------------------------------------------
__global__ void gather_rv_kernel(const int* __restrict__ gt_verb,
                                 const int* __restrict__ role_idx,
                                 const float* __restrict__ vt,
                                 const float* __restrict__ rt)
{
    long idx = (long)blockIdx.x * 256 + threadIdx.x;
    if (idx >= (long)BR_ * TWO_E) return;
    int e = (int)(idx % TWO_E);
    int n = (int)(idx / TWO_E);
    int b = n / R_;
    float val = (e < E_) ? vt[(long)gt_verb[b] * E_ + e]
                         : rt[(long)role_idx[n] * E_ + (e - E_)];
    stsplit(ABF_RV  + (long)n * 640  + e, val);
    stsplit(ABF_CAT + (long)n * 1664 + 1024 + e, val);
}

// ---------------------------------------------------------------------------
// HMMA bf16-split GEMM (round-11 proven config). BM=64, 4 warps (2x2),
// warp tile 32 x (BN/2). 2-stage cp.async pipeline, padded smem.
// ---------------------------------------------------------------------------
template<int BN, int NT, int MAXCTA>
__global__ __launch_bounds__(128, MAXCTA)
void mma_gemm_kernel(long aOff, long wOff,
                     const float* __restrict__ biasPtr, long biasOff,
                     float* CExt, long offC, long offCbf, int cbfStride,
                     int M, int N, int Kp, int act)
{
    constexpr int BM = 64, BKP = 40;
    constexpr int MI  = 2;
    constexpr int ASZ = BM * BKP;
    constexpr int BSZ = BN * BKP;
    constexpr int STG = 2 * ASZ + 2 * BSZ;
    constexpr uint32_t ASZ2 = ASZ * 2, BSZ2 = BSZ * 2;

    extern __shared__ __align__(16) __nv_bfloat16 sm[];
    const __nv_bfloat16* Ahp = g_abf + aOff;
    const __nv_bfloat16* Alp = g_abf + aOff + ATOTAL;
    const __nv_bfloat16* Bwh = g_wbf + wOff;
    const __nv_bfloat16* Bwl = g_wbf + wOff + WTOTAL;
    const float* bias = biasPtr ? biasPtr
                      : (biasOff >= 0 ? (const float*)(g_scratch + biasOff) : nullptr);

    const int tid  = threadIdx.x;
    const int wid  = tid >> 5, lane = tid & 31;
    const int brow = blockIdx.y * BM, bcol = blockIdx.x * BN;
    const int wm   = (wid >> 1) * 32;
    const int wn   = (wid & 1) * (BN / 2);
    const uint32_t sb = smem_u32(sm);

    auto cpAll = [&](int t, int s) {
        const uint32_t st = sb + (uint32_t)(s * STG) * 2;
#pragma unroll
        for (int l = 0; l < 2; l++) {
            int idx = tid + l * 128;
            int row = idx >> 2, seg = idx & 3;
            size_t go = (size_t)(brow + row) * Kp + t * 32 + seg * 8;
            uint32_t so = (uint32_t)(row * BKP + seg * 8) * 2;
            cpa16(st + so,        Ahp + go);
            cpa16(st + ASZ2 + so, Alp + go);
        }
#pragma unroll
        for (int l = 0; l < BN / 32; l++) {
            int idx = tid + l * 128;
            int row = idx >> 2, seg = idx & 3;
            size_t go = (size_t)(bcol + row) * Kp + t * 32 + seg * 8;
            uint32_t so = (uint32_t)(row * BKP + seg * 8) * 2;
            cpa16(st + 2 * ASZ2 + so,        Bwh + go);
            cpa16(st + 2 * ASZ2 + BSZ2 + so, Bwl + go);
        }
    };

    float acc[MI][NT][4];
#pragma unroll
    for (int i = 0; i < MI; i++)
#pragma unroll
        for (int j = 0; j < NT; j++)
#pragma unroll
            for (int q = 0; q < 4; q++) acc[i][j][q] = 0.f;

    const int nCh = Kp / 32;

    cpAll(0, 0); CP_COMMIT();
    CP_WAIT0();
    __syncthreads();

    const int aRow = (lane & 7) + ((lane >> 3) & 1) * 8;
    const int aCol = (lane >> 4) * 8;
    const int bRow = (lane & 7) + ((lane >> 4) & 1) * 8;
    const int bCol = ((lane >> 3) & 1) * 8;

    for (int t = 0; t < nCh; t++) {
        const int s = t & 1;
        if (t + 1 < nCh) { cpAll(t + 1, s ^ 1); CP_COMMIT(); }

        const uint32_t ahB = sb + (uint32_t)(s * STG) * 2;
        const uint32_t alB = ahB + ASZ2;
        const uint32_t bhB = alB + ASZ2;
        const uint32_t blB = bhB + BSZ2;

#pragma unroll
        for (int ks = 0; ks < 2; ks++) {
            uint32_t ah[MI][4], al[MI][4];
#pragma unroll
            for (int mi = 0; mi < MI; mi++) {
                uint32_t off = (uint32_t)((wm + mi * 16 + aRow) * BKP + ks * 16 + aCol) * 2;
                ldm_x4(ah[mi], ahB + off);
                ldm_x4(al[mi], alB + off);
            }
            uint32_t bh[NT][2], bl[NT][2];
#pragma unroll
            for (int bt = 0; bt < NT / 2; bt++) {
                uint32_t off = (uint32_t)((wn + bt * 16 + bRow) * BKP + ks * 16 + bCol) * 2;
                uint32_t r[4];
                ldm_x4(r, bhB + off);
                bh[2 * bt][0] = r[0]; bh[2 * bt][1] = r[1];
                bh[2 * bt + 1][0] = r[2]; bh[2 * bt + 1][1] = r[3];
                ldm_x4(r, blB + off);
                bl[2 * bt][0] = r[0]; bl[2 * bt][1] = r[1];
                bl[2 * bt + 1][0] = r[2]; bl[2 * bt + 1][1] = r[3];
            }
#pragma unroll
            for (int mi = 0; mi < MI; mi++)
#pragma unroll
                for (int ni = 0; ni < NT; ni++) {
                    mma16816(acc[mi][ni], ah[mi], bh[ni]);
                    mma16816(acc[mi][ni], ah[mi], bl[ni]);
                    mma16816(acc[mi][ni], al[mi], bh[ni]);
                }
        }

        if (t + 1 < nCh) {
            CP_WAIT0();
            __syncthreads();
        }
    }

    // epilogue
    float* C = CExt ? CExt : (g_scratch + offC);
#pragma unroll
    for (int mi = 0; mi < MI; mi++) {
#pragma unroll
        for (int ni = 0; ni < NT; ni++) {
            int r0 = brow + wm + mi * 16 + (lane >> 2);
            int c0 = bcol + wn + ni * 8 + 2 * (lane & 3);
#pragma unroll
            for (int half = 0; half < 2; half++) {
                int gr = r0 + half * 8;
                float v0 = acc[mi][ni][2 * half + 0];
                float v1 = acc[mi][ni][2 * half + 1];
                if (offCbf >= 0) {
                    if (bias) { v0 += bias[c0]; v1 += bias[c0 + 1]; }
                    if (act)  { v0 = fmaxf(v0, 0.f); v1 = fmaxf(v1, 0.f); }
                    __nv_bfloat16 h0 = __float2bfloat16(v0);
                    __nv_bfloat16 h1 = __float2bfloat16(v1);
                    __nv_bfloat16 l0 = __float2bfloat16(v0 - __bfloat162float(h0));
                    __nv_bfloat16 l1 = __float2bfloat16(v1 - __bfloat162float(h1));
                    long o = offCbf + (long)gr * cbfStride + c0;
                    uint32_t hp = (uint32_t)__bfloat16_as_ushort(h0)
                                | ((uint32_t)__bfloat16_as_ushort(h1) << 16);
                    uint32_t lp = (uint32_t)__bfloat16_as_ushort(l0)
                                | ((uint32_t)__bfloat16_as_ushort(l1) << 16);
                    *(uint32_t*)&g_abf[o] = hp;
                    *(uint32_t*)&g_abf[o + ATOTAL] = lp;
                } else {
                    if (c0 < N) {
                        float o = v0 + (bias ? bias[c0] : 0.f);
                        if (act) o = fmaxf(o, 0.f);
                        C[(size_t)gr * N + c0] = o;
                    }
                    if (c0 + 1 < N) {
                        float o = v1 + (bias ? bias[c0 + 1] : 0.f);
                        if (act) o = fmaxf(o, 0.f);
                        C[(size_t)gr * N + c0 + 1] = o;
                    }
                }
            }
        }
    }
}

constexpr int SMEM_BIG   = 2 * (2 * 64 * 40 + 2 * 128 * 40) * 2;  // 61440 B
constexpr int SMEM_SMALL = 2 * (2 * 64 * 40 + 2 * 64 * 40) * 2;   // 40960 B

static inline void tgemm(long aOff, long wOff, const float* bias, long biasOff,
                         float* CExt, long offC, long offCbf, int cbfStride,
                         int M, int N, int Np, int Kp, int act)
{
    if (M >= 4096 || Np >= 2048) {
        dim3 grid(Np / 128, M / 64);
        mma_gemm_kernel<128, 8, 3><<<grid, 128, SMEM_BIG>>>(
            aOff, wOff, bias, biasOff, CExt, offC, offCbf, cbfStride, M, N, Kp, act);
    } else {
        dim3 grid(Np / 64, M / 64);
        mma_gemm_kernel<64, 4, 4><<<grid, 128, SMEM_SMALL>>>(
            aOff, wOff, bias, biasOff, CExt, offC, offCbf, cbfStride, M, N, Kp, act);
    }
}

// ---------------------------------------------------------------------------
// Visual attention (block per (b, src)). float4 logit phase.
// ---------------------------------------------------------------------------
__global__ __launch_bounds__(256) void att6_kernel(
    long offQA, int qStride,
    const float* __restrict__ aoW, const float* __restrict__ aoB,
    const float* __restrict__ imgf,
    long abfOut0, long abfOut1)
{
    int b  = blockIdx.x;
    int which = blockIdx.y;
    int n0 = b * R_;
    const float* V   = g_scratch + (which ? OFF_V2 : OFF_V1) + (long)b * K_ * H_;
    const float* img = which ? (imgf + (long)b * K_ * C_)
                             : (g_scratch + OFF_IMG0 + (long)b * K_ * C_);
    long abfOut = which ? abfOut1 : abfOut0;

    __shared__ __align__(16) float qa[R_][H_];
    __shared__ float attw[R_][K_ + 1];

    int tid = threadIdx.x, wid = tid >> 5, lane = tid & 31;

    for (int idx = tid; idx < R_ * H_; idx += 256) {
        int r = idx / H_, h = idx % H_;
        qa[r][h] = g_scratch[offQA + (long)(n0 + r) * qStride + h] * aoW[h];
    }
    __syncthreads();

    for (int k = wid; k < K_; k += 8) {
        const float4* vk4 = (const float4*)(V + (long)k * H_);
        float s0=0,s1=0,s2=0,s3=0,s4=0,s5=0;
#pragma unroll
        for (int h4 = lane; h4 < H_ / 4; h4 += 32) {
            float4 v = vk4[h4];
            float4 q;
            q = *(const float4*)&qa[0][h4 * 4];
            s0 += v.x*q.x + v.y*q.y + v.z*q.z + v.w*q.w;
            q = *(const float4*)&qa[1][h4 * 4];
            s1 += v.x*q.x + v.y*q.y + v.z*q.z + v.w*q.w;
            q = *(const float4*)&qa[2][h4 * 4];
            s2 += v.x*q.x + v.y*q.y + v.z*q.z + v.w*q.w;
            q = *(const float4*)&qa[3][h4 * 4];
            s3 += v.x*q.x + v.y*q.y + v.z*q.z + v.w*q.w;
            q = *(const float4*)&qa[4][h4 * 4];
            s4 += v.x*q.x + v.y*q.y + v.z*q.z + v.w*q.w;
            q = *(const float4*)&qa[5][h4 * 4];
            s5 += v.x*q.x + v.y*q.y + v.z*q.z + v.w*q.w;
        }
#pragma unroll
        for (int o = 16; o; o >>= 1) {
            s0 += __shfl_xor_sync(0xffffffffu, s0, o);
            s1 += __shfl_xor_sync(0xffffffffu, s1, o);
            s2 += __shfl_xor_sync(0xffffffffu, s2, o);
            s3 += __shfl_xor_sync(0xffffffffu, s3, o);
            s4 += __shfl_xor_sync(0xffffffffu, s4, o);
            s5 += __shfl_xor_sync(0xffffffffu, s5, o);
        }
        if (lane == 0) {
            float ab = aoB[0];
            attw[0][k] = s0 + ab; attw[1][k] = s1 + ab; attw[2][k] = s2 + ab;
            attw[3][k] = s3 + ab; attw[4][k] = s4 + ab; attw[5][k] = s5 + ab;
        }
    }
    __syncthreads();

    if (tid < R_) {
        float mx = -1e30f;
        for (int k = 0; k < K_; k++) mx = fmaxf(mx, attw[tid][k]);
        float sum = 0.f;
        for (int k = 0; k < K_; k++) sum += expf(attw[tid][k] - mx);
        float inv = 1.f / sum;
        for (int k = 0; k < K_; k++) attw[tid][k] = expf(attw[tid][k] - mx) * inv;
    }
    __syncthreads();

    for (int c = tid; c < C_; c += 256) {
        float a0=0,a1=0,a2=0,a3=0,a4=0,a5=0;
#pragma unroll 7
        for (int k = 0; k < K_; k++) {
            float f = img[(long)k * C_ + c];
            a0 = fmaf(attw[0][k], f, a0); a1 = fmaf(attw[1][k], f, a1);
            a2 = fmaf(attw[2][k], f, a2); a3 = fmaf(attw[3][k], f, a3);
            a4 = fmaf(attw[4][k], f, a4); a5 = fmaf(attw[5][k], f, a5);
        }
        long base = abfOut + (long)n0 * C_ + c;
        stsplit(base,          a0); stsplit(base + C_,     a1);
        stsplit(base + 2 * C_, a2); stsplit(base + 3 * C_, a3);
        stsplit(base + 4 * C_, a4); stsplit(base + 5 * C_, a5);
    }
}

// ---------------------------------------------------------------------------
// MFB pool. mode 0: write fp32 rows (OUT/OUTV) + bf16 split (ABF_OUT).
// mode 1: fuse gated combine — r=out2; read outv/ans0 fp32; write ABF_OUTF.
// ---------------------------------------------------------------------------
__global__ void mfb_kernel(long offQ, int qStride, int qWrap,
                           long offV, int mode)
{
    int n = blockIdx.x;
    const float* q = g_scratch + offQ + (long)(n % qWrap) * qStride;
    const float* v = g_scratch + offV + (long)n * H_;
    int tid = threadIdx.x;

    float s = 0.f;
    for (int h = tid; h < H_; h += 256) {
        float z = q[h] * v[h];
        s += fabsf(z);
    }
    __shared__ float red[8];
#pragma unroll
    for (int off = 16; off; off >>= 1) s += __shfl_xor_sync(0xffffffffu, s, off);
    if ((tid & 31) == 0) red[tid >> 5] = s;
    __syncthreads();
    float tot = 0.f;
#pragma unroll
    for (int i = 0; i < 8; i++) tot += red[i];
    float inv = 1.f / fmaxf(sqrtf(tot), 1e-12f);

    for (int h = tid; h < H_; h += 256) {
        float z = q[h] * v[h];
        float sg = (z > 0.f) ? sqrtf(z) : -sqrtf(-z);
        float r = sg * inv;
        if (mode == 0) {
            g_scratch[OFF_OUT + (long)n * H_ + h] = r;
            stsplit(ABF_OUT + (long)n * H_ + h, r);
        } else {
            float ov = g_scratch[OFF_OUT + SZ_H + (long)n * H_ + h];
            float a0 = g_scratch[OFF_OUT + (long)n * H_ + h];
            float g  = 1.f / (1.f + expf(-(r + ov)));
            stsplit(ABF_OUTF + (long)n * H_ + h, (1.f - g) * ov + g * tanhf(r + a0));
        }
    }
}

// ---------------------------------------------------------------------------
// Masked role attention -> ctx as bf16 split
// ---------------------------------------------------------------------------
__global__ void role_att_kernel(const int* __restrict__ mask)
{
    int b = blockIdx.x;
    const float* base = g_scratch + OFF_QKV3 + (long)b * R_ * 3072;

    __shared__ float sc[R_][R_];
    __shared__ float attn[R_][R_];
    int tid = threadIdx.x, wid = tid >> 5, lane = tid & 31;

    for (int p = wid; p < R_ * R_; p += 8) {
        int i = p / R_, j = p % R_;
        const float* qh = base + (long)i * 3072;
        const float* kh = base + (long)j * 3072 + 1024;
        float s = 0.f;
        for (int h = lane; h < H_; h += 32)
            s = fmaf(qh[h], kh[h], s);
#pragma unroll
        for (int o = 16; o; o >>= 1) s += __shfl_xor_sync(0xffffffffu, s, o);
        if (lane == 0) {
            bool valid = (i != j) && (mask[((long)b * R_ + i) * R_ + j] > 0);
            sc[i][j] = valid ? s * (1.f / 32.f) : -1e9f;
        }
    }
    __syncthreads();

    if (tid < R_ * R_) {
        int i = tid / R_, j = tid % R_;
        float mx = -1e30f;
        for (int jj = 0; jj < R_; jj++) mx = fmaxf(mx, sc[i][jj]);
        float sum = 0.f;
        for (int jj = 0; jj < R_; jj++) sum += expf(sc[i][jj] - mx);
        attn[i][j] = expf(sc[i][j] - mx) / sum;
    }
    __syncthreads();

    for (int idx = tid; idx < R_ * H_; idx += 256) {
        int i = idx / H_, h = idx % H_;
        float acc = 0.f;
#pragma unroll
        for (int j = 0; j < R_; j++)
            acc = fmaf(attn[i][j], base[(long)j * 3072 + 2048 + h], acc);
        stsplit(ABF_CTX + (long)(b * R_ + i) * H_ + h, acc);
    }
}

// ---------------------------------------------------------------------------
// Launch sequence
// ---------------------------------------------------------------------------
extern "C" void kernel_launch(void* const* d_in, const int* in_sizes, int n_in,
                              void* d_out, int out_size)
{
    const float* v_org    = (const float*)d_in[0];
    const float* img_feat = (const float*)d_in[1];
    const int*   gt_verb  = (const int*)d_in[2];
    const int*   role_idx = (const int*)d_in[3];
    const int*   mask     = (const int*)d_in[4];
    const float* verb_t   = (const float*)d_in[5];
    const float* role_t   = (const float*)d_in[6];
    const float* qc_W = (const float*)d_in[7];   const float* qc_b = (const float*)d_in[8];
    const float* av_W = (const float*)d_in[9];   const float* av_b = (const float*)d_in[10];
    const float* aq_W = (const float*)d_in[11];  const float* aq_b = (const float*)d_in[12];
    const float* ao_W = (const float*)d_in[13];  const float* ao_b = (const float*)d_in[14];
    const float* vn_W = (const float*)d_in[15];  const float* vn_b = (const float*)d_in[16];
    const float* qn_W = (const float*)d_in[17];  const float* qn_b = (const float*)d_in[18];
    const float* Wq   = (const float*)d_in[19];
    const float* Wk   = (const float*)d_in[20];
    const float* Wv   = (const float*)d_in[21];
    const float* Wo   = (const float*)d_in[22];
    const float* uqc_W = (const float*)d_in[23]; const float* uqc_b = (const float*)d_in[24];
    const float* cls_W = (const float*)d_in[25]; const float* cls_b = (const float*)d_in[26];

    cudaFuncSetAttribute((const void*)mma_gemm_kernel<128, 8, 3>,
                         cudaFuncAttributeMaxDynamicSharedMemorySize, SMEM_BIG);
    cudaFuncSetAttribute((const void*)mma_gemm_kernel<64, 4, 4>,
                         cudaFuncAttributeMaxDynamicSharedMemorySize, SMEM_SMALL);

    // megaconv descriptor table
    WAll P;
    const float* Ws[11] = {qc_W, av_W, aq_W, qn_W, vn_W, Wq, Wk, Wv, Wo, uqc_W, cls_W};
    int  Ks[11]  = {600, 512, 1024, 1024, 512, 1024, 1024, 1024, 1024, CATW, 1024};
    int  Ns[11]  = {1024,1024,1024, 1024, 1024,1024, 1024, 1024, 1024, 1024, NL_};
    int  tK[11]  = {20,  16,  32,   32,   16,  32,   32,   32,   32,   52,   32};
    int  Nps[11] = {1024,1024,1024, 1024, 1024,1024, 1024, 1024, 1024, 1024, 2048};
    long offs[11]= {WOFF_QC, WOFF_AV, WOFF_AQN, WOFF_AQN + 1024L * 1024, WOFF_VN,
                    WOFF_QKV, WOFF_QKV + 1024L * 1024, WOFF_QKV + 2048L * 1024,
                    WOFF_WO, WOFF_UQC, WOFF_CLS};
    int pre = 0;
    for (int i = 0; i < 11; i++) {
        P.W[i] = Ws[i]; P.K[i] = Ks[i]; P.N[i] = Ns[i];
        P.tilesK[i] = tK[i]; P.off[i] = offs[i];
        P.pre[i] = pre;
        pre += tK[i] * (Nps[i] / 32);
    }
    P.pre[11] = pre;

    // 0: prep (tiled transpose + imgf + bias), 1: megaconv, 2: gather, 3: QEMB
    prep_kernel<<<TRB + IFB + 1, dim3(32, 8)>>>(v_org, img_feat, aq_b, qn_b);
    megaconv_kernel<<<pre, dim3(32, 8)>>>(P);
    gather_rv_kernel<<<(int)(((long)BR_ * TWO_E + 255) / 256), 256>>>(gt_verb, role_idx,
                                                                      verb_t, role_t);
    // query chain — QEMB first (round-11 proven order)
    tgemm(ABF_RV, WOFF_QC, qc_b, -1, nullptr, 0, ABF_QEMB, 1024,
          BR_, 1024, 1024, 640, 1);

    // FUSED V1+V2 GEMM
    tgemm(ABF_IMG0, WOFF_AV, av_b, -1, nullptr, OFF_V1, -1, 0,
          2 * B_ * K_, 1024, 1024, 512, 1);

    tgemm(ABF_QEMB, WOFF_AQN, nullptr, OFF_BIASAQN, nullptr, OFF_QAQR, -1, 0,
          BR_, 2048, 2048, 1024, 1);

    // attention 1 + attention-verb in ONE launch (grid B x 2)
    att6_kernel<<<dim3(B_, 2), 256>>>(OFF_QAQR, 2048, ao_W, ao_b, img_feat,
                                      ABF_VEMB12, ABF_VEMB12 + (long)BR_ * 512);

    // fused VN over [VEMB1;VEMB2]
    tgemm(ABF_VEMB12, WOFF_VN, vn_b, -1, nullptr, OFF_VREPR1, -1, 0,
          2 * BR_, 1024, 1024, 512, 1);

    // fused MFB for OUT & OUTV (mode 0)
    mfb_kernel<<<2 * BR_, 256>>>(OFF_QAQR + 1024, 2048, BR_, OFF_VREPR1, 0);

    // role-node neighbour attention
    tgemm(ABF_OUT, WOFF_QKV, nullptr, -1, nullptr, OFF_QKV3, -1, 0,
          BR_, 3072, 3072, 1024, 0);
    role_att_kernel<<<B_, 256>>>(mask);
    // WO writes bf16 split DIRECTLY into CAT rows (stride 1664)
    tgemm(ABF_CTX, WOFF_WO, nullptr, -1, nullptr, 0, ABF_CAT, 1664,
          BR_, 1024, 1024, 1024, 0);

    // updated query
    tgemm(ABF_CAT, WOFF_UQC, uqc_b, -1, nullptr, 0, ABF_UQ, 1024,
          BR_, 1024, 1024, 1664, 1);
    tgemm(ABF_UQ, WOFF_AQN, nullptr, OFF_BIASAQN, nullptr, OFF_QAQR2, -1, 0,
          BR_, 2048, 2048, 1024, 1);

    // attention 2 (single source)
    att6_kernel<<<dim3(B_, 1), 256>>>(OFF_QAQR2, 2048, ao_W, ao_b, img_feat,
                                      ABF_VEMB3, ABF_VEMB3);
    tgemm(ABF_VEMB3, WOFF_VN, vn_b, -1, nullptr, OFF_VREPR2, -1, 0,
          BR_, 1024, 1024, 512, 1);

    // MFB(out2) fused with gated combine (mode 1) -> ABF_OUTF
    mfb_kernel<<<BR_, 256>>>(OFF_QAQR2 + 1024, 2048, BR_, OFF_VREPR2, 1);

    // classifier -> d_out
    tgemm(ABF_OUTF, WOFF_CLS, cls_b, -1, (float*)d_out, 0, -1, 0,
          BR_, NL_, 2048, 1024, 0);
}

// round 14
// speedup vs baseline: 1.2893x; 1.2538x over previous
#include <cuda_runtime.h>
#include <cuda_fp16.h>
#include <cstdint>
#include <math.h>

// ---------------------------------------------------------------------------
// Problem dims
// ---------------------------------------------------------------------------
constexpr int B_   = 256;
constexpr int R_   = 6;
constexpr int K_   = 49;
constexpr int C_   = 512;
constexpr int H_   = 1024;
constexpr int E_   = 300;
constexpr int BR_  = B_ * R_;          // 1536
constexpr int NL_  = 2001;
constexpr int TWO_E = 2 * E_;          // 600
constexpr int CATW  = H_ + TWO_E;      // 1624

// ---------------------------------------------------------------------------
// fp32 scratch
// ---------------------------------------------------------------------------
constexpr long SZ_IMG0 = (long)B_ * K_ * C_;   // 6422528
constexpr long SZ_V    = (long)B_ * K_ * H_;
constexpr long SZ_H    = (long)BR_ * H_;
constexpr long SZ_2H   = (long)BR_ * 2048;
constexpr long SZ_3H   = (long)BR_ * 3072;

constexpr long OFF_IMG0  = 0;
constexpr long OFF_V1    = OFF_IMG0  + SZ_IMG0;
constexpr long OFF_V2    = OFF_V1    + SZ_V;
constexpr long OFF_QAQR  = OFF_V2    + SZ_V;      // [BR,2048] = [qa|qrepr]
constexpr long OFF_VREPR1= OFF_QAQR  + SZ_2H;     // [2BR,1024] (VREPR1;VREPRV)
constexpr long OFF_OUT   = OFF_VREPR1+ 2*SZ_H;    // [2BR,1024] (OUT;OUTV)
constexpr long OFF_QKV3  = OFF_OUT   + 2*SZ_H;    // [BR,3072]
constexpr long OFF_QAQR2 = OFF_QKV3  + SZ_3H;     // [BR,2048]
constexpr long OFF_VREPR2= OFF_QAQR2 + SZ_2H;
constexpr long OFF_BIASAQN = OFF_VREPR2 + SZ_H;   // 2048 floats
constexpr long SCRATCH_TOTAL = OFF_BIASAQN + 2048;

__device__ float g_scratch[SCRATCH_TOTAL];

// ---------------------------------------------------------------------------
// fp16 ACTIVATION plane (SINGLE plane — 2-term scheme). Zero-initialized.
// ---------------------------------------------------------------------------
constexpr long ABF_IMG0  = 0;                          // [12544][512]
constexpr long ABF_IMGF  = ABF_IMG0  + 12544L * 512;   // [12544][512]
constexpr long ABF_RV    = ABF_IMGF  + 12544L * 512;   // [1536][640]
constexpr long ABF_QEMB  = ABF_RV    + 1536L * 640;    // [1536][1024]
constexpr long ABF_VEMB12= ABF_QEMB  + 1536L * 1024;   // [3072][512]
constexpr long ABF_VEMB3 = ABF_VEMB12+ 3072L * 512;    // [1536][512]
constexpr long ABF_OUT   = ABF_VEMB3 + 1536L * 512;    // [3072][1024]
constexpr long ABF_CTX   = ABF_OUT   + 3072L * 1024;   // [1536][1024]
constexpr long ABF_CAT   = ABF_CTX   + 1536L * 1024;   // [1536][1664]
constexpr long ABF_UQ    = ABF_CAT   + 1536L * 1664;   // [1536][1024]
constexpr long ABF_OUTF  = ABF_UQ    + 1536L * 1024;   // [1536][1024]
constexpr long ATOTAL    = ABF_OUTF  + 1536L * 1024;

__device__ __align__(256) __half g_abf[ATOTAL];

// ---------------------------------------------------------------------------
// fp16 WEIGHT planes (transposed [Npad][Kpad], hi at off, lo at off+WTOTAL)
// ---------------------------------------------------------------------------
constexpr long WOFF_QC  = 0;                           // [1024][640]
constexpr long WOFF_AV  = WOFF_QC  + 1024L * 640;      // [1024][512]
constexpr long WOFF_AQN = WOFF_AV  + 1024L * 512;      // [2048][1024]
constexpr long WOFF_VN  = WOFF_AQN + 2048L * 1024;     // [1024][512]
constexpr long WOFF_QKV = WOFF_VN  + 1024L * 512;      // [3072][1024]
constexpr long WOFF_WO  = WOFF_QKV + 3072L * 1024;     // [1024][1024]
constexpr long WOFF_UQC = WOFF_WO  + 1024L * 1024;     // [1024][1664]
constexpr long WOFF_CLS = WOFF_UQC + 1024L * 1664;     // [2048][1024]
constexpr long WTOTAL   = WOFF_CLS + 2048L * 1024;

__device__ __align__(256) __half g_wbf[2 * WTOTAL];

// ---------------------------------------------------------------------------
// helpers
// ---------------------------------------------------------------------------
__device__ __forceinline__ uint32_t smem_u32(const void* p) {
    uint32_t a;
    asm("{ .reg .u64 t; cvta.to.shared.u64 t, %1; cvt.u32.u64 %0, t; }" : "=r"(a) : "l"(p));
    return a;
}
__device__ __forceinline__ void stA(long base, float v) {
    g_abf[base] = __float2half_rn(v);
}
__device__ __forceinline__ void ldm_x4(uint32_t* r, uint32_t addr) {
    asm volatile("ldmatrix.sync.aligned.m8n8.x4.shared.b16 {%0,%1,%2,%3}, [%4];"
                 : "=r"(r[0]), "=r"(r[1]), "=r"(r[2]), "=r"(r[3]) : "r"(addr));
}
__device__ __forceinline__ void mma16816(float* c, const uint32_t* a, const uint32_t* b) {
    asm volatile(
        "mma.sync.aligned.m16n8k16.row.col.f32.f16.f16.f32 "
        "{%0,%1,%2,%3}, {%4,%5,%6,%7}, {%8,%9}, {%0,%1,%2,%3};"
        : "+f"(c[0]), "+f"(c[1]), "+f"(c[2]), "+f"(c[3])
        : "r"(a[0]), "r"(a[1]), "r"(a[2]), "r"(a[3]), "r"(b[0]), "r"(b[1]));
}
__device__ __forceinline__ void cpa16(uint32_t s, const void* g) {
    asm volatile("cp.async.cg.shared.global [%0], [%1], 16;" :: "r"(s), "l"(g));
}
#define CP_COMMIT() asm volatile("cp.async.commit_group;" ::: "memory")
#define CP_WAIT0()  asm volatile("cp.async.wait_group 0;" ::: "memory")

// ---------------------------------------------------------------------------
// megaconv: ALL weight transposes + fp16 hi/lo splits in ONE launch
// ---------------------------------------------------------------------------
struct WAll {
    const float* W[11];
    int K[11], N[11], tilesK[11];
    int pre[12];
    long off[11];
};

__global__ void megaconv_kernel(WAll P)
{
    __shared__ float tile[32][33];
    int bx = blockIdx.x;
    int w = 0;
    while (bx >= P.pre[w + 1]) w++;
    int tix = bx - P.pre[w];
    int tK  = P.tilesK[w];
    int k0  = (tix % tK) * 32;
    int n0  = (tix / tK) * 32;
    int K = P.K[w], N = P.N[w], Kp = tK * 32;
    const float* W = P.W[w];
    long off = P.off[w];

    int tx = threadIdx.x, ty = threadIdx.y;
#pragma unroll
    for (int i = 0; i < 32; i += 8) {
        int k = k0 + ty + i, n = n0 + tx;
        tile[ty + i][tx] = (k < K && n < N) ? W[(size_t)k * N + n] : 0.f;
    }
    __syncthreads();
#pragma unroll
    for (int i = 0; i < 32; i += 8) {
        int n = n0 + ty + i, k = k0 + tx;
        float v = tile[tx][ty + i];
        __half h = __float2half_rn(v);
        __half l = __float2half_rn(v - __half2float(h));
        long o = off + (long)n * Kp + k;
        g_wbf[o] = h;
        g_wbf[o + WTOTAL] = l;
    }
}

// ---------------------------------------------------------------------------
// prep: coalesced tiled v_org transpose + img_feat convert + bias pack.
// ---------------------------------------------------------------------------
constexpr int TR_TILES_B = 2 * (C_ / 32);
constexpr int TRB = B_ * TR_TILES_B;                   // 8192
constexpr int IFB = (int)(SZ_IMG0 / 2048);             // 3136

__global__ void prep_kernel(const float* __restrict__ v_org,
                            const float* __restrict__ imgf,
                            const float* __restrict__ b0,
                            const float* __restrict__ b1)
{
    int bx = blockIdx.x;
    int tx = threadIdx.x, ty = threadIdx.y;
    int tid = ty * 32 + tx;

    if (bx < TRB) {
        __shared__ float tile[32][33];
        int b   = bx / TR_TILES_B;
        int t   = bx % TR_TILES_B;
        int k0  = (t & 1) * 32;
        int c0  = (t >> 1) * 32;
        const float* src = v_org + (long)b * C_ * K_;
#pragma unroll
        for (int i = 0; i < 32; i += 8) {
            int c = c0 + ty + i, k = k0 + tx;
            tile[ty + i][tx] = (k < K_) ? src[(long)c * K_ + k] : 0.f;
        }
        __syncthreads();
#pragma unroll
        for (int i = 0; i < 32; i += 8) {
            int k = k0 + ty + i, c = c0 + tx;
            if (k < K_) {
                float v = tile[tx][ty + i];
                long idx = ((long)b * K_ + k) * C_ + c;
                g_scratch[OFF_IMG0 + idx] = v;
                stA(ABF_IMG0 + idx, v);
            }
        }
    } else if (bx < TRB + IFB) {
        long base = (long)(bx - TRB) * 2048;
#pragma unroll
        for (int j = 0; j < 8; j++) {
            long i = base + tid + j * 256;
            stA(ABF_IMGF + i, imgf[i]);
        }
    } else {
#pragma unroll
        for (int j = 0; j < 8; j++) {
            int i = tid + j * 256;
            if (i < 1024)      g_scratch[OFF_BIASAQN + i] = b0[i];
            else if (i < 2048) g_scratch[OFF_BIASAQN + i] = b1[i - 1024];
        }
    }
}

// ---------------------------------------------------------------------------
// rv gather: fp16 into ABF_RV (stride 640) AND ABF_CAT cols 1024..
// ---------------------------------------------------------------------------
__global__ void gather_rv_kernel(const int* __restrict__ gt_verb,
                                 const int* __restrict__ role_idx,
                                 const float* __restrict__ vt,
                                 const float* __restrict__ rt)
{
    long idx = (long)blockIdx.x * 256 + threadIdx.x;
    if (idx >= (long)BR_ * TWO_E) return;
    int e = (int)(idx % TWO_E);
    int n = (int)(idx / TWO_E);
    int b = n / R_;
    float val = (e < E_) ? vt[(long)gt_verb[b] * E_ + e]
                         : rt[(long)role_idx[n] * E_ + (e - E_)];
    stA(ABF_RV  + (long)n * 640  + e, val);
    stA(ABF_CAT + (long)n * 1664 + 1024 + e, val);
}

// ---------------------------------------------------------------------------
// HMMA fp16 2-term GEMM: D = Ah@(Bh+Bl). BM=64, 4 warps (2x2),
// warp tile 32 x (BN/2). 2-stage cp.async pipeline, padded smem.
// Stage: [Ah | Bh | Bl].
// ---------------------------------------------------------------------------
template<int BN, int NT, int MAXCTA>
__global__ __launch_bounds__(128, MAXCTA)
void mma_gemm_kernel(long aOff, long wOff,
                     const float* __restrict__ biasPtr, long biasOff,
                     float* CExt, long offC, long offCbf, int cbfStride,
                     int M, int N, int Kp, int act)
{
    constexpr int BM = 64, BKP = 40;
    constexpr int MI  = 2;
    constexpr int ASZ = BM * BKP;
    constexpr int BSZ = BN * BKP;
    constexpr int STG = ASZ + 2 * BSZ;
    constexpr uint32_t ASZ2 = ASZ * 2, BSZ2 = BSZ * 2;

    extern __shared__ __align__(16) __half sm[];
    const __half* Ahp = g_abf + aOff;
    const __half* Bwh = g_wbf + wOff;
    const __half* Bwl = g_wbf + wOff + WTOTAL;
    const float* bias = biasPtr ? biasPtr
                      : (biasOff >= 0 ? (const float*)(g_scratch + biasOff) : nullptr);

    const int tid  = threadIdx.x;
    const int wid  = tid >> 5, lane = tid & 31;
    const int brow = blockIdx.y * BM, bcol = blockIdx.x * BN;
    const int wm   = (wid >> 1) * 32;
    const int wn   = (wid & 1) * (BN / 2);
    const uint32_t sb = smem_u32(sm);

    auto cpAll = [&](int t, int s) {
        const uint32_t st = sb + (uint32_t)(s * STG) * 2;
#pragma unroll
        for (int l = 0; l < 2; l++) {                 // A: 64 rows x 4 segs, 1 plane
            int idx = tid + l * 128;
            int row = idx >> 2, seg = idx & 3;
            size_t go = (size_t)(brow + row) * Kp + t * 32 + seg * 8;
            uint32_t so = (uint32_t)(row * BKP + seg * 8) * 2;
            cpa16(st + so, Ahp + go);
        }
#pragma unroll
        for (int l = 0; l < BN / 32; l++) {           // B: BN rows x 4 segs, 2 planes
            int idx = tid + l * 128;
            int row = idx >> 2, seg = idx & 3;
            size_t go = (size_t)(bcol + row) * Kp + t * 32 + seg * 8;
            uint32_t so = (uint32_t)(row * BKP + seg * 8) * 2;
            cpa16(st + ASZ2 + so,        Bwh + go);
            cpa16(st + ASZ2 + BSZ2 + so, Bwl + go);
        }
    };

    float acc[MI][NT][4];
#pragma unroll
    for (int i = 0; i < MI; i++)
#pragma unroll
        for (int j = 0; j < NT; j++)
#pragma unroll
            for (int q = 0; q < 4; q++) acc[i][j][q] = 0.f;

    const int nCh = Kp / 32;

    cpAll(0, 0); CP_COMMIT();
    CP_WAIT0();
    __syncthreads();

    const int aRow = (lane & 7) + ((lane >> 3) & 1) * 8;
    const int aCol = (lane >> 4) * 8;
    const int bRow = (lane & 7) + ((lane >> 4) & 1) * 8;
    const int bCol = ((lane >> 3) & 1) * 8;

    for (int t = 0; t < nCh; t++) {
        const int s = t & 1;
        if (t + 1 < nCh) { cpAll(t + 1, s ^ 1); CP_COMMIT(); }

        const uint32_t ahB = sb + (uint32_t)(s * STG) * 2;
        const uint32_t bhB = ahB + ASZ2;
        const uint32_t blB = bhB + BSZ2;

#pragma unroll
        for (int ks = 0; ks < 2; ks++) {
            uint32_t ah[MI][4];
#pragma unroll
            for (int mi = 0; mi < MI; mi++) {
                uint32_t off = (uint32_t)((wm + mi * 16 + aRow) * BKP + ks * 16 + aCol) * 2;
                ldm_x4(ah[mi], ahB + off);
            }
            uint32_t bh[NT][2], bl[NT][2];
#pragma unroll
            for (int bt = 0; bt < NT / 2; bt++) {
                uint32_t off = (uint32_t)((wn + bt * 16 + bRow) * BKP + ks * 16 + bCol) * 2;
                uint32_t r[4];
                ldm_x4(r, bhB + off);
                bh[2 * bt][0] = r[0]; bh[2 * bt][1] = r[1];
                bh[2 * bt + 1][0] = r[2]; bh[2 * bt + 1][1] = r[3];
                ldm_x4(r, blB + off);
                bl[2 * bt][0] = r[0]; bl[2 * bt][1] = r[1];
                bl[2 * bt + 1][0] = r[2]; bl[2 * bt + 1][1] = r[3];
            }
#pragma unroll
            for (int mi = 0; mi < MI; mi++)
#pragma unroll
                for (int ni = 0; ni < NT; ni++) {
                    mma16816(acc[mi][ni], ah[mi], bh[ni]);
                    mma16816(acc[mi][ni], ah[mi], bl[ni]);
                }
        }

        if (t + 1 < nCh) {
            CP_WAIT0();
            __syncthreads();
        }
    }

    // epilogue
    float* C = CExt ? CExt : (g_scratch + offC);
#pragma unroll
    for (int mi = 0; mi < MI; mi++) {
#pragma unroll
        for (int ni = 0; ni < NT; ni++) {
            int r0 = brow + wm + mi * 16 + (lane >> 2);
            int c0 = bcol + wn + ni * 8 + 2 * (lane & 3);
#pragma unroll
            for (int half = 0; half < 2; half++) {
                int gr = r0 + half * 8;
                float v0 = acc[mi][ni][2 * half + 0];
                float v1 = acc[mi][ni][2 * half + 1];
                if (offCbf >= 0) {
                    if (bias) { v0 += bias[c0]; v1 += bias[c0 + 1]; }
                    if (act)  { v0 = fmaxf(v0, 0.f); v1 = fmaxf(v1, 0.f); }
                    __half h0 = __float2half_rn(v0);
                    __half h1 = __float2half_rn(v1);
                    long o = offCbf + (long)gr * cbfStride + c0;
                    uint32_t hp = (uint32_t)__half_as_ushort(h0)
                                | ((uint32_t)__half_as_ushort(h1) << 16);
                    *(uint32_t*)&g_abf[o] = hp;
                } else {
                    if (c0 < N) {
                        float o = v0 + (bias ? bias[c0] : 0.f);
                        if (act) o = fmaxf(o, 0.f);
                        C[(size_t)gr * N + c0] = o;
                    }
                    if (c0 + 1 < N) {
                        float o = v1 + (bias ? bias[c0 + 1] : 0.f);
                        if (act) o = fmaxf(o, 0.f);
                        C[(size_t)gr * N + c0 + 1] = o;
                    }
                }
            }
        }
    }
}

constexpr int SMEM_BIG   = 2 * (64 * 40 + 2 * 128 * 40) * 2;  // 51200 B
constexpr int SMEM_SMALL = 2 * (64 * 40 + 2 * 64 * 40) * 2;   // 30720 B

static inline void tgemm(long aOff, long wOff, const float* bias, long biasOff,
                         float* CExt, long offC, long offCbf, int cbfStride,
                         int M, int N, int Np, int Kp, int act)
{
    if (M >= 4096 || Np >= 2048) {
        dim3 grid(Np / 128, M / 64);
        mma_gemm_kernel<128, 8, 3><<<grid, 128, SMEM_BIG>>>(
            aOff, wOff, bias, biasOff, CExt, offC, offCbf, cbfStride, M, N, Kp, act);
    } else {
        dim3 grid(Np / 64, M / 64);
        mma_gemm_kernel<64, 4, 4><<<grid, 128, SMEM_SMALL>>>(
            aOff, wOff, bias, biasOff, CExt, offC, offCbf, cbfStride, M, N, Kp, act);
    }
}

// ---------------------------------------------------------------------------
// Visual attention (block per (b, src)). float4 logit phase.
// ---------------------------------------------------------------------------
__global__ __launch_bounds__(256) void att6_kernel(
    long offQA, int qStride,
    const float* __restrict__ aoW, const float* __restrict__ aoB,
    const float* __restrict__ imgf,
    long abfOut0, long abfOut1)
{
    int b  = blockIdx.x;
    int which = blockIdx.y;
    int n0 = b * R_;
    const float* V   = g_scratch + (which ? OFF_V2 : OFF_V1) + (long)b * K_ * H_;
    const float* img = which ? (imgf + (long)b * K_ * C_)
                             : (g_scratch + OFF_IMG0 + (long)b * K_ * C_);
    long abfOut = which ? abfOut1 : abfOut0;

    __shared__ __align__(16) float qa[R_][H_];
    __shared__ float attw[R_][K_ + 1];

    int tid = threadIdx.x, wid = tid >> 5, lane = tid & 31;

    for (int idx = tid; idx < R_ * H_; idx += 256) {
        int r = idx / H_, h = idx % H_;
        qa[r][h] = g_scratch[offQA + (long)(n0 + r) * qStride + h] * aoW[h];
    }
    __syncthreads();

    for (int k = wid; k < K_; k += 8) {
        const float4* vk4 = (const float4*)(V + (long)k * H_);
        float s0=0,s1=0,s2=0,s3=0,s4=0,s5=0;
#pragma unroll
        for (int h4 = lane; h4 < H_ / 4; h4 += 32) {
            float4 v = vk4[h4];
            float4 q;
            q = *(const float4*)&qa[0][h4 * 4];
            s0 += v.x*q.x + v.y*q.y + v.z*q.z + v.w*q.w;
            q = *(const float4*)&qa[1][h4 * 4];
            s1 += v.x*q.x + v.y*q.y + v.z*q.z + v.w*q.w;
            q = *(const float4*)&qa[2][h4 * 4];
            s2 += v.x*q.x + v.y*q.y + v.z*q.z + v.w*q.w;
            q = *(const float4*)&qa[3][h4 * 4];
            s3 += v.x*q.x + v.y*q.y + v.z*q.z + v.w*q.w;
            q = *(const float4*)&qa[4][h4 * 4];
            s4 += v.x*q.x + v.y*q.y + v.z*q.z + v.w*q.w;
            q = *(const float4*)&qa[5][h4 * 4];
            s5 += v.x*q.x + v.y*q.y + v.z*q.z + v.w*q.w;
        }
#pragma unroll
        for (int o = 16; o; o >>= 1) {
            s0 += __shfl_xor_sync(0xffffffffu, s0, o);
            s1 += __shfl_xor_sync(0xffffffffu, s1, o);
            s2 += __shfl_xor_sync(0xffffffffu, s2, o);
            s3 += __shfl_xor_sync(0xffffffffu, s3, o);
            s4 += __shfl_xor_sync(0xffffffffu, s4, o);
            s5 += __shfl_xor_sync(0xffffffffu, s5, o);
        }
        if (lane == 0) {
            float ab = aoB[0];
            attw[0][k] = s0 + ab; attw[1][k] = s1 + ab; attw[2][k] = s2 + ab;
            attw[3][k] = s3 + ab; attw[4][k] = s4 + ab; attw[5][k] = s5 + ab;
        }
    }
    __syncthreads();

    if (tid < R_) {
        float mx = -1e30f;
        for (int k = 0; k < K_; k++) mx = fmaxf(mx, attw[tid][k]);
        float sum = 0.f;
        for (int k = 0; k < K_; k++) sum += expf(attw[tid][k] - mx);
        float inv = 1.f / sum;
        for (int k = 0; k < K_; k++) attw[tid][k] = expf(attw[tid][k] - mx) * inv;
    }
    __syncthreads();

    for (int c = tid; c < C_; c += 256) {
        float a0=0,a1=0,a2=0,a3=0,a4=0,a5=0;
#pragma unroll 7
        for (int k = 0; k < K_; k++) {
            float f = img[(long)k * C_ + c];
            a0 = fmaf(attw[0][k], f, a0); a1 = fmaf(attw[1][k], f, a1);
            a2 = fmaf(attw[2][k], f, a2); a3 = fmaf(attw[3][k], f, a3);
            a4 = fmaf(attw[4][k], f, a4); a5 = fmaf(attw[5][k], f, a5);
        }
        long base = abfOut + (long)n0 * C_ + c;
        stA(base,          a0); stA(base + C_,     a1);
        stA(base + 2 * C_, a2); stA(base + 3 * C_, a3);
        stA(base + 4 * C_, a4); stA(base + 5 * C_, a5);
    }
}

// ---------------------------------------------------------------------------
// MFB pool. mode 0: fp32 rows (OUT/OUTV) + fp16 (ABF_OUT).
// mode 1: fuse gated combine -> ABF_OUTF.
// ---------------------------------------------------------------------------
__global__ void mfb_kernel(long offQ, int qStride, int qWrap,
                           long offV, int mode)
{
    int n = blockIdx.x;
    const float* q = g_scratch + offQ + (long)(n % qWrap) * qStride;
    const float* v = g_scratch + offV + (long)n * H_;
    int tid = threadIdx.x;

    float s = 0.f;
    for (int h = tid; h < H_; h += 256) {
        float z = q[h] * v[h];
        s += fabsf(z);
    }
    __shared__ float red[8];
#pragma unroll
    for (int off = 16; off; off >>= 1) s += __shfl_xor_sync(0xffffffffu, s, off);
    if ((tid & 31) == 0) red[tid >> 5] = s;
    __syncthreads();
    float tot = 0.f;
#pragma unroll
    for (int i = 0; i < 8; i++) tot += red[i];
    float inv = 1.f / fmaxf(sqrtf(tot), 1e-12f);

    for (int h = tid; h < H_; h += 256) {
        float z = q[h] * v[h];
        float sg = (z > 0.f) ? sqrtf(z) : -sqrtf(-z);
        float r = sg * inv;
        if (mode == 0) {
            g_scratch[OFF_OUT + (long)n * H_ + h] = r;
            stA(ABF_OUT + (long)n * H_ + h, r);
        } else {
            float ov = g_scratch[OFF_OUT + SZ_H + (long)n * H_ + h];
            float a0 = g_scratch[OFF_OUT + (long)n * H_ + h];
            float g  = 1.f / (1.f + expf(-(r + ov)));
            stA(ABF_OUTF + (long)n * H_ + h, (1.f - g) * ov + g * tanhf(r + a0));
        }
    }
}

// ---------------------------------------------------------------------------
// Masked role attention -> ctx as fp16
// ---------------------------------------------------------------------------
__global__ void role_att_kernel(const int* __restrict__ mask)
{
    int b = blockIdx.x;
    const float* base = g_scratch + OFF_QKV3 + (long)b * R_ * 3072;

    __shared__ float sc[R_][R_];
    __shared__ float attn[R_][R_];
    int tid = threadIdx.x, wid = tid >> 5, lane = tid & 31;

    for (int p = wid; p < R_ * R_; p += 8) {
        int i = p / R_, j = p % R_;
        const float* qh = base + (long)i * 3072;
        const float* kh = base + (long)j * 3072 + 1024;
        float s = 0.f;
        for (int h = lane; h < H_; h += 32)
            s = fmaf(qh[h], kh[h], s);
#pragma unroll
        for (int o = 16; o; o >>= 1) s += __shfl_xor_sync(0xffffffffu, s, o);
        if (lane == 0) {
            bool valid = (i != j) && (mask[((long)b * R_ + i) * R_ + j] > 0);
            sc[i][j] = valid ? s * (1.f / 32.f) : -1e9f;
        }
    }
    __syncthreads();

    if (tid < R_ * R_) {
        int i = tid / R_, j = tid % R_;
        float mx = -1e30f;
        for (int jj = 0; jj < R_; jj++) mx = fmaxf(mx, sc[i][jj]);
        float sum = 0.f;
        for (int jj = 0; jj < R_; jj++) sum += expf(sc[i][jj] - mx);
        attn[i][j] = expf(sc[i][j] - mx) / sum;
    }
    __syncthreads();

    for (int idx = tid; idx < R_ * H_; idx += 256) {
        int i = idx / H_, h = idx % H_;
        float acc = 0.f;
#pragma unroll
        for (int j = 0; j < R_; j++)
            acc = fmaf(attn[i][j], base[(long)j * 3072 + 2048 + h], acc);
        stA(ABF_CTX + (long)(b * R_ + i) * H_ + h, acc);
    }
}

// ---------------------------------------------------------------------------
// Launch sequence
// ---------------------------------------------------------------------------
extern "C" void kernel_launch(void* const* d_in, const int* in_sizes, int n_in,
                              void* d_out, int out_size)
{
    const float* v_org    = (const float*)d_in[0];
    const float* img_feat = (const float*)d_in[1];
    const int*   gt_verb  = (const int*)d_in[2];
    const int*   role_idx = (const int*)d_in[3];
    const int*   mask     = (const int*)d_in[4];
    const float* verb_t   = (const float*)d_in[5];
    const float* role_t   = (const float*)d_in[6];
    const float* qc_W = (const float*)d_in[7];   const float* qc_b = (const float*)d_in[8];
    const float* av_W = (const float*)d_in[9];   const float* av_b = (const float*)d_in[10];
    const float* aq_W = (const float*)d_in[11];  const float* aq_b = (const float*)d_in[12];
    const float* ao_W = (const float*)d_in[13];  const float* ao_b = (const float*)d_in[14];
    const float* vn_W = (const float*)d_in[15];  const float* vn_b = (const float*)d_in[16];
    const float* qn_W = (const float*)d_in[17];  const float* qn_b = (const float*)d_in[18];
    const float* Wq   = (const float*)d_in[19];
    const float* Wk   = (const float*)d_in[20];
    const float* Wv   = (const float*)d_in[21];
    const float* Wo   = (const float*)d_in[22];
    const float* uqc_W = (const float*)d_in[23]; const float* uqc_b = (const float*)d_in[24];
    const float* cls_W = (const float*)d_in[25]; const float* cls_b = (const float*)d_in[26];

    cudaFuncSetAttribute((const void*)mma_gemm_kernel<128, 8, 3>,
                         cudaFuncAttributeMaxDynamicSharedMemorySize, SMEM_BIG);
    cudaFuncSetAttribute((const void*)mma_gemm_kernel<64, 4, 4>,
                         cudaFuncAttributeMaxDynamicSharedMemorySize, SMEM_SMALL);

    // megaconv descriptor table
    WAll P;
    const float* Ws[11] = {qc_W, av_W, aq_W, qn_W, vn_W, Wq, Wk, Wv, Wo, uqc_W, cls_W};
    int  Ks[11]  = {600, 512, 1024, 1024, 512, 1024, 1024, 1024, 1024, CATW, 1024};
    int  Ns[11]  = {1024,1024,1024, 1024, 1024,1024, 1024, 1024, 1024, 1024, NL_};
    int  tK[11]  = {20,  16,  32,   32,   16,  32,   32,   32,   32,   52,   32};
    int  Nps[11] = {1024,1024,1024, 1024, 1024,1024, 1024, 1024, 1024, 1024, 2048};
    long offs[11]= {WOFF_QC, WOFF_AV, WOFF_AQN, WOFF_AQN + 1024L * 1024, WOFF_VN,
                    WOFF_QKV, WOFF_QKV + 1024L * 1024, WOFF_QKV + 2048L * 1024,
                    WOFF_WO, WOFF_UQC, WOFF_CLS};
    int pre = 0;
    for (int i = 0; i < 11; i++) {
        P.W[i] = Ws[i]; P.K[i] = Ks[i]; P.N[i] = Ns[i];
        P.tilesK[i] = tK[i]; P.off[i] = offs[i];
        P.pre[i] = pre;
        pre += tK[i] * (Nps[i] / 32);
    }
    P.pre[11] = pre;

    // 0: prep, 1: megaconv, 2: gather, 3: QEMB
    prep_kernel<<<TRB + IFB + 1, dim3(32, 8)>>>(v_org, img_feat, aq_b, qn_b);
    megaconv_kernel<<<pre, dim3(32, 8)>>>(P);
    gather_rv_kernel<<<(int)(((long)BR_ * TWO_E + 255) / 256), 256>>>(gt_verb, role_idx,
                                                                      verb_t, role_t);
    // query chain
    tgemm(ABF_RV, WOFF_QC, qc_b, -1, nullptr, 0, ABF_QEMB, 1024,
          BR_, 1024, 1024, 640, 1);

    // FUSED V1+V2 GEMM
    tgemm(ABF_IMG0, WOFF_AV, av_b, -1, nullptr, OFF_V1, -1, 0,
          2 * B_ * K_, 1024, 1024, 512, 1);

    tgemm(ABF_QEMB, WOFF_AQN, nullptr, OFF_BIASAQN, nullptr, OFF_QAQR, -1, 0,
          BR_, 2048, 2048, 1024, 1);

    // attention 1 + attention-verb in ONE launch (grid B x 2)
    att6_kernel<<<dim3(B_, 2), 256>>>(OFF_QAQR, 2048, ao_W, ao_b, img_feat,
                                      ABF_VEMB12, ABF_VEMB12 + (long)BR_ * 512);

    // fused VN over [VEMB1;VEMB2]
    tgemm(ABF_VEMB12, WOFF_VN, vn_b, -1, nullptr, OFF_VREPR1, -1, 0,
          2 * BR_, 1024, 1024, 512, 1);

    // fused MFB for OUT & OUTV (mode 0)
    mfb_kernel<<<2 * BR_, 256>>>(OFF_QAQR + 1024, 2048, BR_, OFF_VREPR1, 0);

    // role-node neighbour attention
    tgemm(ABF_OUT, WOFF_QKV, nullptr, -1, nullptr, OFF_QKV3, -1, 0,
          BR_, 3072, 3072, 1024, 0);
    role_att_kernel<<<B_, 256>>>(mask);
    // WO writes fp16 DIRECTLY into CAT rows (stride 1664)
    tgemm(ABF_CTX, WOFF_WO, nullptr, -1, nullptr, 0, ABF_CAT, 1664,
          BR_, 1024, 1024, 1024, 0);

    // updated query
    tgemm(ABF_CAT, WOFF_UQC, uqc_b, -1, nullptr, 0, ABF_UQ, 1024,
          BR_, 1024, 1024, 1664, 1);
    tgemm(ABF_UQ, WOFF_AQN, nullptr, OFF_BIASAQN, nullptr, OFF_QAQR2, -1, 0,
          BR_, 2048, 2048, 1024, 1);

    // attention 2 (single source)
    att6_kernel<<<dim3(B_, 1), 256>>>(OFF_QAQR2, 2048, ao_W, ao_b, img_feat,
                                      ABF_VEMB3, ABF_VEMB3);
    tgemm(ABF_VEMB3, WOFF_VN, vn_b, -1, nullptr, OFF_VREPR2, -1, 0,
          BR_, 1024, 1024, 512, 1);

    // MFB(out2) fused with gated combine (mode 1) -> ABF_OUTF
    mfb_kernel<<<BR_, 256>>>(OFF_QAQR2 + 1024, 2048, BR_, OFF_VREPR2, 1);

    // classifier -> d_out
    tgemm(ABF_OUTF, WOFF_CLS, cls_b, -1, (float*)d_out, 0, -1, 0,
          BR_, NL_, 2048, 1024, 0);
}

// round 15
// speedup vs baseline: 1.3475x; 1.0451x over previous
#include <cuda_runtime.h>
#include <cuda_fp16.h>
#include <cstdint>
#include <math.h>

// ---------------------------------------------------------------------------
// Problem dims
// ---------------------------------------------------------------------------
constexpr int B_   = 256;
constexpr int R_   = 6;
constexpr int K_   = 49;
constexpr int C_   = 512;
constexpr int H_   = 1024;
constexpr int E_   = 300;
constexpr int BR_  = B_ * R_;          // 1536
constexpr int NL_  = 2001;
constexpr int TWO_E = 2 * E_;          // 600
constexpr int CATW  = H_ + TWO_E;      // 1624

// ---------------------------------------------------------------------------
// fp32 scratch
// ---------------------------------------------------------------------------
constexpr long SZ_IMG0 = (long)B_ * K_ * C_;   // 6422528
constexpr long SZ_H    = (long)BR_ * H_;
constexpr long SZ_2H   = (long)BR_ * 2048;
constexpr long SZ_3H   = (long)BR_ * 3072;

constexpr long OFF_QAQR  = 0;                     // [BR,2048] = [qa|qrepr]
constexpr long OFF_VREPR1= OFF_QAQR  + SZ_2H;     // [2BR,1024] (VREPR1;VREPRV)
constexpr long OFF_OUT   = OFF_VREPR1+ 2*SZ_H;    // [2BR,1024] (OUT;OUTV)
constexpr long OFF_QKV3  = OFF_OUT   + 2*SZ_H;    // [BR,3072]
constexpr long OFF_QAQR2 = OFF_QKV3  + SZ_3H;     // [BR,2048]
constexpr long OFF_VREPR2= OFF_QAQR2 + SZ_2H;
constexpr long OFF_BIASAQN = OFF_VREPR2 + SZ_H;   // 2048 floats
constexpr long SCRATCH_TOTAL = OFF_BIASAQN + 2048;

__device__ float g_scratch[SCRATCH_TOTAL];

// ---------------------------------------------------------------------------
// fp16 ACTIVATION plane (single plane). Zero-initialized.
// ---------------------------------------------------------------------------
constexpr long ABF_IMG0  = 0;                          // [12544][512]
constexpr long ABF_IMGF  = ABF_IMG0  + 12544L * 512;   // [12544][512]
constexpr long ABF_RV    = ABF_IMGF  + 12544L * 512;   // [1536][640]
constexpr long ABF_QEMB  = ABF_RV    + 1536L * 640;    // [1536][1024]
constexpr long ABF_VEMB12= ABF_QEMB  + 1536L * 1024;   // [3072][512]
constexpr long ABF_VEMB3 = ABF_VEMB12+ 3072L * 512;    // [1536][512]
constexpr long ABF_OUT   = ABF_VEMB3 + 1536L * 512;    // [3072][1024]
constexpr long ABF_CTX   = ABF_OUT   + 3072L * 1024;   // [1536][1024]
constexpr long ABF_CAT   = ABF_CTX   + 1536L * 1024;   // [1536][1664]
constexpr long ABF_UQ    = ABF_CAT   + 1536L * 1664;   // [1536][1024]
constexpr long ABF_OUTF  = ABF_UQ    + 1536L * 1024;   // [1536][1024]
constexpr long ABF_V12   = ABF_OUTF  + 1536L * 1024;   // [2*12544][1024] V1;V2 fp16
constexpr long ATOTAL    = ABF_V12   + 2L * 12544 * 1024;

__device__ __align__(256) __half g_abf[ATOTAL];

// ---------------------------------------------------------------------------
// fp16 WEIGHT planes (transposed [Npad][Kpad], hi at off, lo at off+WTOTAL)
// ---------------------------------------------------------------------------
constexpr long WOFF_QC  = 0;                           // [1024][640]
constexpr long WOFF_AV  = WOFF_QC  + 1024L * 640;      // [1024][512]
constexpr long WOFF_AQN = WOFF_AV  + 1024L * 512;      // [2048][1024]
constexpr long WOFF_VN  = WOFF_AQN + 2048L * 1024;     // [1024][512]
constexpr long WOFF_QKV = WOFF_VN  + 1024L * 512;      // [3072][1024]
constexpr long WOFF_WO  = WOFF_QKV + 3072L * 1024;     // [1024][1024]
constexpr long WOFF_UQC = WOFF_WO  + 1024L * 1024;     // [1024][1664]
constexpr long WOFF_CLS = WOFF_UQC + 1024L * 1664;     // [2048][1024]
constexpr long WTOTAL   = WOFF_CLS + 2048L * 1024;

__device__ __align__(256) __half g_wbf[2 * WTOTAL];

// ---------------------------------------------------------------------------
// helpers
// ---------------------------------------------------------------------------
__device__ __forceinline__ uint32_t smem_u32(const void* p) {
    uint32_t a;
    asm("{ .reg .u64 t; cvta.to.shared.u64 t, %1; cvt.u32.u64 %0, t; }" : "=r"(a) : "l"(p));
    return a;
}
__device__ __forceinline__ void stA(long base, float v) {
    g_abf[base] = __float2half_rn(v);
}
__device__ __forceinline__ void ldm_x4(uint32_t* r, uint32_t addr) {
    asm volatile("ldmatrix.sync.aligned.m8n8.x4.shared.b16 {%0,%1,%2,%3}, [%4];"
                 : "=r"(r[0]), "=r"(r[1]), "=r"(r[2]), "=r"(r[3]) : "r"(addr));
}
__device__ __forceinline__ void mma16816(float* c, const uint32_t* a, const uint32_t* b) {
    asm volatile(
        "mma.sync.aligned.m16n8k16.row.col.f32.f16.f16.f32 "
        "{%0,%1,%2,%3}, {%4,%5,%6,%7}, {%8,%9}, {%0,%1,%2,%3};"
        : "+f"(c[0]), "+f"(c[1]), "+f"(c[2]), "+f"(c[3])
        : "r"(a[0]), "r"(a[1]), "r"(a[2]), "r"(a[3]), "r"(b[0]), "r"(b[1]));
}
__device__ __forceinline__ void cpa16(uint32_t s, const void* g) {
    asm volatile("cp.async.cg.shared.global [%0], [%1], 16;" :: "r"(s), "l"(g));
}
#define CP_COMMIT() asm volatile("cp.async.commit_group;" ::: "memory")
#define CP_WAIT0()  asm volatile("cp.async.wait_group 0;" ::: "memory")

// ---------------------------------------------------------------------------
// megaconv: ALL weight transposes + fp16 hi/lo splits in ONE launch
// ---------------------------------------------------------------------------
struct WAll {
    const float* W[11];
    int K[11], N[11], tilesK[11];
    int pre[12];
    long off[11];
};

__global__ void megaconv_kernel(WAll P)
{
    __shared__ float tile[32][33];
    int bx = blockIdx.x;
    int w = 0;
    while (bx >= P.pre[w + 1]) w++;
    int tix = bx - P.pre[w];
    int tK  = P.tilesK[w];
    int k0  = (tix % tK) * 32;
    int n0  = (tix / tK) * 32;
    int K = P.K[w], N = P.N[w], Kp = tK * 32;
    const float* W = P.W[w];
    long off = P.off[w];

    int tx = threadIdx.x, ty = threadIdx.y;
#pragma unroll
    for (int i = 0; i < 32; i += 8) {
        int k = k0 + ty + i, n = n0 + tx;
        tile[ty + i][tx] = (k < K && n < N) ? W[(size_t)k * N + n] : 0.f;
    }
    __syncthreads();
#pragma unroll
    for (int i = 0; i < 32; i += 8) {
        int n = n0 + ty + i, k = k0 + tx;
        float v = tile[tx][ty + i];
        __half h = __float2half_rn(v);
        __half l = __float2half_rn(v - __half2float(h));
        long o = off + (long)n * Kp + k;
        g_wbf[o] = h;
        g_wbf[o + WTOTAL] = l;
    }
}

// ---------------------------------------------------------------------------
// prep: coalesced tiled v_org transpose (fp16 only) + img_feat + bias pack.
// ---------------------------------------------------------------------------
constexpr int TR_TILES_B = 2 * (C_ / 32);
constexpr int TRB = B_ * TR_TILES_B;                   // 8192
constexpr int IFB = (int)(SZ_IMG0 / 2048);             // 3136

__global__ void prep_kernel(const float* __restrict__ v_org,
                            const float* __restrict__ imgf,
                            const float* __restrict__ b0,
                            const float* __restrict__ b1)
{
    int bx = blockIdx.x;
    int tx = threadIdx.x, ty = threadIdx.y;
    int tid = ty * 32 + tx;

    if (bx < TRB) {
        __shared__ float tile[32][33];
        int b   = bx / TR_TILES_B;
        int t   = bx % TR_TILES_B;
        int k0  = (t & 1) * 32;
        int c0  = (t >> 1) * 32;
        const float* src = v_org + (long)b * C_ * K_;
#pragma unroll
        for (int i = 0; i < 32; i += 8) {
            int c = c0 + ty + i, k = k0 + tx;
            tile[ty + i][tx] = (k < K_) ? src[(long)c * K_ + k] : 0.f;
        }
        __syncthreads();
#pragma unroll
        for (int i = 0; i < 32; i += 8) {
            int k = k0 + ty + i, c = c0 + tx;
            if (k < K_) {
                long idx = ((long)b * K_ + k) * C_ + c;
                stA(ABF_IMG0 + idx, tile[tx][ty + i]);
            }
        }
    } else if (bx < TRB + IFB) {
        long base = (long)(bx - TRB) * 2048;
#pragma unroll
        for (int j = 0; j < 8; j++) {
            long i = base + tid + j * 256;
            stA(ABF_IMGF + i, imgf[i]);
        }
    } else {
#pragma unroll
        for (int j = 0; j < 8; j++) {
            int i = tid + j * 256;
            if (i < 1024)      g_scratch[OFF_BIASAQN + i] = b0[i];
            else if (i < 2048) g_scratch[OFF_BIASAQN + i] = b1[i - 1024];
        }
    }
}

// ---------------------------------------------------------------------------
// rv gather: fp16 into ABF_RV (stride 640) AND ABF_CAT cols 1024..
// ---------------------------------------------------------------------------
__global__ void gather_rv_kernel(const int* __restrict__ gt_verb,
                                 const int* __restrict__ role_idx,
                                 const float* __restrict__ vt,
                                 const float* __restrict__ rt)
{
    long idx = (long)blockIdx.x * 256 + threadIdx.x;
    if (idx >= (long)BR_ * TWO_E) return;
    int e = (int)(idx % TWO_E);
    int n = (int)(idx / TWO_E);
    int b = n / R_;
    float val = (e < E_) ? vt[(long)gt_verb[b] * E_ + e]
                         : rt[(long)role_idx[n] * E_ + (e - E_)];
    stA(ABF_RV  + (long)n * 640  + e, val);
    stA(ABF_CAT + (long)n * 1664 + 1024 + e, val);
}

// ---------------------------------------------------------------------------
// HMMA fp16 2-term GEMM: D = Ah@(Bh+Bl). BM=64, 4 warps (2x2),
// warp tile 32 x (BN/2). 2-stage cp.async pipeline, padded smem.
// ---------------------------------------------------------------------------
template<int BN, int NT, int MAXCTA>
__global__ __launch_bounds__(128, MAXCTA)
void mma_gemm_kernel(long aOff, long wOff,
                     const float* __restrict__ biasPtr, long biasOff,
                     float* CExt, long offC, long offCbf, int cbfStride,
                     int M, int N, int Kp, int act)
{
    constexpr int BM = 64, BKP = 40;
    constexpr int MI  = 2;
    constexpr int ASZ = BM * BKP;
    constexpr int BSZ = BN * BKP;
    constexpr int STG = ASZ + 2 * BSZ;
    constexpr uint32_t ASZ2 = ASZ * 2, BSZ2 = BSZ * 2;

    extern __shared__ __align__(16) __half sm[];
    const __half* Ahp = g_abf + aOff;
    const __half* Bwh = g_wbf + wOff;
    const __half* Bwl = g_wbf + wOff + WTOTAL;
    const float* bias = biasPtr ? biasPtr
                      : (biasOff >= 0 ? (const float*)(g_scratch + biasOff) : nullptr);

    const int tid  = threadIdx.x;
    const int wid  = tid >> 5, lane = tid & 31;
    const int brow = blockIdx.y * BM, bcol = blockIdx.x * BN;
    const int wm   = (wid >> 1) * 32;
    const int wn   = (wid & 1) * (BN / 2);
    const uint32_t sb = smem_u32(sm);

    auto cpAll = [&](int t, int s) {
        const uint32_t st = sb + (uint32_t)(s * STG) * 2;
#pragma unroll
        for (int l = 0; l < 2; l++) {
            int idx = tid + l * 128;
            int row = idx >> 2, seg = idx & 3;
            size_t go = (size_t)(brow + row) * Kp + t * 32 + seg * 8;
            uint32_t so = (uint32_t)(row * BKP + seg * 8) * 2;
            cpa16(st + so, Ahp + go);
        }
#pragma unroll
        for (int l = 0; l < BN / 32; l++) {
            int idx = tid + l * 128;
            int row = idx >> 2, seg = idx & 3;
            size_t go = (size_t)(bcol + row) * Kp + t * 32 + seg * 8;
            uint32_t so = (uint32_t)(row * BKP + seg * 8) * 2;
            cpa16(st + ASZ2 + so,        Bwh + go);
            cpa16(st + ASZ2 + BSZ2 + so, Bwl + go);
        }
    };

    float acc[MI][NT][4];
#pragma unroll
    for (int i = 0; i < MI; i++)
#pragma unroll
        for (int j = 0; j < NT; j++)
#pragma unroll
            for (int q = 0; q < 4; q++) acc[i][j][q] = 0.f;

    const int nCh = Kp / 32;

    cpAll(0, 0); CP_COMMIT();
    CP_WAIT0();
    __syncthreads();

    const int aRow = (lane & 7) + ((lane >> 3) & 1) * 8;
    const int aCol = (lane >> 4) * 8;
    const int bRow = (lane & 7) + ((lane >> 4) & 1) * 8;
    const int bCol = ((lane >> 3) & 1) * 8;

    for (int t = 0; t < nCh; t++) {
        const int s = t & 1;
        if (t + 1 < nCh) { cpAll(t + 1, s ^ 1); CP_COMMIT(); }

        const uint32_t ahB = sb + (uint32_t)(s * STG) * 2;
        const uint32_t bhB = ahB + ASZ2;
        const uint32_t blB = bhB + BSZ2;

#pragma unroll
        for (int ks = 0; ks < 2; ks++) {
            uint32_t ah[MI][4];
#pragma unroll
            for (int mi = 0; mi < MI; mi++) {
                uint32_t off = (uint32_t)((wm + mi * 16 + aRow) * BKP + ks * 16 + aCol) * 2;
                ldm_x4(ah[mi], ahB + off);
            }
            uint32_t bh[NT][2], bl[NT][2];
#pragma unroll
            for (int bt = 0; bt < NT / 2; bt++) {
                uint32_t off = (uint32_t)((wn + bt * 16 + bRow) * BKP + ks * 16 + bCol) * 2;
                uint32_t r[4];
                ldm_x4(r, bhB + off);
                bh[2 * bt][0] = r[0]; bh[2 * bt][1] = r[1];
                bh[2 * bt + 1][0] = r[2]; bh[2 * bt + 1][1] = r[3];
                ldm_x4(r, blB + off);
                bl[2 * bt][0] = r[0]; bl[2 * bt][1] = r[1];
                bl[2 * bt + 1][0] = r[2]; bl[2 * bt + 1][1] = r[3];
            }
#pragma unroll
            for (int mi = 0; mi < MI; mi++)
#pragma unroll
                for (int ni = 0; ni < NT; ni++) {
                    mma16816(acc[mi][ni], ah[mi], bh[ni]);
                    mma16816(acc[mi][ni], ah[mi], bl[ni]);
                }
        }

        if (t + 1 < nCh) {
            CP_WAIT0();
            __syncthreads();
        }
    }

    // epilogue
    float* C = CExt ? CExt : (g_scratch + offC);
#pragma unroll
    for (int mi = 0; mi < MI; mi++) {
#pragma unroll
        for (int ni = 0; ni < NT; ni++) {
            int r0 = brow + wm + mi * 16 + (lane >> 2);
            int c0 = bcol + wn + ni * 8 + 2 * (lane & 3);
#pragma unroll
            for (int half = 0; half < 2; half++) {
                int gr = r0 + half * 8;
                float v0 = acc[mi][ni][2 * half + 0];
                float v1 = acc[mi][ni][2 * half + 1];
                if (offCbf >= 0) {
                    if (bias) { v0 += bias[c0]; v1 += bias[c0 + 1]; }
                    if (act)  { v0 = fmaxf(v0, 0.f); v1 = fmaxf(v1, 0.f); }
                    __half h0 = __float2half_rn(v0);
                    __half h1 = __float2half_rn(v1);
                    long o = offCbf + (long)gr * cbfStride + c0;
                    uint32_t hp = (uint32_t)__half_as_ushort(h0)
                                | ((uint32_t)__half_as_ushort(h1) << 16);
                    *(uint32_t*)&g_abf[o] = hp;
                } else {
                    if (c0 < N) {
                        float o = v0 + (bias ? bias[c0] : 0.f);
                        if (act) o = fmaxf(o, 0.f);
                        C[(size_t)gr * N + c0] = o;
                    }
                    if (c0 + 1 < N) {
                        float o = v1 + (bias ? bias[c0 + 1] : 0.f);
                        if (act) o = fmaxf(o, 0.f);
                        C[(size_t)gr * N + c0 + 1] = o;
                    }
                }
            }
        }
    }
}

constexpr int SMEM_BIG   = 2 * (64 * 40 + 2 * 128 * 40) * 2;  // 51200 B
constexpr int SMEM_SMALL = 2 * (64 * 40 + 2 * 64 * 40) * 2;   // 30720 B

static inline void tgemm(long aOff, long wOff, const float* bias, long biasOff,
                         float* CExt, long offC, long offCbf, int cbfStride,
                         int M, int N, int Np, int Kp, int act)
{
    if (M >= 4096 || Np >= 2048) {
        dim3 grid(Np / 128, M / 64);
        mma_gemm_kernel<128, 8, 3><<<grid, 128, SMEM_BIG>>>(
            aOff, wOff, bias, biasOff, CExt, offC, offCbf, cbfStride, M, N, Kp, act);
    } else {
        dim3 grid(Np / 64, M / 64);
        mma_gemm_kernel<64, 4, 4><<<grid, 128, SMEM_SMALL>>>(
            aOff, wOff, bias, biasOff, CExt, offC, offCbf, cbfStride, M, N, Kp, act);
    }
}

// ---------------------------------------------------------------------------
// Visual attention (block per (b, src)); V and img read as fp16.
// src=blockIdx.y: 0 -> (V1, img0), 1 -> (V2, img_feat).
// ---------------------------------------------------------------------------
__global__ __launch_bounds__(256) void att6_kernel(
    long offQA, int qStride,
    const float* __restrict__ aoW, const float* __restrict__ aoB,
    long abfOut0, long abfOut1)
{
    int b  = blockIdx.x;
    int which = blockIdx.y;
    int n0 = b * R_;
    const __half* V   = g_abf + ABF_V12 + ((long)which * B_ * K_ + (long)b * K_) * H_;
    const __half* img = g_abf + (which ? ABF_IMGF : ABF_IMG0) + (long)b * K_ * C_;
    long abfOut = which ? abfOut1 : abfOut0;

    __shared__ __align__(16) float qa[R_][H_];
    __shared__ float attw[R_][K_ + 1];

    int tid = threadIdx.x, wid = tid >> 5, lane = tid & 31;

    for (int idx = tid; idx < R_ * H_; idx += 256) {
        int r = idx / H_, h = idx % H_;
        qa[r][h] = g_scratch[offQA + (long)(n0 + r) * qStride + h] * aoW[h];
    }
    __syncthreads();

    for (int k = wid; k < K_; k += 8) {
        const uint4* vk = (const uint4*)(V + (long)k * H_);
        float s0=0,s1=0,s2=0,s3=0,s4=0,s5=0;
#pragma unroll
        for (int h8 = lane; h8 < H_ / 8; h8 += 32) {
            uint4 pv = vk[h8];
            const __half2* ph = (const __half2*)&pv;
            float2 f0 = __half22float2(ph[0]);
            float2 f1 = __half22float2(ph[1]);
            float2 f2 = __half22float2(ph[2]);
            float2 f3 = __half22float2(ph[3]);
            float vv[8] = {f0.x, f0.y, f1.x, f1.y, f2.x, f2.y, f3.x, f3.y};
            int hb = h8 * 8;
#pragma unroll
            for (int r = 0; r < R_; r++) {
                const float* qr = &qa[r][hb];
                float acc = vv[0]*qr[0] + vv[1]*qr[1] + vv[2]*qr[2] + vv[3]*qr[3]
                          + vv[4]*qr[4] + vv[5]*qr[5] + vv[6]*qr[6] + vv[7]*qr[7];
                if (r == 0) s0 += acc; else if (r == 1) s1 += acc;
                else if (r == 2) s2 += acc; else if (r == 3) s3 += acc;
                else if (r == 4) s4 += acc; else s5 += acc;
            }
        }
#pragma unroll
        for (int o = 16; o; o >>= 1) {
            s0 += __shfl_xor_sync(0xffffffffu, s0, o);
            s1 += __shfl_xor_sync(0xffffffffu, s1, o);
            s2 += __shfl_xor_sync(0xffffffffu, s2, o);
            s3 += __shfl_xor_sync(0xffffffffu, s3, o);
            s4 += __shfl_xor_sync(0xffffffffu, s4, o);
            s5 += __shfl_xor_sync(0xffffffffu, s5, o);
        }
        if (lane == 0) {
            float ab = aoB[0];
            attw[0][k] = s0 + ab; attw[1][k] = s1 + ab; attw[2][k] = s2 + ab;
            attw[3][k] = s3 + ab; attw[4][k] = s4 + ab; attw[5][k] = s5 + ab;
        }
    }
    __syncthreads();

    if (tid < R_) {
        float mx = -1e30f;
        for (int k = 0; k < K_; k++) mx = fmaxf(mx, attw[tid][k]);
        float sum = 0.f;
        for (int k = 0; k < K_; k++) sum += expf(attw[tid][k] - mx);
        float inv = 1.f / sum;
        for (int k = 0; k < K_; k++) attw[tid][k] = expf(attw[tid][k] - mx) * inv;
    }
    __syncthreads();

    for (int c = tid; c < C_; c += 256) {
        float a0=0,a1=0,a2=0,a3=0,a4=0,a5=0;
#pragma unroll 7
        for (int k = 0; k < K_; k++) {
            float f = __half2float(img[(long)k * C_ + c]);
            a0 = fmaf(attw[0][k], f, a0); a1 = fmaf(attw[1][k], f, a1);
            a2 = fmaf(attw[2][k], f, a2); a3 = fmaf(attw[3][k], f, a3);
            a4 = fmaf(attw[4][k], f, a4); a5 = fmaf(attw[5][k], f, a5);
        }
        long base = abfOut + (long)n0 * C_ + c;
        stA(base,          a0); stA(base + C_,     a1);
        stA(base + 2 * C_, a2); stA(base + 3 * C_, a3);
        stA(base + 4 * C_, a4); stA(base + 5 * C_, a5);
    }
}

// ---------------------------------------------------------------------------
// MFB pool. mode 0: fp32 rows (OUT/OUTV) + fp16 (ABF_OUT).
// mode 1: fuse gated combine -> ABF_OUTF.
// ---------------------------------------------------------------------------
__global__ void mfb_kernel(long offQ, int qStride, int qWrap,
                           long offV, int mode)
{
    int n = blockIdx.x;
    const float* q = g_scratch + offQ + (long)(n % qWrap) * qStride;
    const float* v = g_scratch + offV + (long)n * H_;
    int tid = threadIdx.x;

    float s = 0.f;
    for (int h = tid; h < H_; h += 256) {
        float z = q[h] * v[h];
        s += fabsf(z);
    }
    __shared__ float red[8];
#pragma unroll
    for (int off = 16; off; off >>= 1) s += __shfl_xor_sync(0xffffffffu, s, off);
    if ((tid & 31) == 0) red[tid >> 5] = s;
    __syncthreads();
    float tot = 0.f;
#pragma unroll
    for (int i = 0; i < 8; i++) tot += red[i];
    float inv = 1.f / fmaxf(sqrtf(tot), 1e-12f);

    for (int h = tid; h < H_; h += 256) {
        float z = q[h] * v[h];
        float sg = (z > 0.f) ? sqrtf(z) : -sqrtf(-z);
        float r = sg * inv;
        if (mode == 0) {
            g_scratch[OFF_OUT + (long)n * H_ + h] = r;
            stA(ABF_OUT + (long)n * H_ + h, r);
        } else {
            float ov = g_scratch[OFF_OUT + SZ_H + (long)n * H_ + h];
            float a0 = g_scratch[OFF_OUT + (long)n * H_ + h];
            float g  = 1.f / (1.f + expf(-(r + ov)));
            stA(ABF_OUTF + (long)n * H_ + h, (1.f - g) * ov + g * tanhf(r + a0));
        }
    }
}

// ---------------------------------------------------------------------------
// Masked role attention with q/k/v cached in smem -> ctx as fp16.
// Dynamic smem: 18 * 1024 floats (q rows 0-5, k rows 6-11, v rows 12-17).
// ---------------------------------------------------------------------------
__global__ __launch_bounds__(256, 1) void role_att_kernel(const int* __restrict__ mask)
{
    extern __shared__ float rs[];
    float* qs = rs;
    float* ks = rs + 6 * 1024;
    float* vs = rs + 12 * 1024;

    int b = blockIdx.x;
    const float* base = g_scratch + OFF_QKV3 + (long)b * R_ * 3072;

    __shared__ float sc[R_][R_];
    __shared__ float attn[R_][R_];
    int tid = threadIdx.x, wid = tid >> 5, lane = tid & 31;

    for (int idx = tid; idx < 18 * 1024; idx += 256) {
        int row = idx >> 10, h = idx & 1023;
        int part = row / 6, role = row % 6;
        rs[idx] = base[(long)role * 3072 + part * 1024 + h];
    }
    __syncthreads();

    for (int p = wid; p < R_ * R_; p += 8) {
        int i = p / R_, j = p % R_;
        const float* qh = qs + i * 1024;
        const float* kh = ks + j * 1024;
        float s = 0.f;
        for (int h = lane; h < H_; h += 32)
            s = fmaf(qh[h], kh[h], s);
#pragma unroll
        for (int o = 16; o; o >>= 1) s += __shfl_xor_sync(0xffffffffu, s, o);
        if (lane == 0) {
            bool valid = (i != j) && (mask[((long)b * R_ + i) * R_ + j] > 0);
            sc[i][j] = valid ? s * (1.f / 32.f) : -1e9f;
        }
    }
    __syncthreads();

    if (tid < R_ * R_) {
        int i = tid / R_, j = tid % R_;
        float mx = -1e30f;
        for (int jj = 0; jj < R_; jj++) mx = fmaxf(mx, sc[i][jj]);
        float sum = 0.f;
        for (int jj = 0; jj < R_; jj++) sum += expf(sc[i][jj] - mx);
        attn[i][j] = expf(sc[i][j] - mx) / sum;
    }
    __syncthreads();

    for (int idx = tid; idx < R_ * H_; idx += 256) {
        int i = idx / H_, h = idx % H_;
        float acc = 0.f;
#pragma unroll
        for (int j = 0; j < R_; j++)
            acc = fmaf(attn[i][j], vs[j * 1024 + h], acc);
        stA(ABF_CTX + (long)(b * R_ + i) * H_ + h, acc);
    }
}

constexpr int SMEM_ROLE = 18 * 1024 * 4;   // 73728 B

// ---------------------------------------------------------------------------
// Launch sequence
// ---------------------------------------------------------------------------
extern "C" void kernel_launch(void* const* d_in, const int* in_sizes, int n_in,
                              void* d_out, int out_size)
{
    const float* v_org    = (const float*)d_in[0];
    const float* img_feat = (const float*)d_in[1];
    const int*   gt_verb  = (const int*)d_in[2];
    const int*   role_idx = (const int*)d_in[3];
    const int*   mask     = (const int*)d_in[4];
    const float* verb_t   = (const float*)d_in[5];
    const float* role_t   = (const float*)d_in[6];
    const float* qc_W = (const float*)d_in[7];   const float* qc_b = (const float*)d_in[8];
    const float* av_W = (const float*)d_in[9];   const float* av_b = (const float*)d_in[10];
    const float* aq_W = (const float*)d_in[11];  const float* aq_b = (const float*)d_in[12];
    const float* ao_W = (const float*)d_in[13];  const float* ao_b = (const float*)d_in[14];
    const float* vn_W = (const float*)d_in[15];  const float* vn_b = (const float*)d_in[16];
    const float* qn_W = (const float*)d_in[17];  const float* qn_b = (const float*)d_in[18];
    const float* Wq   = (const float*)d_in[19];
    const float* Wk   = (const float*)d_in[20];
    const float* Wv   = (const float*)d_in[21];
    const float* Wo   = (const float*)d_in[22];
    const float* uqc_W = (const float*)d_in[23]; const float* uqc_b = (const float*)d_in[24];
    const float* cls_W = (const float*)d_in[25]; const float* cls_b = (const float*)d_in[26];

    cudaFuncSetAttribute((const void*)mma_gemm_kernel<128, 8, 3>,
                         cudaFuncAttributeMaxDynamicSharedMemorySize, SMEM_BIG);
    cudaFuncSetAttribute((const void*)mma_gemm_kernel<64, 4, 4>,
                         cudaFuncAttributeMaxDynamicSharedMemorySize, SMEM_SMALL);
    cudaFuncSetAttribute((const void*)role_att_kernel,
                         cudaFuncAttributeMaxDynamicSharedMemorySize, SMEM_ROLE);

    // megaconv descriptor table
    WAll P;
    const float* Ws[11] = {qc_W, av_W, aq_W, qn_W, vn_W, Wq, Wk, Wv, Wo, uqc_W, cls_W};
    int  Ks[11]  = {600, 512, 1024, 1024, 512, 1024, 1024, 1024, 1024, CATW, 1024};
    int  Ns[11]  = {1024,1024,1024, 1024, 1024,1024, 1024, 1024, 1024, 1024, NL_};
    int  tK[11]  = {20,  16,  32,   32,   16,  32,   32,   32,   32,   52,   32};
    int  Nps[11] = {1024,1024,1024, 1024, 1024,1024, 1024, 1024, 1024, 1024, 2048};
    long offs[11]= {WOFF_QC, WOFF_AV, WOFF_AQN, WOFF_AQN + 1024L * 1024, WOFF_VN,
                    WOFF_QKV, WOFF_QKV + 1024L * 1024, WOFF_QKV + 2048L * 1024,
                    WOFF_WO, WOFF_UQC, WOFF_CLS};
    int pre = 0;
    for (int i = 0; i < 11; i++) {
        P.W[i] = Ws[i]; P.K[i] = Ks[i]; P.N[i] = Ns[i];
        P.tilesK[i] = tK[i]; P.off[i] = offs[i];
        P.pre[i] = pre;
        pre += tK[i] * (Nps[i] / 32);
    }
    P.pre[11] = pre;

    // 0: prep, 1: megaconv, 2: gather, 3: QEMB
    prep_kernel<<<TRB + IFB + 1, dim3(32, 8)>>>(v_org, img_feat, aq_b, qn_b);
    megaconv_kernel<<<pre, dim3(32, 8)>>>(P);
    gather_rv_kernel<<<(int)(((long)BR_ * TWO_E + 255) / 256), 256>>>(gt_verb, role_idx,
                                                                      verb_t, role_t);
    // query chain
    tgemm(ABF_RV, WOFF_QC, qc_b, -1, nullptr, 0, ABF_QEMB, 1024,
          BR_, 1024, 1024, 640, 1);

    // FUSED V1+V2 GEMM -> fp16 output (ABF_V12)
    tgemm(ABF_IMG0, WOFF_AV, av_b, -1, nullptr, 0, ABF_V12, 1024,
          2 * B_ * K_, 1024, 1024, 512, 1);

    tgemm(ABF_QEMB, WOFF_AQN, nullptr, OFF_BIASAQN, nullptr, OFF_QAQR, -1, 0,
          BR_, 2048, 2048, 1024, 1);

    // attention 1 + attention-verb in ONE launch (grid B x 2)
    att6_kernel<<<dim3(B_, 2), 256>>>(OFF_QAQR, 2048, ao_W, ao_b,
                                      ABF_VEMB12, ABF_VEMB12 + (long)BR_ * 512);

    // fused VN over [VEMB1;VEMB2]
    tgemm(ABF_VEMB12, WOFF_VN, vn_b, -1, nullptr, OFF_VREPR1, -1, 0,
          2 * BR_, 1024, 1024, 512, 1);

    // fused MFB for OUT & OUTV (mode 0)
    mfb_kernel<<<2 * BR_, 256>>>(OFF_QAQR + 1024, 2048, BR_, OFF_VREPR1, 0);

    // role-node neighbour attention
    tgemm(ABF_OUT, WOFF_QKV, nullptr, -1, nullptr, OFF_QKV3, -1, 0,
          BR_, 3072, 3072, 1024, 0);
    role_att_kernel<<<B_, 256, SMEM_ROLE>>>(mask);
    // WO writes fp16 DIRECTLY into CAT rows (stride 1664)
    tgemm(ABF_CTX, WOFF_WO, nullptr, -1, nullptr, 0, ABF_CAT, 1664,
          BR_, 1024, 1024, 1024, 0);

    // updated query
    tgemm(ABF_CAT, WOFF_UQC, uqc_b, -1, nullptr, 0, ABF_UQ, 1024,
          BR_, 1024, 1024, 1664, 1);
    tgemm(ABF_UQ, WOFF_AQN, nullptr, OFF_BIASAQN, nullptr, OFF_QAQR2, -1, 0,
          BR_, 2048, 2048, 1024, 1);

    // attention 2 (single source: V1 + img0)
    att6_kernel<<<dim3(B_, 1), 256>>>(OFF_QAQR2, 2048, ao_W, ao_b,
                                      ABF_VEMB3, ABF_VEMB3);
    tgemm(ABF_VEMB3, WOFF_VN, vn_b, -1, nullptr, OFF_VREPR2, -1, 0,
          BR_, 1024, 1024, 512, 1);

    // MFB(out2) fused with gated combine (mode 1) -> ABF_OUTF
    mfb_kernel<<<BR_, 256>>>(OFF_QAQR2 + 1024, 2048, BR_, OFF_VREPR2, 1);

    // classifier -> d_out
    tgemm(ABF_OUTF, WOFF_CLS, cls_b, -1, (float*)d_out, 0, -1, 0,
          BR_, NL_, 2048, 1024, 0);
}

// round 16
// speedup vs baseline: 1.4062x; 1.0436x over previous
#include <cuda_runtime.h>
#include <cuda_fp16.h>
#include <cstdint>
#include <math.h>

// ---------------------------------------------------------------------------
// Problem dims
// ---------------------------------------------------------------------------
constexpr int B_   = 256;
constexpr int R_   = 6;
constexpr int K_   = 49;
constexpr int C_   = 512;
constexpr int H_   = 1024;
constexpr int E_   = 300;
constexpr int BR_  = B_ * R_;          // 1536
constexpr int NL_  = 2001;
constexpr int TWO_E = 2 * E_;          // 600
constexpr int CATW  = H_ + TWO_E;      // 1624

// ---------------------------------------------------------------------------
// fp32 scratch
// ---------------------------------------------------------------------------
constexpr long SZ_IMG0 = (long)B_ * K_ * C_;   // 6422528
constexpr long SZ_H    = (long)BR_ * H_;
constexpr long SZ_2H   = (long)BR_ * 2048;
constexpr long SZ_3H   = (long)BR_ * 3072;

constexpr long OFF_QAQR  = 0;                     // [BR,2048] = [qa|qrepr]
constexpr long OFF_VREPR1= OFF_QAQR  + SZ_2H;     // [2BR,1024] (VREPR1;VREPRV)
constexpr long OFF_OUT   = OFF_VREPR1+ 2*SZ_H;    // [2BR,1024] (OUT;OUTV)
constexpr long OFF_QKV3  = OFF_OUT   + 2*SZ_H;    // [BR,3072]
constexpr long OFF_QAQR2 = OFF_QKV3  + SZ_3H;     // [BR,2048]
constexpr long OFF_VREPR2= OFF_QAQR2 + SZ_2H;
constexpr long OFF_BIASAQN = OFF_VREPR2 + SZ_H;   // 2048 floats
constexpr long SCRATCH_TOTAL = OFF_BIASAQN + 2048;

__device__ float g_scratch[SCRATCH_TOTAL];

// ---------------------------------------------------------------------------
// fp16 ACTIVATION plane (single plane). Zero-initialized.
// ---------------------------------------------------------------------------
constexpr long ABF_IMG0  = 0;                          // [12544][512]
constexpr long ABF_IMGF  = ABF_IMG0  + 12544L * 512;   // [12544][512]
constexpr long ABF_RV    = ABF_IMGF  + 12544L * 512;   // [1536][640]
constexpr long ABF_QEMB  = ABF_RV    + 1536L * 640;    // [1536][1024]
constexpr long ABF_VEMB12= ABF_QEMB  + 1536L * 1024;   // [3072][512]
constexpr long ABF_VEMB3 = ABF_VEMB12+ 3072L * 512;    // [1536][512]
constexpr long ABF_OUT   = ABF_VEMB3 + 1536L * 512;    // [3072][1024]
constexpr long ABF_CTX   = ABF_OUT   + 3072L * 1024;   // [1536][1024]
constexpr long ABF_CAT   = ABF_CTX   + 1536L * 1024;   // [1536][1664]
constexpr long ABF_UQ    = ABF_CAT   + 1536L * 1664;   // [1536][1024]
constexpr long ABF_OUTF  = ABF_UQ    + 1536L * 1024;   // [1536][1024]
constexpr long ABF_V12   = ABF_OUTF  + 1536L * 1024;   // [2*12544][1024] V1;V2 fp16
constexpr long ATOTAL    = ABF_V12   + 2L * 12544 * 1024;

__device__ __align__(256) __half g_abf[ATOTAL];

// ---------------------------------------------------------------------------
// fp16 WEIGHT planes (transposed [Npad][Kpad], hi at off, lo at off+WTOTAL)
// ---------------------------------------------------------------------------
constexpr long WOFF_QC  = 0;                           // [1024][640]
constexpr long WOFF_AV  = WOFF_QC  + 1024L * 640;      // [1024][512]
constexpr long WOFF_AQN = WOFF_AV  + 1024L * 512;      // [2048][1024]
constexpr long WOFF_VN  = WOFF_AQN + 2048L * 1024;     // [1024][512]
constexpr long WOFF_QKV = WOFF_VN  + 1024L * 512;      // [3072][1024]
constexpr long WOFF_WO  = WOFF_QKV + 3072L * 1024;     // [1024][1024]
constexpr long WOFF_UQC = WOFF_WO  + 1024L * 1024;     // [1024][1664]
constexpr long WOFF_CLS = WOFF_UQC + 1024L * 1664;     // [2048][1024]
constexpr long WTOTAL   = WOFF_CLS + 2048L * 1024;

__device__ __align__(256) __half g_wbf[2 * WTOTAL];

// ---------------------------------------------------------------------------
// helpers
// ---------------------------------------------------------------------------
__device__ __forceinline__ uint32_t smem_u32(const void* p) {
    uint32_t a;
    asm("{ .reg .u64 t; cvta.to.shared.u64 t, %1; cvt.u32.u64 %0, t; }" : "=r"(a) : "l"(p));
    return a;
}
__device__ __forceinline__ void stA(long base, float v) {
    g_abf[base] = __float2half_rn(v);
}
__device__ __forceinline__ void stA2(long base, float v0, float v1) {
    __half h0 = __float2half_rn(v0);
    __half h1 = __float2half_rn(v1);
    uint32_t p = (uint32_t)__half_as_ushort(h0) | ((uint32_t)__half_as_ushort(h1) << 16);
    *(uint32_t*)&g_abf[base] = p;
}
__device__ __forceinline__ void ldm_x4(uint32_t* r, uint32_t addr) {
    asm volatile("ldmatrix.sync.aligned.m8n8.x4.shared.b16 {%0,%1,%2,%3}, [%4];"
                 : "=r"(r[0]), "=r"(r[1]), "=r"(r[2]), "=r"(r[3]) : "r"(addr));
}
__device__ __forceinline__ void mma16816(float* c, const uint32_t* a, const uint32_t* b) {
    asm volatile(
        "mma.sync.aligned.m16n8k16.row.col.f32.f16.f16.f32 "
        "{%0,%1,%2,%3}, {%4,%5,%6,%7}, {%8,%9}, {%0,%1,%2,%3};"
        : "+f"(c[0]), "+f"(c[1]), "+f"(c[2]), "+f"(c[3])
        : "r"(a[0]), "r"(a[1]), "r"(a[2]), "r"(a[3]), "r"(b[0]), "r"(b[1]));
}
__device__ __forceinline__ void cpa16(uint32_t s, const void* g) {
    asm volatile("cp.async.cg.shared.global [%0], [%1], 16;" :: "r"(s), "l"(g));
}
#define CP_COMMIT() asm volatile("cp.async.commit_group;" ::: "memory")
#define CP_WAIT0()  asm volatile("cp.async.wait_group 0;" ::: "memory")

// ---------------------------------------------------------------------------
// megaconv: ALL weight transposes + fp16 hi/lo splits in ONE launch
// ---------------------------------------------------------------------------
struct WAll {
    const float* W[11];
    int K[11], N[11], tilesK[11];
    int pre[12];
    long off[11];
};

__global__ void megaconv_kernel(WAll P)
{
    __shared__ float tile[32][33];
    int bx = blockIdx.x;
    int w = 0;
    while (bx >= P.pre[w + 1]) w++;
    int tix = bx - P.pre[w];
    int tK  = P.tilesK[w];
    int k0  = (tix % tK) * 32;
    int n0  = (tix / tK) * 32;
    int K = P.K[w], N = P.N[w], Kp = tK * 32;
    const float* W = P.W[w];
    long off = P.off[w];

    int tx = threadIdx.x, ty = threadIdx.y;
#pragma unroll
    for (int i = 0; i < 32; i += 8) {
        int k = k0 + ty + i, n = n0 + tx;
        tile[ty + i][tx] = (k < K && n < N) ? W[(size_t)k * N + n] : 0.f;
    }
    __syncthreads();
#pragma unroll
    for (int i = 0; i < 32; i += 8) {
        int n = n0 + ty + i, k = k0 + tx;
        float v = tile[tx][ty + i];
        __half h = __float2half_rn(v);
        __half l = __float2half_rn(v - __half2float(h));
        long o = off + (long)n * Kp + k;
        g_wbf[o] = h;
        g_wbf[o + WTOTAL] = l;
    }
}

// ---------------------------------------------------------------------------
// prep: coalesced tiled v_org transpose (fp16 only) + img_feat + bias pack.
// ---------------------------------------------------------------------------
constexpr int TR_TILES_B = 2 * (C_ / 32);
constexpr int TRB = B_ * TR_TILES_B;                   // 8192
constexpr int IFB = (int)(SZ_IMG0 / 2048);             // 3136

__global__ void prep_kernel(const float* __restrict__ v_org,
                            const float* __restrict__ imgf,
                            const float* __restrict__ b0,
                            const float* __restrict__ b1)
{
    int bx = blockIdx.x;
    int tx = threadIdx.x, ty = threadIdx.y;
    int tid = ty * 32 + tx;

    if (bx < TRB) {
        __shared__ float tile[32][33];
        int b   = bx / TR_TILES_B;
        int t   = bx % TR_TILES_B;
        int k0  = (t & 1) * 32;
        int c0  = (t >> 1) * 32;
        const float* src = v_org + (long)b * C_ * K_;
#pragma unroll
        for (int i = 0; i < 32; i += 8) {
            int c = c0 + ty + i, k = k0 + tx;
            tile[ty + i][tx] = (k < K_) ? src[(long)c * K_ + k] : 0.f;
        }
        __syncthreads();
#pragma unroll
        for (int i = 0; i < 32; i += 8) {
            int k = k0 + ty + i, c = c0 + tx;
            if (k < K_) {
                long idx = ((long)b * K_ + k) * C_ + c;
                stA(ABF_IMG0 + idx, tile[tx][ty + i]);
            }
        }
    } else if (bx < TRB + IFB) {
        long base = (long)(bx - TRB) * 2048;
#pragma unroll
        for (int j = 0; j < 8; j++) {
            long i = base + tid + j * 256;
            stA(ABF_IMGF + i, imgf[i]);
        }
    } else {
#pragma unroll
        for (int j = 0; j < 8; j++) {
            int i = tid + j * 256;
            if (i < 1024)      g_scratch[OFF_BIASAQN + i] = b0[i];
            else if (i < 2048) g_scratch[OFF_BIASAQN + i] = b1[i - 1024];
        }
    }
}

// ---------------------------------------------------------------------------
// rv gather: fp16 into ABF_RV (stride 640) AND ABF_CAT cols 1024..
// ---------------------------------------------------------------------------
__global__ void gather_rv_kernel(const int* __restrict__ gt_verb,
                                 const int* __restrict__ role_idx,
                                 const float* __restrict__ vt,
                                 const float* __restrict__ rt)
{
    long idx = (long)blockIdx.x * 256 + threadIdx.x;
    if (idx >= (long)BR_ * TWO_E) return;
    int e = (int)(idx % TWO_E);
    int n = (int)(idx / TWO_E);
    int b = n / R_;
    float val = (e < E_) ? vt[(long)gt_verb[b] * E_ + e]
                         : rt[(long)role_idx[n] * E_ + (e - E_)];
    stA(ABF_RV  + (long)n * 640  + e, val);
    stA(ABF_CAT + (long)n * 1664 + 1024 + e, val);
}

// ---------------------------------------------------------------------------
// HMMA fp16 2-term GEMM: D = Ah@(Bh+Bl). BM=64, 4 warps (2x2),
// warp tile 32 x (BN/2). 2-stage cp.async pipeline, padded smem.
// ---------------------------------------------------------------------------
template<int BN, int NT, int MAXCTA>
__global__ __launch_bounds__(128, MAXCTA)
void mma_gemm_kernel(long aOff, long wOff,
                     const float* __restrict__ biasPtr, long biasOff,
                     float* CExt, long offC, long offCbf, int cbfStride,
                     int M, int N, int Kp, int act)
{
    constexpr int BM = 64, BKP = 40;
    constexpr int MI  = 2;
    constexpr int ASZ = BM * BKP;
    constexpr int BSZ = BN * BKP;
    constexpr int STG = ASZ + 2 * BSZ;
    constexpr uint32_t ASZ2 = ASZ * 2, BSZ2 = BSZ * 2;

    extern __shared__ __align__(16) __half sm[];
    const __half* Ahp = g_abf + aOff;
    const __half* Bwh = g_wbf + wOff;
    const __half* Bwl = g_wbf + wOff + WTOTAL;
    const float* bias = biasPtr ? biasPtr
                      : (biasOff >= 0 ? (const float*)(g_scratch + biasOff) : nullptr);

    const int tid  = threadIdx.x;
    const int wid  = tid >> 5, lane = tid & 31;
    const int brow = blockIdx.y * BM, bcol = blockIdx.x * BN;
    const int wm   = (wid >> 1) * 32;
    const int wn   = (wid & 1) * (BN / 2);
    const uint32_t sb = smem_u32(sm);

    auto cpAll = [&](int t, int s) {
        const uint32_t st = sb + (uint32_t)(s * STG) * 2;
#pragma unroll
        for (int l = 0; l < 2; l++) {
            int idx = tid + l * 128;
            int row = idx >> 2, seg = idx & 3;
            size_t go = (size_t)(brow + row) * Kp + t * 32 + seg * 8;
            uint32_t so = (uint32_t)(row * BKP + seg * 8) * 2;
            cpa16(st + so, Ahp + go);
        }
#pragma unroll
        for (int l = 0; l < BN / 32; l++) {
            int idx = tid + l * 128;
            int row = idx >> 2, seg = idx & 3;
            size_t go = (size_t)(bcol + row) * Kp + t * 32 + seg * 8;
            uint32_t so = (uint32_t)(row * BKP + seg * 8) * 2;
            cpa16(st + ASZ2 + so,        Bwh + go);
            cpa16(st + ASZ2 + BSZ2 + so, Bwl + go);
        }
    };

    float acc[MI][NT][4];
#pragma unroll
    for (int i = 0; i < MI; i++)
#pragma unroll
        for (int j = 0; j < NT; j++)
#pragma unroll
            for (int q = 0; q < 4; q++) acc[i][j][q] = 0.f;

    const int nCh = Kp / 32;

    cpAll(0, 0); CP_COMMIT();
    CP_WAIT0();
    __syncthreads();

    const int aRow = (lane & 7) + ((lane >> 3) & 1) * 8;
    const int aCol = (lane >> 4) * 8;
    const int bRow = (lane & 7) + ((lane >> 4) & 1) * 8;
    const int bCol = ((lane >> 3) & 1) * 8;

    for (int t = 0; t < nCh; t++) {
        const int s = t & 1;
        if (t + 1 < nCh) { cpAll(t + 1, s ^ 1); CP_COMMIT(); }

        const uint32_t ahB = sb + (uint32_t)(s * STG) * 2;
        const uint32_t bhB = ahB + ASZ2;
        const uint32_t blB = bhB + BSZ2;

#pragma unroll
        for (int ks = 0; ks < 2; ks++) {
            uint32_t ah[MI][4];
#pragma unroll
            for (int mi = 0; mi < MI; mi++) {
                uint32_t off = (uint32_t)((wm + mi * 16 + aRow) * BKP + ks * 16 + aCol) * 2;
                ldm_x4(ah[mi], ahB + off);
            }
            uint32_t bh[NT][2], bl[NT][2];
#pragma unroll
            for (int bt = 0; bt < NT / 2; bt++) {
                uint32_t off = (uint32_t)((wn + bt * 16 + bRow) * BKP + ks * 16 + bCol) * 2;
                uint32_t r[4];
                ldm_x4(r, bhB + off);
                bh[2 * bt][0] = r[0]; bh[2 * bt][1] = r[1];
                bh[2 * bt + 1][0] = r[2]; bh[2 * bt + 1][1] = r[3];
                ldm_x4(r, blB + off);
                bl[2 * bt][0] = r[0]; bl[2 * bt][1] = r[1];
                bl[2 * bt + 1][0] = r[2]; bl[2 * bt + 1][1] = r[3];
            }
#pragma unroll
            for (int mi = 0; mi < MI; mi++)
#pragma unroll
                for (int ni = 0; ni < NT; ni++) {
                    mma16816(acc[mi][ni], ah[mi], bh[ni]);
                    mma16816(acc[mi][ni], ah[mi], bl[ni]);
                }
        }

        if (t + 1 < nCh) {
            CP_WAIT0();
            __syncthreads();
        }
    }

    // epilogue
    float* C = CExt ? CExt : (g_scratch + offC);
#pragma unroll
    for (int mi = 0; mi < MI; mi++) {
#pragma unroll
        for (int ni = 0; ni < NT; ni++) {
            int r0 = brow + wm + mi * 16 + (lane >> 2);
            int c0 = bcol + wn + ni * 8 + 2 * (lane & 3);
#pragma unroll
            for (int half = 0; half < 2; half++) {
                int gr = r0 + half * 8;
                float v0 = acc[mi][ni][2 * half + 0];
                float v1 = acc[mi][ni][2 * half + 1];
                if (offCbf >= 0) {
                    if (bias) { v0 += bias[c0]; v1 += bias[c0 + 1]; }
                    if (act)  { v0 = fmaxf(v0, 0.f); v1 = fmaxf(v1, 0.f); }
                    stA2(offCbf + (long)gr * cbfStride + c0, v0, v1);
                } else {
                    if (c0 < N) {
                        float o = v0 + (bias ? bias[c0] : 0.f);
                        if (act) o = fmaxf(o, 0.f);
                        C[(size_t)gr * N + c0] = o;
                    }
                    if (c0 + 1 < N) {
                        float o = v1 + (bias ? bias[c0 + 1] : 0.f);
                        if (act) o = fmaxf(o, 0.f);
                        C[(size_t)gr * N + c0 + 1] = o;
                    }
                }
            }
        }
    }
}

constexpr int SMEM_BIG   = 2 * (64 * 40 + 2 * 128 * 40) * 2;  // 51200 B
constexpr int SMEM_SMALL = 2 * (64 * 40 + 2 * 64 * 40) * 2;   // 30720 B

static inline void tgemm(long aOff, long wOff, const float* bias, long biasOff,
                         float* CExt, long offC, long offCbf, int cbfStride,
                         int M, int N, int Np, int Kp, int act)
{
    if (M >= 4096 || Np >= 2048) {
        dim3 grid(Np / 128, M / 64);
        mma_gemm_kernel<128, 8, 3><<<grid, 128, SMEM_BIG>>>(
            aOff, wOff, bias, biasOff, CExt, offC, offCbf, cbfStride, M, N, Kp, act);
    } else {
        dim3 grid(Np / 64, M / 64);
        mma_gemm_kernel<64, 4, 4><<<grid, 128, SMEM_SMALL>>>(
            aOff, wOff, bias, biasOff, CExt, offC, offCbf, cbfStride, M, N, Kp, act);
    }
}

// ---------------------------------------------------------------------------
// Visual attention (block per (b, src)); V and img fp16, half2 vemb phase.
// ---------------------------------------------------------------------------
__global__ __launch_bounds__(256) void att6_kernel(
    long offQA, int qStride,
    const float* __restrict__ aoW, const float* __restrict__ aoB,
    long abfOut0, long abfOut1)
{
    int b  = blockIdx.x;
    int which = blockIdx.y;
    int n0 = b * R_;
    const __half* V   = g_abf + ABF_V12 + ((long)which * B_ * K_ + (long)b * K_) * H_;
    const __half* img = g_abf + (which ? ABF_IMGF : ABF_IMG0) + (long)b * K_ * C_;
    long abfOut = which ? abfOut1 : abfOut0;

    __shared__ __align__(16) float qa[R_][H_];
    __shared__ float attw[R_][K_ + 1];

    int tid = threadIdx.x, wid = tid >> 5, lane = tid & 31;

    for (int idx = tid; idx < R_ * H_; idx += 256) {
        int r = idx / H_, h = idx % H_;
        qa[r][h] = g_scratch[offQA + (long)(n0 + r) * qStride + h] * aoW[h];
    }
    __syncthreads();

    for (int k = wid; k < K_; k += 8) {
        const uint4* vk = (const uint4*)(V + (long)k * H_);
        float s0=0,s1=0,s2=0,s3=0,s4=0,s5=0;
#pragma unroll
        for (int h8 = lane; h8 < H_ / 8; h8 += 32) {
            uint4 pv = vk[h8];
            const __half2* ph = (const __half2*)&pv;
            float2 f0 = __half22float2(ph[0]);
            float2 f1 = __half22float2(ph[1]);
            float2 f2 = __half22float2(ph[2]);
            float2 f3 = __half22float2(ph[3]);
            float vv[8] = {f0.x, f0.y, f1.x, f1.y, f2.x, f2.y, f3.x, f3.y};
            int hb = h8 * 8;
#pragma unroll
            for (int r = 0; r < R_; r++) {
                const float* qr = &qa[r][hb];
                float acc = vv[0]*qr[0] + vv[1]*qr[1] + vv[2]*qr[2] + vv[3]*qr[3]
                          + vv[4]*qr[4] + vv[5]*qr[5] + vv[6]*qr[6] + vv[7]*qr[7];
                if (r == 0) s0 += acc; else if (r == 1) s1 += acc;
                else if (r == 2) s2 += acc; else if (r == 3) s3 += acc;
                else if (r == 4) s4 += acc; else s5 += acc;
            }
        }
#pragma unroll
        for (int o = 16; o; o >>= 1) {
            s0 += __shfl_xor_sync(0xffffffffu, s0, o);
            s1 += __shfl_xor_sync(0xffffffffu, s1, o);
            s2 += __shfl_xor_sync(0xffffffffu, s2, o);
            s3 += __shfl_xor_sync(0xffffffffu, s3, o);
            s4 += __shfl_xor_sync(0xffffffffu, s4, o);
            s5 += __shfl_xor_sync(0xffffffffu, s5, o);
        }
        if (lane == 0) {
            float ab = aoB[0];
            attw[0][k] = s0 + ab; attw[1][k] = s1 + ab; attw[2][k] = s2 + ab;
            attw[3][k] = s3 + ab; attw[4][k] = s4 + ab; attw[5][k] = s5 + ab;
        }
    }
    __syncthreads();

    if (tid < R_) {
        float mx = -1e30f;
        for (int k = 0; k < K_; k++) mx = fmaxf(mx, attw[tid][k]);
        float sum = 0.f;
        for (int k = 0; k < K_; k++) sum += expf(attw[tid][k] - mx);
        float inv = 1.f / sum;
        for (int k = 0; k < K_; k++) attw[tid][k] = expf(attw[tid][k] - mx) * inv;
    }
    __syncthreads();

    // vemb: 2 columns per thread via half2 (C_ = 2 * 256)
    {
        const __half2* img2 = (const __half2*)img;
        int c2 = tid;                       // 0..255
        float a0x=0,a0y=0,a1x=0,a1y=0,a2x=0,a2y=0;
        float a3x=0,a3y=0,a4x=0,a4y=0,a5x=0,a5y=0;
#pragma unroll 7
        for (int k = 0; k < K_; k++) {
            float2 f = __half22float2(img2[(long)k * (C_ / 2) + c2]);
            float w0 = attw[0][k], w1 = attw[1][k], w2 = attw[2][k];
            float w3 = attw[3][k], w4 = attw[4][k], w5 = attw[5][k];
            a0x = fmaf(w0, f.x, a0x); a0y = fmaf(w0, f.y, a0y);
            a1x = fmaf(w1, f.x, a1x); a1y = fmaf(w1, f.y, a1y);
            a2x = fmaf(w2, f.x, a2x); a2y = fmaf(w2, f.y, a2y);
            a3x = fmaf(w3, f.x, a3x); a3y = fmaf(w3, f.y, a3y);
            a4x = fmaf(w4, f.x, a4x); a4y = fmaf(w4, f.y, a4y);
            a5x = fmaf(w5, f.x, a5x); a5y = fmaf(w5, f.y, a5y);
        }
        long base = abfOut + (long)n0 * C_ + 2 * c2;
        stA2(base,          a0x, a0y); stA2(base + C_,     a1x, a1y);
        stA2(base + 2 * C_, a2x, a2y); stA2(base + 3 * C_, a3x, a3y);
        stA2(base + 4 * C_, a4x, a4y); stA2(base + 5 * C_, a5x, a5y);
    }
}

// ---------------------------------------------------------------------------
// MFB pool, single pass (z cached in registers; H = 4 * 256 exactly).
// mode 0: fp32 rows (OUT/OUTV) + fp16 (ABF_OUT).
// mode 1: fuse gated combine -> ABF_OUTF.
// ---------------------------------------------------------------------------
__global__ void mfb_kernel(long offQ, int qStride, int qWrap,
                           long offV, int mode)
{
    int n = blockIdx.x;
    const float* q = g_scratch + offQ + (long)(n % qWrap) * qStride;
    const float* v = g_scratch + offV + (long)n * H_;
    int tid = threadIdx.x;

    float zreg[4];
    float s = 0.f;
#pragma unroll
    for (int j = 0; j < 4; j++) {
        int h = tid + j * 256;
        float z = q[h] * v[h];
        zreg[j] = z;
        s += fabsf(z);
    }
    __shared__ float red[8];
#pragma unroll
    for (int off = 16; off; off >>= 1) s += __shfl_xor_sync(0xffffffffu, s, off);
    if ((tid & 31) == 0) red[tid >> 5] = s;
    __syncthreads();
    float tot = 0.f;
#pragma unroll
    for (int i = 0; i < 8; i++) tot += red[i];
    float inv = 1.f / fmaxf(sqrtf(tot), 1e-12f);

#pragma unroll
    for (int j = 0; j < 4; j++) {
        int h = tid + j * 256;
        float z = zreg[j];
        float sg = (z > 0.f) ? sqrtf(z) : -sqrtf(-z);
        float r = sg * inv;
        if (mode == 0) {
            g_scratch[OFF_OUT + (long)n * H_ + h] = r;
            stA(ABF_OUT + (long)n * H_ + h, r);
        } else {
            float ov = g_scratch[OFF_OUT + SZ_H + (long)n * H_ + h];
            float a0 = g_scratch[OFF_OUT + (long)n * H_ + h];
            float g  = 1.f / (1.f + expf(-(r + ov)));
            stA(ABF_OUTF + (long)n * H_ + h, (1.f - g) * ov + g * tanhf(r + a0));
        }
    }
}

// ---------------------------------------------------------------------------
// Masked role attention with q/k/v cached in smem (float4 fill) -> fp16 ctx.
// ---------------------------------------------------------------------------
__global__ __launch_bounds__(256, 1) void role_att_kernel(const int* __restrict__ mask)
{
    extern __shared__ float rs[];
    float* qs = rs;
    float* ks = rs + 6 * 1024;
    float* vs = rs + 12 * 1024;

    int b = blockIdx.x;
    const float* base = g_scratch + OFF_QKV3 + (long)b * R_ * 3072;

    __shared__ float sc[R_][R_];
    __shared__ float attn[R_][R_];
    int tid = threadIdx.x, wid = tid >> 5, lane = tid & 31;

    // float4 fill: layout in smem mirrors [role][part][h] source order:
    // rs is organized q rows 0-5 | k rows 6-11 | v rows 12-17, where
    // row = part*6 + role. Source float4 index: (role*3072 + part*1024)/4.
#pragma unroll
    for (int j = 0; j < 18; j++) {
        int f4 = tid + j * 256;                 // 0 .. 4607 float4s
        int row = f4 >> 8;                      // /256 float4s per 1024 row
        int h4  = f4 & 255;
        int part = row / 6, role = row % 6;
        *(float4*)&rs[(long)row * 1024 + h4 * 4] =
            *(const float4*)&base[(long)role * 3072 + part * 1024 + h4 * 4];
    }
    __syncthreads();

    for (int p = wid; p < R_ * R_; p += 8) {
        int i = p / R_, j = p % R_;
        const float* qh = qs + i * 1024;
        const float* kh = ks + j * 1024;
        float s = 0.f;
        for (int h = lane; h < H_; h += 32)
            s = fmaf(qh[h], kh[h], s);
#pragma unroll
        for (int o = 16; o; o >>= 1) s += __shfl_xor_sync(0xffffffffu, s, o);
        if (lane == 0) {
            bool valid = (i != j) && (mask[((long)b * R_ + i) * R_ + j] > 0);
            sc[i][j] = valid ? s * (1.f / 32.f) : -1e9f;
        }
    }
    __syncthreads();

    if (tid < R_ * R_) {
        int i = tid / R_, j = tid % R_;
        float mx = -1e30f;
        for (int jj = 0; jj < R_; jj++) mx = fmaxf(mx, sc[i][jj]);
        float sum = 0.f;
        for (int jj = 0; jj < R_; jj++) sum += expf(sc[i][jj] - mx);
        attn[i][j] = expf(sc[i][j] - mx) / sum;
    }
    __syncthreads();

    for (int idx = tid; idx < R_ * H_; idx += 256) {
        int i = idx / H_, h = idx % H_;
        float acc = 0.f;
#pragma unroll
        for (int j = 0; j < R_; j++)
            acc = fmaf(attn[i][j], vs[j * 1024 + h], acc);
        stA(ABF_CTX + (long)(b * R_ + i) * H_ + h, acc);
    }
}

constexpr int SMEM_ROLE = 18 * 1024 * 4;   // 73728 B

// ---------------------------------------------------------------------------
// Launch sequence
// ---------------------------------------------------------------------------
extern "C" void kernel_launch(void* const* d_in, const int* in_sizes, int n_in,
                              void* d_out, int out_size)
{
    const float* v_org    = (const float*)d_in[0];
    const float* img_feat = (const float*)d_in[1];
    const int*   gt_verb  = (const int*)d_in[2];
    const int*   role_idx = (const int*)d_in[3];
    const int*   mask     = (const int*)d_in[4];
    const float* verb_t   = (const float*)d_in[5];
    const float* role_t   = (const float*)d_in[6];
    const float* qc_W = (const float*)d_in[7];   const float* qc_b = (const float*)d_in[8];
    const float* av_W = (const float*)d_in[9];   const float* av_b = (const float*)d_in[10];
    const float* aq_W = (const float*)d_in[11];  const float* aq_b = (const float*)d_in[12];
    const float* ao_W = (const float*)d_in[13];  const float* ao_b = (const float*)d_in[14];
    const float* vn_W = (const float*)d_in[15];  const float* vn_b = (const float*)d_in[16];
    const float* qn_W = (const float*)d_in[17];  const float* qn_b = (const float*)d_in[18];
    const float* Wq   = (const float*)d_in[19];
    const float* Wk   = (const float*)d_in[20];
    const float* Wv   = (const float*)d_in[21];
    const float* Wo   = (const float*)d_in[22];
    const float* uqc_W = (const float*)d_in[23]; const float* uqc_b = (const float*)d_in[24];
    const float* cls_W = (const float*)d_in[25]; const float* cls_b = (const float*)d_in[26];

    cudaFuncSetAttribute((const void*)mma_gemm_kernel<128, 8, 3>,
                         cudaFuncAttributeMaxDynamicSharedMemorySize, SMEM_BIG);
    cudaFuncSetAttribute((const void*)mma_gemm_kernel<64, 4, 4>,
                         cudaFuncAttributeMaxDynamicSharedMemorySize, SMEM_SMALL);
    cudaFuncSetAttribute((const void*)role_att_kernel,
                         cudaFuncAttributeMaxDynamicSharedMemorySize, SMEM_ROLE);

    // megaconv descriptor table
    WAll P;
    const float* Ws[11] = {qc_W, av_W, aq_W, qn_W, vn_W, Wq, Wk, Wv, Wo, uqc_W, cls_W};
    int  Ks[11]  = {600, 512, 1024, 1024, 512, 1024, 1024, 1024, 1024, CATW, 1024};
    int  Ns[11]  = {1024,1024,1024, 1024, 1024,1024, 1024, 1024, 1024, 1024, NL_};
    int  tK[11]  = {20,  16,  32,   32,   16,  32,   32,   32,   32,   52,   32};
    int  Nps[11] = {1024,1024,1024, 1024, 1024,1024, 1024, 1024, 1024, 1024, 2048};
    long offs[11]= {WOFF_QC, WOFF_AV, WOFF_AQN, WOFF_AQN + 1024L * 1024, WOFF_VN,
                    WOFF_QKV, WOFF_QKV + 1024L * 1024, WOFF_QKV + 2048L * 1024,
                    WOFF_WO, WOFF_UQC, WOFF_CLS};
    int pre = 0;
    for (int i = 0; i < 11; i++) {
        P.W[i] = Ws[i]; P.K[i] = Ks[i]; P.N[i] = Ns[i];
        P.tilesK[i] = tK[i]; P.off[i] = offs[i];
        P.pre[i] = pre;
        pre += tK[i] * (Nps[i] / 32);
    }
    P.pre[11] = pre;

    // 0: prep, 1: megaconv, 2: gather, 3: QEMB
    prep_kernel<<<TRB + IFB + 1, dim3(32, 8)>>>(v_org, img_feat, aq_b, qn_b);
    megaconv_kernel<<<pre, dim3(32, 8)>>>(P);
    gather_rv_kernel<<<(int)(((long)BR_ * TWO_E + 255) / 256), 256>>>(gt_verb, role_idx,
                                                                      verb_t, role_t);
    // query chain
    tgemm(ABF_RV, WOFF_QC, qc_b, -1, nullptr, 0, ABF_QEMB, 1024,
          BR_, 1024, 1024, 640, 1);

    // FUSED V1+V2 GEMM -> fp16 output (ABF_V12)
    tgemm(ABF_IMG0, WOFF_AV, av_b, -1, nullptr, 0, ABF_V12, 1024,
          2 * B_ * K_, 1024, 1024, 512, 1);

    tgemm(ABF_QEMB, WOFF_AQN, nullptr, OFF_BIASAQN, nullptr, OFF_QAQR, -1, 0,
          BR_, 2048, 2048, 1024, 1);

    // attention 1 + attention-verb in ONE launch (grid B x 2)
    att6_kernel<<<dim3(B_, 2), 256>>>(OFF_QAQR, 2048, ao_W, ao_b,
                                      ABF_VEMB12, ABF_VEMB12 + (long)BR_ * 512);

    // fused VN over [VEMB1;VEMB2]
    tgemm(ABF_VEMB12, WOFF_VN, vn_b, -1, nullptr, OFF_VREPR1, -1, 0,
          2 * BR_, 1024, 1024, 512, 1);

    // fused MFB for OUT & OUTV (mode 0)
    mfb_kernel<<<2 * BR_, 256>>>(OFF_QAQR + 1024, 2048, BR_, OFF_VREPR1, 0);

    // role-node neighbour attention
    tgemm(ABF_OUT, WOFF_QKV, nullptr, -1, nullptr, OFF_QKV3, -1, 0,
          BR_, 3072, 3072, 1024, 0);
    role_att_kernel<<<B_, 256, SMEM_ROLE>>>(mask);
    // WO writes fp16 DIRECTLY into CAT rows (stride 1664)
    tgemm(ABF_CTX, WOFF_WO, nullptr, -1, nullptr, 0, ABF_CAT, 1664,
          BR_, 1024, 1024, 1024, 0);

    // updated query
    tgemm(ABF_CAT, WOFF_UQC, uqc_b, -1, nullptr, 0, ABF_UQ, 1024,
          BR_, 1024, 1024, 1664, 1);
    tgemm(ABF_UQ, WOFF_AQN, nullptr, OFF_BIASAQN, nullptr, OFF_QAQR2, -1, 0,
          BR_, 2048, 2048, 1024, 1);

    // attention 2 (single source: V1 + img0)
    att6_kernel<<<dim3(B_, 1), 256>>>(OFF_QAQR2, 2048, ao_W, ao_b,
                                      ABF_VEMB3, ABF_VEMB3);
    tgemm(ABF_VEMB3, WOFF_VN, vn_b, -1, nullptr, OFF_VREPR2, -1, 0,
          BR_, 1024, 1024, 512, 1);

    // MFB(out2) fused with gated combine (mode 1) -> ABF_OUTF
    mfb_kernel<<<BR_, 256>>>(OFF_QAQR2 + 1024, 2048, BR_, OFF_VREPR2, 1);

    // classifier -> d_out
    tgemm(ABF_OUTF, WOFF_CLS, cls_b, -1, (float*)d_out, 0, -1, 0,
          BR_, NL_, 2048, 1024, 0);
}

// round 17
// speedup vs baseline: 1.5560x; 1.1065x over previous
#include <cuda_runtime.h>
#include <cuda_fp16.h>
#include <cstdint>
#include <math.h>

// ---------------------------------------------------------------------------
// Problem dims
// ---------------------------------------------------------------------------
constexpr int B_   = 256;
constexpr int R_   = 6;
constexpr int K_   = 49;
constexpr int C_   = 512;
constexpr int H_   = 1024;
constexpr int E_   = 300;
constexpr int BR_  = B_ * R_;          // 1536
constexpr int NL_  = 2001;
constexpr int TWO_E = 2 * E_;          // 600
constexpr int CATW  = H_ + TWO_E;      // 1624

// ---------------------------------------------------------------------------
// fp32 scratch
// ---------------------------------------------------------------------------
constexpr long SZ_IMG0 = (long)B_ * K_ * C_;   // 6422528
constexpr long SZ_H    = (long)BR_ * H_;
constexpr long SZ_2H   = (long)BR_ * 2048;
constexpr long SZ_3H   = (long)BR_ * 3072;

constexpr long OFF_QAQR  = 0;                     // [BR,2048] = [qa|qrepr]
constexpr long OFF_VREPR1= OFF_QAQR  + SZ_2H;     // [2BR,1024] (VREPR1;VREPRV)
constexpr long OFF_OUT   = OFF_VREPR1+ 2*SZ_H;    // [2BR,1024] (OUT;OUTV)
constexpr long OFF_QKV3  = OFF_OUT   + 2*SZ_H;    // [BR,3072]
constexpr long OFF_QAQR2 = OFF_QKV3  + SZ_3H;     // [BR,2048]
constexpr long OFF_VREPR2= OFF_QAQR2 + SZ_2H;
constexpr long OFF_BIASAQN = OFF_VREPR2 + SZ_H;   // 2048 floats
constexpr long SCRATCH_TOTAL = OFF_BIASAQN + 2048;

__device__ float g_scratch[SCRATCH_TOTAL];

// ---------------------------------------------------------------------------
// fp16 ACTIVATION plane (single plane). Zero-initialized.
// ---------------------------------------------------------------------------
constexpr long ABF_IMG0  = 0;                          // [12544][512]
constexpr long ABF_IMGF  = ABF_IMG0  + 12544L * 512;   // [12544][512]
constexpr long ABF_RV    = ABF_IMGF  + 12544L * 512;   // [1536][640]
constexpr long ABF_QEMB  = ABF_RV    + 1536L * 640;    // [1536][1024]
constexpr long ABF_VEMB12= ABF_QEMB  + 1536L * 1024;   // [3072][512]
constexpr long ABF_VEMB3 = ABF_VEMB12+ 3072L * 512;    // [1536][512]
constexpr long ABF_OUT   = ABF_VEMB3 + 1536L * 512;    // [3072][1024]
constexpr long ABF_CTX   = ABF_OUT   + 3072L * 1024;   // [1536][1024]
constexpr long ABF_CAT   = ABF_CTX   + 1536L * 1024;   // [1536][1664]
constexpr long ABF_UQ    = ABF_CAT   + 1536L * 1664;   // [1536][1024]
constexpr long ABF_OUTF  = ABF_UQ    + 1536L * 1024;   // [1536][1024]
constexpr long ABF_V12   = ABF_OUTF  + 1536L * 1024;   // [2*12544][1024] V1;V2 fp16
constexpr long ATOTAL    = ABF_V12   + 2L * 12544 * 1024;

__device__ __align__(256) __half g_abf[ATOTAL];

// ---------------------------------------------------------------------------
// fp16 WEIGHT planes (transposed [Npad][Kpad], hi at off, lo at off+WTOTAL)
// ---------------------------------------------------------------------------
constexpr long WOFF_QC  = 0;                           // [1024][640]
constexpr long WOFF_AV  = WOFF_QC  + 1024L * 640;      // [1024][512]
constexpr long WOFF_AQN = WOFF_AV  + 1024L * 512;      // [2048][1024]
constexpr long WOFF_VN  = WOFF_AQN + 2048L * 1024;     // [1024][512]
constexpr long WOFF_QKV = WOFF_VN  + 1024L * 512;      // [3072][1024]
constexpr long WOFF_WO  = WOFF_QKV + 3072L * 1024;     // [1024][1024]
constexpr long WOFF_UQC = WOFF_WO  + 1024L * 1024;     // [1024][1664]
constexpr long WOFF_CLS = WOFF_UQC + 1024L * 1664;     // [2048][1024]
constexpr long WTOTAL   = WOFF_CLS + 2048L * 1024;

__device__ __align__(256) __half g_wbf[2 * WTOTAL];

// ---------------------------------------------------------------------------
// helpers
// ---------------------------------------------------------------------------
__device__ __forceinline__ uint32_t smem_u32(const void* p) {
    uint32_t a;
    asm("{ .reg .u64 t; cvta.to.shared.u64 t, %1; cvt.u32.u64 %0, t; }" : "=r"(a) : "l"(p));
    return a;
}
__device__ __forceinline__ void stA(long base, float v) {
    g_abf[base] = __float2half_rn(v);
}
__device__ __forceinline__ void stA2(long base, float v0, float v1) {
    __half h0 = __float2half_rn(v0);
    __half h1 = __float2half_rn(v1);
    uint32_t p = (uint32_t)__half_as_ushort(h0) | ((uint32_t)__half_as_ushort(h1) << 16);
    *(uint32_t*)&g_abf[base] = p;
}
__device__ __forceinline__ void ldm_x4(uint32_t* r, uint32_t addr) {
    asm volatile("ldmatrix.sync.aligned.m8n8.x4.shared.b16 {%0,%1,%2,%3}, [%4];"
                 : "=r"(r[0]), "=r"(r[1]), "=r"(r[2]), "=r"(r[3]) : "r"(addr));
}
__device__ __forceinline__ void mma16816(float* c, const uint32_t* a, const uint32_t* b) {
    asm volatile(
        "mma.sync.aligned.m16n8k16.row.col.f32.f16.f16.f32 "
        "{%0,%1,%2,%3}, {%4,%5,%6,%7}, {%8,%9}, {%0,%1,%2,%3};"
        : "+f"(c[0]), "+f"(c[1]), "+f"(c[2]), "+f"(c[3])
        : "r"(a[0]), "r"(a[1]), "r"(a[2]), "r"(a[3]), "r"(b[0]), "r"(b[1]));
}
__device__ __forceinline__ void cpa16(uint32_t s, const void* g) {
    asm volatile("cp.async.cg.shared.global [%0], [%1], 16;" :: "r"(s), "l"(g));
}
#define CP_COMMIT() asm volatile("cp.async.commit_group;" ::: "memory")
#define CP_WAIT0()  asm volatile("cp.async.wait_group 0;" ::: "memory")

// ---------------------------------------------------------------------------
// megaconv: ALL weight transposes + fp16 hi/lo splits in ONE launch
// ---------------------------------------------------------------------------
struct WAll {
    const float* W[11];
    int K[11], N[11], tilesK[11];
    int pre[12];
    long off[11];
};

__global__ void megaconv_kernel(WAll P)
{
    __shared__ float tile[32][33];
    int bx = blockIdx.x;
    int w = 0;
    while (bx >= P.pre[w + 1]) w++;
    int tix = bx - P.pre[w];
    int tK  = P.tilesK[w];
    int k0  = (tix % tK) * 32;
    int n0  = (tix / tK) * 32;
    int K = P.K[w], N = P.N[w], Kp = tK * 32;
    const float* W = P.W[w];
    long off = P.off[w];

    int tx = threadIdx.x, ty = threadIdx.y;
#pragma unroll
    for (int i = 0; i < 32; i += 8) {
        int k = k0 + ty + i, n = n0 + tx;
        tile[ty + i][tx] = (k < K && n < N) ? W[(size_t)k * N + n] : 0.f;
    }
    __syncthreads();
#pragma unroll
    for (int i = 0; i < 32; i += 8) {
        int n = n0 + ty + i, k = k0 + tx;
        float v = tile[tx][ty + i];
        __half h = __float2half_rn(v);
        __half l = __float2half_rn(v - __half2float(h));
        long o = off + (long)n * Kp + k;
        g_wbf[o] = h;
        g_wbf[o + WTOTAL] = l;
    }
}

// ---------------------------------------------------------------------------
// prep: coalesced tiled v_org transpose (fp16 only) + img_feat + bias pack.
// ---------------------------------------------------------------------------
constexpr int TR_TILES_B = 2 * (C_ / 32);
constexpr int TRB = B_ * TR_TILES_B;                   // 8192
constexpr int IFB = (int)(SZ_IMG0 / 2048);             // 3136

__global__ void prep_kernel(const float* __restrict__ v_org,
                            const float* __restrict__ imgf,
                            const float* __restrict__ b0,
                            const float* __restrict__ b1)
{
    int bx = blockIdx.x;
    int tx = threadIdx.x, ty = threadIdx.y;
    int tid = ty * 32 + tx;

    if (bx < TRB) {
        __shared__ float tile[32][33];
        int b   = bx / TR_TILES_B;
        int t   = bx % TR_TILES_B;
        int k0  = (t & 1) * 32;
        int c0  = (t >> 1) * 32;
        const float* src = v_org + (long)b * C_ * K_;
#pragma unroll
        for (int i = 0; i < 32; i += 8) {
            int c = c0 + ty + i, k = k0 + tx;
            tile[ty + i][tx] = (k < K_) ? src[(long)c * K_ + k] : 0.f;
        }
        __syncthreads();
#pragma unroll
        for (int i = 0; i < 32; i += 8) {
            int k = k0 + ty + i, c = c0 + tx;
            if (k < K_) {
                long idx = ((long)b * K_ + k) * C_ + c;
                stA(ABF_IMG0 + idx, tile[tx][ty + i]);
            }
        }
    } else if (bx < TRB + IFB) {
        long base = (long)(bx - TRB) * 2048;
#pragma unroll
        for (int j = 0; j < 8; j++) {
            long i = base + tid + j * 256;
            stA(ABF_IMGF + i, imgf[i]);
        }
    } else {
#pragma unroll
        for (int j = 0; j < 8; j++) {
            int i = tid + j * 256;
            if (i < 1024)      g_scratch[OFF_BIASAQN + i] = b0[i];
            else if (i < 2048) g_scratch[OFF_BIASAQN + i] = b1[i - 1024];
        }
    }
}

// ---------------------------------------------------------------------------
// rv gather: fp16 into ABF_RV (stride 640) AND ABF_CAT cols 1024..
// ---------------------------------------------------------------------------
__global__ void gather_rv_kernel(const int* __restrict__ gt_verb,
                                 const int* __restrict__ role_idx,
                                 const float* __restrict__ vt,
                                 const float* __restrict__ rt)
{
    long idx = (long)blockIdx.x * 256 + threadIdx.x;
    if (idx >= (long)BR_ * TWO_E) return;
    int e = (int)(idx % TWO_E);
    int n = (int)(idx / TWO_E);
    int b = n / R_;
    float val = (e < E_) ? vt[(long)gt_verb[b] * E_ + e]
                         : rt[(long)role_idx[n] * E_ + (e - E_)];
    stA(ABF_RV  + (long)n * 640  + e, val);
    stA(ABF_CAT + (long)n * 1664 + 1024 + e, val);
}

// ---------------------------------------------------------------------------
// HMMA fp16 GEMM: D = Ah@(Bh [+ Bl if TERMS==2]). BM=64, 4 warps (2x2),
// warp tile 32 x (BN/2). 2-stage cp.async pipeline, padded smem.
// TERMS=1 halves MMAs + B traffic (use ONLY for logit-path GEMMs).
// ---------------------------------------------------------------------------
template<int BN, int NT, int MAXCTA, int TERMS>
__global__ __launch_bounds__(128, MAXCTA)
void mma_gemm_kernel(long aOff, long wOff,
                     const float* __restrict__ biasPtr, long biasOff,
                     float* CExt, long offC, long offCbf, int cbfStride,
                     int M, int N, int Kp, int act)
{
    constexpr int BM = 64, BKP = 40;
    constexpr int MI  = 2;
    constexpr int ASZ = BM * BKP;
    constexpr int BSZ = BN * BKP;
    constexpr int STG = ASZ + TERMS * BSZ;
    constexpr uint32_t ASZ2 = ASZ * 2, BSZ2 = BSZ * 2;

    extern __shared__ __align__(16) __half sm[];
    const __half* Ahp = g_abf + aOff;
    const __half* Bwh = g_wbf + wOff;
    const __half* Bwl = g_wbf + wOff + WTOTAL;
    const float* bias = biasPtr ? biasPtr
                      : (biasOff >= 0 ? (const float*)(g_scratch + biasOff) : nullptr);

    const int tid  = threadIdx.x;
    const int wid  = tid >> 5, lane = tid & 31;
    const int brow = blockIdx.y * BM, bcol = blockIdx.x * BN;
    const int wm   = (wid >> 1) * 32;
    const int wn   = (wid & 1) * (BN / 2);
    const uint32_t sb = smem_u32(sm);

    auto cpAll = [&](int t, int s) {
        const uint32_t st = sb + (uint32_t)(s * STG) * 2;
#pragma unroll
        for (int l = 0; l < 2; l++) {
            int idx = tid + l * 128;
            int row = idx >> 2, seg = idx & 3;
            size_t go = (size_t)(brow + row) * Kp + t * 32 + seg * 8;
            uint32_t so = (uint32_t)(row * BKP + seg * 8) * 2;
            cpa16(st + so, Ahp + go);
        }
#pragma unroll
        for (int l = 0; l < BN / 32; l++) {
            int idx = tid + l * 128;
            int row = idx >> 2, seg = idx & 3;
            size_t go = (size_t)(bcol + row) * Kp + t * 32 + seg * 8;
            uint32_t so = (uint32_t)(row * BKP + seg * 8) * 2;
            cpa16(st + ASZ2 + so, Bwh + go);
            if (TERMS == 2) cpa16(st + ASZ2 + BSZ2 + so, Bwl + go);
        }
    };

    float acc[MI][NT][4];
#pragma unroll
    for (int i = 0; i < MI; i++)
#pragma unroll
        for (int j = 0; j < NT; j++)
#pragma unroll
            for (int q = 0; q < 4; q++) acc[i][j][q] = 0.f;

    const int nCh = Kp / 32;

    cpAll(0, 0); CP_COMMIT();
    CP_WAIT0();
    __syncthreads();

    const int aRow = (lane & 7) + ((lane >> 3) & 1) * 8;
    const int aCol = (lane >> 4) * 8;
    const int bRow = (lane & 7) + ((lane >> 4) & 1) * 8;
    const int bCol = ((lane >> 3) & 1) * 8;

    for (int t = 0; t < nCh; t++) {
        const int s = t & 1;
        if (t + 1 < nCh) { cpAll(t + 1, s ^ 1); CP_COMMIT(); }

        const uint32_t ahB = sb + (uint32_t)(s * STG) * 2;
        const uint32_t bhB = ahB + ASZ2;
        const uint32_t blB = bhB + BSZ2;

#pragma unroll
        for (int ks = 0; ks < 2; ks++) {
            uint32_t ah[MI][4];
#pragma unroll
            for (int mi = 0; mi < MI; mi++) {
                uint32_t off = (uint32_t)((wm + mi * 16 + aRow) * BKP + ks * 16 + aCol) * 2;
                ldm_x4(ah[mi], ahB + off);
            }
            uint32_t bh[NT][2], bl[NT][2];
#pragma unroll
            for (int bt = 0; bt < NT / 2; bt++) {
                uint32_t off = (uint32_t)((wn + bt * 16 + bRow) * BKP + ks * 16 + bCol) * 2;
                uint32_t r[4];
                ldm_x4(r, bhB + off);
                bh[2 * bt][0] = r[0]; bh[2 * bt][1] = r[1];
                bh[2 * bt + 1][0] = r[2]; bh[2 * bt + 1][1] = r[3];
                if (TERMS == 2) {
                    ldm_x4(r, blB + off);
                    bl[2 * bt][0] = r[0]; bl[2 * bt][1] = r[1];
                    bl[2 * bt + 1][0] = r[2]; bl[2 * bt + 1][1] = r[3];
                }
            }
#pragma unroll
            for (int mi = 0; mi < MI; mi++)
#pragma unroll
                for (int ni = 0; ni < NT; ni++) {
                    mma16816(acc[mi][ni], ah[mi], bh[ni]);
                    if (TERMS == 2) mma16816(acc[mi][ni], ah[mi], bl[ni]);
                }
        }

        if (t + 1 < nCh) {
            CP_WAIT0();
            __syncthreads();
        }
    }

    // epilogue
    float* C = CExt ? CExt : (g_scratch + offC);
#pragma unroll
    for (int mi = 0; mi < MI; mi++) {
#pragma unroll
        for (int ni = 0; ni < NT; ni++) {
            int r0 = brow + wm + mi * 16 + (lane >> 2);
            int c0 = bcol + wn + ni * 8 + 2 * (lane & 3);
#pragma unroll
            for (int half = 0; half < 2; half++) {
                int gr = r0 + half * 8;
                float v0 = acc[mi][ni][2 * half + 0];
                float v1 = acc[mi][ni][2 * half + 1];
                if (offCbf >= 0) {
                    if (bias) { v0 += bias[c0]; v1 += bias[c0 + 1]; }
                    if (act)  { v0 = fmaxf(v0, 0.f); v1 = fmaxf(v1, 0.f); }
                    stA2(offCbf + (long)gr * cbfStride + c0, v0, v1);
                } else {
                    if (c0 < N) {
                        float o = v0 + (bias ? bias[c0] : 0.f);
                        if (act) o = fmaxf(o, 0.f);
                        C[(size_t)gr * N + c0] = o;
                    }
                    if (c0 + 1 < N) {
                        float o = v1 + (bias ? bias[c0 + 1] : 0.f);
                        if (act) o = fmaxf(o, 0.f);
                        C[(size_t)gr * N + c0 + 1] = o;
                    }
                }
            }
        }
    }
}

constexpr int SMEM_BIG2  = 2 * (64 * 40 + 2 * 128 * 40) * 2;  // 51200 B
constexpr int SMEM_BIG1  = 2 * (64 * 40 + 1 * 128 * 40) * 2;  // 30720 B
constexpr int SMEM_SMALL = 2 * (64 * 40 + 2 * 64 * 40) * 2;   // 30720 B

static inline void tgemm(long aOff, long wOff, const float* bias, long biasOff,
                         float* CExt, long offC, long offCbf, int cbfStride,
                         int M, int N, int Np, int Kp, int act, int terms = 2)
{
    if (terms == 1) {
        dim3 grid(Np / 128, M / 64);
        mma_gemm_kernel<128, 8, 3, 1><<<grid, 128, SMEM_BIG1>>>(
            aOff, wOff, bias, biasOff, CExt, offC, offCbf, cbfStride, M, N, Kp, act);
    } else if (M >= 4096 || Np >= 2048) {
        dim3 grid(Np / 128, M / 64);
        mma_gemm_kernel<128, 8, 3, 2><<<grid, 128, SMEM_BIG2>>>(
            aOff, wOff, bias, biasOff, CExt, offC, offCbf, cbfStride, M, N, Kp, act);
    } else {
        dim3 grid(Np / 64, M / 64);
        mma_gemm_kernel<64, 4, 4, 2><<<grid, 128, SMEM_SMALL>>>(
            aOff, wOff, bias, biasOff, CExt, offC, offCbf, cbfStride, M, N, Kp, act);
    }
}

// ---------------------------------------------------------------------------
// Visual attention (block per (b, src)); V and img fp16, half2 vemb phase.
// ---------------------------------------------------------------------------
__global__ __launch_bounds__(256) void att6_kernel(
    long offQA, int qStride,
    const float* __restrict__ aoW, const float* __restrict__ aoB,
    long abfOut0, long abfOut1)
{
    int b  = blockIdx.x;
    int which = blockIdx.y;
    int n0 = b * R_;
    const __half* V   = g_abf + ABF_V12 + ((long)which * B_ * K_ + (long)b * K_) * H_;
    const __half* img = g_abf + (which ? ABF_IMGF : ABF_IMG0) + (long)b * K_ * C_;
    long abfOut = which ? abfOut1 : abfOut0;

    __shared__ __align__(16) float qa[R_][H_];
    __shared__ float attw[R_][K_ + 1];

    int tid = threadIdx.x, wid = tid >> 5, lane = tid & 31;

    for (int idx = tid; idx < R_ * H_; idx += 256) {
        int r = idx / H_, h = idx % H_;
        qa[r][h] = g_scratch[offQA + (long)(n0 + r) * qStride + h] * aoW[h];
    }
    __syncthreads();

    for (int k = wid; k < K_; k += 8) {
        const uint4* vk = (const uint4*)(V + (long)k * H_);
        float s0=0,s1=0,s2=0,s3=0,s4=0,s5=0;
#pragma unroll
        for (int h8 = lane; h8 < H_ / 8; h8 += 32) {
            uint4 pv = vk[h8];
            const __half2* ph = (const __half2*)&pv;
            float2 f0 = __half22float2(ph[0]);
            float2 f1 = __half22float2(ph[1]);
            float2 f2 = __half22float2(ph[2]);
            float2 f3 = __half22float2(ph[3]);
            float vv[8] = {f0.x, f0.y, f1.x, f1.y, f2.x, f2.y, f3.x, f3.y};
            int hb = h8 * 8;
#pragma unroll
            for (int r = 0; r < R_; r++) {
                const float* qr = &qa[r][hb];
                float acc = vv[0]*qr[0] + vv[1]*qr[1] + vv[2]*qr[2] + vv[3]*qr[3]
                          + vv[4]*qr[4] + vv[5]*qr[5] + vv[6]*qr[6] + vv[7]*qr[7];
                if (r == 0) s0 += acc; else if (r == 1) s1 += acc;
                else if (r == 2) s2 += acc; else if (r == 3) s3 += acc;
                else if (r == 4) s4 += acc; else s5 += acc;
            }
        }
#pragma unroll
        for (int o = 16; o; o >>= 1) {
            s0 += __shfl_xor_sync(0xffffffffu, s0, o);
            s1 += __shfl_xor_sync(0xffffffffu, s1, o);
            s2 += __shfl_xor_sync(0xffffffffu, s2, o);
            s3 += __shfl_xor_sync(0xffffffffu, s3, o);
            s4 += __shfl_xor_sync(0xffffffffu, s4, o);
            s5 += __shfl_xor_sync(0xffffffffu, s5, o);
        }
        if (lane == 0) {
            float ab = aoB[0];
            attw[0][k] = s0 + ab; attw[1][k] = s1 + ab; attw[2][k] = s2 + ab;
            attw[3][k] = s3 + ab; attw[4][k] = s4 + ab; attw[5][k] = s5 + ab;
        }
    }
    __syncthreads();

    if (tid < R_) {
        float mx = -1e30f;
        for (int k = 0; k < K_; k++) mx = fmaxf(mx, attw[tid][k]);
        float sum = 0.f;
        for (int k = 0; k < K_; k++) sum += expf(attw[tid][k] - mx);
        float inv = 1.f / sum;
        for (int k = 0; k < K_; k++) attw[tid][k] = expf(attw[tid][k] - mx) * inv;
    }
    __syncthreads();

    // vemb: 2 columns per thread via half2 (C_ = 2 * 256)
    {
        const __half2* img2 = (const __half2*)img;
        int c2 = tid;
        float a0x=0,a0y=0,a1x=0,a1y=0,a2x=0,a2y=0;
        float a3x=0,a3y=0,a4x=0,a4y=0,a5x=0,a5y=0;
#pragma unroll 7
        for (int k = 0; k < K_; k++) {
            float2 f = __half22float2(img2[(long)k * (C_ / 2) + c2]);
            float w0 = attw[0][k], w1 = attw[1][k], w2 = attw[2][k];
            float w3 = attw[3][k], w4 = attw[4][k], w5 = attw[5][k];
            a0x = fmaf(w0, f.x, a0x); a0y = fmaf(w0, f.y, a0y);
            a1x = fmaf(w1, f.x, a1x); a1y = fmaf(w1, f.y, a1y);
            a2x = fmaf(w2, f.x, a2x); a2y = fmaf(w2, f.y, a2y);
            a3x = fmaf(w3, f.x, a3x); a3y = fmaf(w3, f.y, a3y);
            a4x = fmaf(w4, f.x, a4x); a4y = fmaf(w4, f.y, a4y);
            a5x = fmaf(w5, f.x, a5x); a5y = fmaf(w5, f.y, a5y);
        }
        long base = abfOut + (long)n0 * C_ + 2 * c2;
        stA2(base,          a0x, a0y); stA2(base + C_,     a1x, a1y);
        stA2(base + 2 * C_, a2x, a2y); stA2(base + 3 * C_, a3x, a3y);
        stA2(base + 4 * C_, a4x, a4y); stA2(base + 5 * C_, a5x, a5y);
    }
}

// ---------------------------------------------------------------------------
// MFB pool, single pass. mode 0: fp32 rows + fp16. mode 1: gated combine.
// ---------------------------------------------------------------------------
__global__ void mfb_kernel(long offQ, int qStride, int qWrap,
                           long offV, int mode)
{
    int n = blockIdx.x;
    const float* q = g_scratch + offQ + (long)(n % qWrap) * qStride;
    const float* v = g_scratch + offV + (long)n * H_;
    int tid = threadIdx.x;

    float zreg[4];
    float s = 0.f;
#pragma unroll
    for (int j = 0; j < 4; j++) {
        int h = tid + j * 256;
        float z = q[h] * v[h];
        zreg[j] = z;
        s += fabsf(z);
    }
    __shared__ float red[8];
#pragma unroll
    for (int off = 16; off; off >>= 1) s += __shfl_xor_sync(0xffffffffu, s, off);
    if ((tid & 31) == 0) red[tid >> 5] = s;
    __syncthreads();
    float tot = 0.f;
#pragma unroll
    for (int i = 0; i < 8; i++) tot += red[i];
    float inv = 1.f / fmaxf(sqrtf(tot), 1e-12f);

#pragma unroll
    for (int j = 0; j < 4; j++) {
        int h = tid + j * 256;
        float z = zreg[j];
        float sg = (z > 0.f) ? sqrtf(z) : -sqrtf(-z);
        float r = sg * inv;
        if (mode == 0) {
            g_scratch[OFF_OUT + (long)n * H_ + h] = r;
            stA(ABF_OUT + (long)n * H_ + h, r);
        } else {
            float ov = g_scratch[OFF_OUT + SZ_H + (long)n * H_ + h];
            float a0 = g_scratch[OFF_OUT + (long)n * H_ + h];
            float g  = 1.f / (1.f + expf(-(r + ov)));
            stA(ABF_OUTF + (long)n * H_ + h, (1.f - g) * ov + g * tanhf(r + a0));
        }
    }
}

// ---------------------------------------------------------------------------
// Masked role attention with q/k/v cached in smem (float4 fill) -> fp16 ctx.
// ---------------------------------------------------------------------------
__global__ __launch_bounds__(256, 1) void role_att_kernel(const int* __restrict__ mask)
{
    extern __shared__ float rs[];
    float* qs = rs;
    float* ks = rs + 6 * 1024;
    float* vs = rs + 12 * 1024;

    int b = blockIdx.x;
    const float* base = g_scratch + OFF_QKV3 + (long)b * R_ * 3072;

    __shared__ float sc[R_][R_];
    __shared__ float attn[R_][R_];
    int tid = threadIdx.x, wid = tid >> 5, lane = tid & 31;

#pragma unroll
    for (int j = 0; j < 18; j++) {
        int f4 = tid + j * 256;
        int row = f4 >> 8;
        int h4  = f4 & 255;
        int part = row / 6, role = row % 6;
        *(float4*)&rs[(long)row * 1024 + h4 * 4] =
            *(const float4*)&base[(long)role * 3072 + part * 1024 + h4 * 4];
    }
    __syncthreads();

    for (int p = wid; p < R_ * R_; p += 8) {
        int i = p / R_, j = p % R_;
        const float* qh = qs + i * 1024;
        const float* kh = ks + j * 1024;
        float s = 0.f;
        for (int h = lane; h < H_; h += 32)
            s = fmaf(qh[h], kh[h], s);
#pragma unroll
        for (int o = 16; o; o >>= 1) s += __shfl_xor_sync(0xffffffffu, s, o);
        if (lane == 0) {
            bool valid = (i != j) && (mask[((long)b * R_ + i) * R_ + j] > 0);
            sc[i][j] = valid ? s * (1.f / 32.f) : -1e9f;
        }
    }
    __syncthreads();

    if (tid < R_ * R_) {
        int i = tid / R_, j = tid % R_;
        float mx = -1e30f;
        for (int jj = 0; jj < R_; jj++) mx = fmaxf(mx, sc[i][jj]);
        float sum = 0.f;
        for (int jj = 0; jj < R_; jj++) sum += expf(sc[i][jj] - mx);
        attn[i][j] = expf(sc[i][j] - mx) / sum;
    }
    __syncthreads();

    for (int idx = tid; idx < R_ * H_; idx += 256) {
        int i = idx / H_, h = idx % H_;
        float acc = 0.f;
#pragma unroll
        for (int j = 0; j < R_; j++)
            acc = fmaf(attn[i][j], vs[j * 1024 + h], acc);
        stA(ABF_CTX + (long)(b * R_ + i) * H_ + h, acc);
    }
}

constexpr int SMEM_ROLE = 18 * 1024 * 4;   // 73728 B

// ---------------------------------------------------------------------------
// Launch sequence
// ---------------------------------------------------------------------------
extern "C" void kernel_launch(void* const* d_in, const int* in_sizes, int n_in,
                              void* d_out, int out_size)
{
    const float* v_org    = (const float*)d_in[0];
    const float* img_feat = (const float*)d_in[1];
    const int*   gt_verb  = (const int*)d_in[2];
    const int*   role_idx = (const int*)d_in[3];
    const int*   mask     = (const int*)d_in[4];
    const float* verb_t   = (const float*)d_in[5];
    const float* role_t   = (const float*)d_in[6];
    const float* qc_W = (const float*)d_in[7];   const float* qc_b = (const float*)d_in[8];
    const float* av_W = (const float*)d_in[9];   const float* av_b = (const float*)d_in[10];
    const float* aq_W = (const float*)d_in[11];  const float* aq_b = (const float*)d_in[12];
    const float* ao_W = (const float*)d_in[13];  const float* ao_b = (const float*)d_in[14];
    const float* vn_W = (const float*)d_in[15];  const float* vn_b = (const float*)d_in[16];
    const float* qn_W = (const float*)d_in[17];  const float* qn_b = (const float*)d_in[18];
    const float* Wq   = (const float*)d_in[19];
    const float* Wk   = (const float*)d_in[20];
    const float* Wv   = (const float*)d_in[21];
    const float* Wo   = (const float*)d_in[22];
    const float* uqc_W = (const float*)d_in[23]; const float* uqc_b = (const float*)d_in[24];
    const float* cls_W = (const float*)d_in[25]; const float* cls_b = (const float*)d_in[26];

    cudaFuncSetAttribute((const void*)mma_gemm_kernel<128, 8, 3, 2>,
                         cudaFuncAttributeMaxDynamicSharedMemorySize, SMEM_BIG2);
    cudaFuncSetAttribute((const void*)mma_gemm_kernel<128, 8, 3, 1>,
                         cudaFuncAttributeMaxDynamicSharedMemorySize, SMEM_BIG1);
    cudaFuncSetAttribute((const void*)mma_gemm_kernel<64, 4, 4, 2>,
                         cudaFuncAttributeMaxDynamicSharedMemorySize, SMEM_SMALL);
    cudaFuncSetAttribute((const void*)role_att_kernel,
                         cudaFuncAttributeMaxDynamicSharedMemorySize, SMEM_ROLE);

    // megaconv descriptor table
    WAll P;
    const float* Ws[11] = {qc_W, av_W, aq_W, qn_W, vn_W, Wq, Wk, Wv, Wo, uqc_W, cls_W};
    int  Ks[11]  = {600, 512, 1024, 1024, 512, 1024, 1024, 1024, 1024, CATW, 1024};
    int  Ns[11]  = {1024,1024,1024, 1024, 1024,1024, 1024, 1024, 1024, 1024, NL_};
    int  tK[11]  = {20,  16,  32,   32,   16,  32,   32,   32,   32,   52,   32};
    int  Nps[11] = {1024,1024,1024, 1024, 1024,1024, 1024, 1024, 1024, 1024, 2048};
    long offs[11]= {WOFF_QC, WOFF_AV, WOFF_AQN, WOFF_AQN + 1024L * 1024, WOFF_VN,
                    WOFF_QKV, WOFF_QKV + 1024L * 1024, WOFF_QKV + 2048L * 1024,
                    WOFF_WO, WOFF_UQC, WOFF_CLS};
    int pre = 0;
    for (int i = 0; i < 11; i++) {
        P.W[i] = Ws[i]; P.K[i] = Ks[i]; P.N[i] = Ns[i];
        P.tilesK[i] = tK[i]; P.off[i] = offs[i];
        P.pre[i] = pre;
        pre += tK[i] * (Nps[i] / 32);
    }
    P.pre[11] = pre;

    // 0: prep, 1: megaconv, 2: gather, 3: QEMB
    prep_kernel<<<TRB + IFB + 1, dim3(32, 8)>>>(v_org, img_feat, aq_b, qn_b);
    megaconv_kernel<<<pre, dim3(32, 8)>>>(P);
    gather_rv_kernel<<<(int)(((long)BR_ * TWO_E + 255) / 256), 256>>>(gt_verb, role_idx,
                                                                      verb_t, role_t);
    // query chain
    tgemm(ABF_RV, WOFF_QC, qc_b, -1, nullptr, 0, ABF_QEMB, 1024,
          BR_, 1024, 1024, 640, 1);

    // FUSED V1+V2 GEMM -> fp16 (ABF_V12) — 1-TERM (logit-path only)
    tgemm(ABF_IMG0, WOFF_AV, av_b, -1, nullptr, 0, ABF_V12, 1024,
          2 * B_ * K_, 1024, 1024, 512, 1, /*terms=*/1);

    tgemm(ABF_QEMB, WOFF_AQN, nullptr, OFF_BIASAQN, nullptr, OFF_QAQR, -1, 0,
          BR_, 2048, 2048, 1024, 1);

    // attention 1 + attention-verb in ONE launch (grid B x 2)
    att6_kernel<<<dim3(B_, 2), 256>>>(OFF_QAQR, 2048, ao_W, ao_b,
                                      ABF_VEMB12, ABF_VEMB12 + (long)BR_ * 512);

    // fused VN over [VEMB1;VEMB2]
    tgemm(ABF_VEMB12, WOFF_VN, vn_b, -1, nullptr, OFF_VREPR1, -1, 0,
          2 * BR_, 1024, 1024, 512, 1);

    // fused MFB for OUT & OUTV (mode 0)
    mfb_kernel<<<2 * BR_, 256>>>(OFF_QAQR + 1024, 2048, BR_, OFF_VREPR1, 0);

    // role-node neighbour attention
    tgemm(ABF_OUT, WOFF_QKV, nullptr, -1, nullptr, OFF_QKV3, -1, 0,
          BR_, 3072, 3072, 1024, 0);
    role_att_kernel<<<B_, 256, SMEM_ROLE>>>(mask);
    // WO writes fp16 DIRECTLY into CAT rows (stride 1664)
    tgemm(ABF_CTX, WOFF_WO, nullptr, -1, nullptr, 0, ABF_CAT, 1664,
          BR_, 1024, 1024, 1024, 0);

    // updated query
    tgemm(ABF_CAT, WOFF_UQC, uqc_b, -1, nullptr, 0, ABF_UQ, 1024,
          BR_, 1024, 1024, 1664, 1);
    tgemm(ABF_UQ, WOFF_AQN, nullptr, OFF_BIASAQN, nullptr, OFF_QAQR2, -1, 0,
          BR_, 2048, 2048, 1024, 1);

    // attention 2 (single source: V1 + img0)
    att6_kernel<<<dim3(B_, 1), 256>>>(OFF_QAQR2, 2048, ao_W, ao_b,
                                      ABF_VEMB3, ABF_VEMB3);
    tgemm(ABF_VEMB3, WOFF_VN, vn_b, -1, nullptr, OFF_VREPR2, -1, 0,
          BR_, 1024, 1024, 512, 1);

    // MFB(out2) fused with gated combine (mode 1) -> ABF_OUTF
    mfb_kernel<<<BR_, 256>>>(OFF_QAQR2 + 1024, 2048, BR_, OFF_VREPR2, 1);

    // classifier -> d_out
    tgemm(ABF_OUTF, WOFF_CLS, cls_b, -1, (float*)d_out, 0, -1, 0,
          BR_, NL_, 2048, 1024, 0);
}